// round 1
// baseline (speedup 1.0000x reference)
#include <cuda_runtime.h>
#include <cuda_bf16.h>
#include <math.h>

// Problem constants
#define BATCH 2
#define SEQ   2048
#define EMB   2048
#define HEADS 16
#define HDIM  128
#define HDIM2 64           // rotary half-dim
#define THREE_E 6144
#define MROWS (BATCH*SEQ)  // 4096

// Scratch (no cudaMalloc allowed)
__device__ float g_qkv[(size_t)BATCH * SEQ * 3 * EMB];   // [b][s][3][h][d]
__device__ float g_ctx[(size_t)BATCH * SEQ * EMB];       // [b][s][h*d]

// ---------------------------------------------------------------------------
// SGEMM: C[M,N] = A[M,K] @ B[N,K]^T + bias[N]
// BM=BN=128, BK=16, 256 threads, 8x8 per thread. Dims assumed divisible.
// ---------------------------------------------------------------------------
__global__ __launch_bounds__(256) void sgemm_nt_bias(
    const float* __restrict__ A, const float* __restrict__ Bm,
    const float* __restrict__ bias, float* __restrict__ C,
    int M, int N, int K)
{
    __shared__ float As[16 * 128];
    __shared__ float Bs[16 * 128];

    const int tid  = threadIdx.x;
    const int m0   = blockIdx.y * 128;
    const int n0   = blockIdx.x * 128;
    const int rowC = (tid >> 4) * 8;
    const int colC = (tid & 15) * 8;

    const int aRow = tid >> 1;          // 0..127
    const int aCol = (tid & 1) * 8;     // 0 or 8

    const float* Aptr = A + (size_t)(m0 + aRow) * K + aCol;
    const float* Bptr = Bm + (size_t)(n0 + aRow) * K + aCol;

    float acc[8][8];
#pragma unroll
    for (int i = 0; i < 8; i++)
#pragma unroll
        for (int j = 0; j < 8; j++) acc[i][j] = 0.0f;

    for (int k0 = 0; k0 < K; k0 += 16) {
        float4 a0 = *(const float4*)(Aptr + k0);
        float4 a1 = *(const float4*)(Aptr + k0 + 4);
        float4 b0 = *(const float4*)(Bptr + k0);
        float4 b1 = *(const float4*)(Bptr + k0 + 4);

        __syncthreads();   // previous iteration's smem reads done
        As[(aCol + 0) * 128 + aRow] = a0.x;
        As[(aCol + 1) * 128 + aRow] = a0.y;
        As[(aCol + 2) * 128 + aRow] = a0.z;
        As[(aCol + 3) * 128 + aRow] = a0.w;
        As[(aCol + 4) * 128 + aRow] = a1.x;
        As[(aCol + 5) * 128 + aRow] = a1.y;
        As[(aCol + 6) * 128 + aRow] = a1.z;
        As[(aCol + 7) * 128 + aRow] = a1.w;
        Bs[(aCol + 0) * 128 + aRow] = b0.x;
        Bs[(aCol + 1) * 128 + aRow] = b0.y;
        Bs[(aCol + 2) * 128 + aRow] = b0.z;
        Bs[(aCol + 3) * 128 + aRow] = b0.w;
        Bs[(aCol + 4) * 128 + aRow] = b1.x;
        Bs[(aCol + 5) * 128 + aRow] = b1.y;
        Bs[(aCol + 6) * 128 + aRow] = b1.z;
        Bs[(aCol + 7) * 128 + aRow] = b1.w;
        __syncthreads();

#pragma unroll
        for (int kk = 0; kk < 16; kk++) {
            float4 ra0 = *(const float4*)&As[kk * 128 + rowC];
            float4 ra1 = *(const float4*)&As[kk * 128 + rowC + 4];
            float4 rb0 = *(const float4*)&Bs[kk * 128 + colC];
            float4 rb1 = *(const float4*)&Bs[kk * 128 + colC + 4];
            float ra[8] = {ra0.x, ra0.y, ra0.z, ra0.w, ra1.x, ra1.y, ra1.z, ra1.w};
            float rb[8] = {rb0.x, rb0.y, rb0.z, rb0.w, rb1.x, rb1.y, rb1.z, rb1.w};
#pragma unroll
            for (int i = 0; i < 8; i++)
#pragma unroll
                for (int j = 0; j < 8; j++)
                    acc[i][j] = fmaf(ra[i], rb[j], acc[i][j]);
        }
    }

#pragma unroll
    for (int i = 0; i < 8; i++) {
        float* crow = C + (size_t)(m0 + rowC + i) * N + n0 + colC;
#pragma unroll
        for (int j = 0; j < 8; j++)
            crow[j] = acc[i][j] + bias[n0 + colC + j];
    }
}

// ---------------------------------------------------------------------------
// RoPE on q (slot 0) and k (slot 1), in place. One thread per rotary pair.
// ---------------------------------------------------------------------------
__global__ __launch_bounds__(256) void rope_kernel(float* __restrict__ qkv)
{
    const int total = BATCH * SEQ * 2 * HEADS * HDIM2;  // 8388608
    int idx = blockIdx.x * blockDim.x + threadIdx.x;
    if (idx >= total) return;

    int j  = idx % HDIM2;
    int h  = (idx / HDIM2) % HEADS;
    int qk = (idx / (HDIM2 * HEADS)) % 2;
    int s  = (idx / (HDIM2 * HEADS * 2)) % SEQ;
    int b  = idx / (HDIM2 * HEADS * 2 * SEQ);

    size_t base = ((((size_t)(b * SEQ + s)) * 3 + qk) * HEADS + h) * HDIM;

    float inv = powf(10000.0f, -(float)j / 64.0f);  // exponent (2j)/128
    float ang = (float)s * inv;
    float sn, c;
    sincosf(ang, &sn, &c);

    float x1 = qkv[base + j];
    float x2 = qkv[base + HDIM2 + j];
    qkv[base + j]         = x1 * c - x2 * sn;
    qkv[base + HDIM2 + j] = x1 * sn + x2 * c;
}

// ---------------------------------------------------------------------------
// Flash attention, causal. BM=BN=64, D=128, 256 threads (16x16),
// 4x4 score micro-tile, 4x8 output micro-tile. K/V share one smem buffer.
// ---------------------------------------------------------------------------
#define KV_STRIDE 132
#define P_STRIDE  68
#define FLASH_SMEM ((64*128 + 64*KV_STRIDE + 64*P_STRIDE) * (int)sizeof(float))

__global__ __launch_bounds__(256) void flash_attn(
    const float* __restrict__ qkv, float* __restrict__ ctx)
{
    extern __shared__ float sm[];
    float* Qs  = sm;                     // [64][128]
    float* KVs = sm + 64 * 128;          // [64][KV_STRIDE]
    float* Ps  = KVs + 64 * KV_STRIDE;   // [64][P_STRIDE]

    const int qt = blockIdx.x;
    const int bh = blockIdx.y;
    const int b  = bh / HEADS;
    const int h  = bh % HEADS;
    const int tid = threadIdx.x;
    const int ty  = tid >> 4;   // 0..15
    const int tx  = tid & 15;   // 0..15
    const int q0  = qt * 64;
    const float scale = 0.08838834764831845f;  // 1/sqrt(128)

    // Load Q tile [64][128]
#pragma unroll
    for (int t = 0; t < 8; t++) {
        int i4 = tid + t * 256;       // float4 index 0..2047
        int r  = i4 >> 5;             // 32 float4 per row
        int c  = (i4 & 31) * 4;
        size_t src = ((((size_t)(b * SEQ + q0 + r)) * 3 + 0) * HEADS + h) * HDIM + c;
        *(float4*)&Qs[r * 128 + c] = *(const float4*)(qkv + src);
    }

    float m_run[4], l_run[4];
    float o[4][8];
#pragma unroll
    for (int i = 0; i < 4; i++) {
        m_run[i] = -1e30f;
        l_run[i] = 0.0f;
#pragma unroll
        for (int j = 0; j < 8; j++) o[i][j] = 0.0f;
    }

    const int nkt = qt + 1;  // causal: tiles up to and including diagonal
    for (int kt = 0; kt < nkt; kt++) {
        const int k0 = kt * 64;
        __syncthreads();  // previous tile's KVs/Ps reads done (and Qs store on iter 0)

        // Load K tile
#pragma unroll
        for (int t = 0; t < 8; t++) {
            int i4 = tid + t * 256;
            int r  = i4 >> 5;
            int c  = (i4 & 31) * 4;
            size_t src = ((((size_t)(b * SEQ + k0 + r)) * 3 + 1) * HEADS + h) * HDIM + c;
            *(float4*)&KVs[r * KV_STRIDE + c] = *(const float4*)(qkv + src);
        }
        __syncthreads();

        // S = Q @ K^T  (4x4 per thread)
        float sacc[4][4];
#pragma unroll
        for (int i = 0; i < 4; i++)
#pragma unroll
            for (int j = 0; j < 4; j++) sacc[i][j] = 0.0f;

        for (int kk = 0; kk < 128; kk += 4) {
            float4 rq[4], rk[4];
#pragma unroll
            for (int i = 0; i < 4; i++)
                rq[i] = *(const float4*)&Qs[(ty * 4 + i) * 128 + kk];
#pragma unroll
            for (int j = 0; j < 4; j++)
                rk[j] = *(const float4*)&KVs[(tx * 4 + j) * KV_STRIDE + kk];
#pragma unroll
            for (int i = 0; i < 4; i++)
#pragma unroll
                for (int j = 0; j < 4; j++) {
                    sacc[i][j] = fmaf(rq[i].x, rk[j].x, sacc[i][j]);
                    sacc[i][j] = fmaf(rq[i].y, rk[j].y, sacc[i][j]);
                    sacc[i][j] = fmaf(rq[i].z, rk[j].z, sacc[i][j]);
                    sacc[i][j] = fmaf(rq[i].w, rk[j].w, sacc[i][j]);
                }
        }

        // Online softmax per row. Reduce over tx (16 lanes within half-warp).
        const bool diag = (kt == qt);
#pragma unroll
        for (int i = 0; i < 4; i++) {
            const int rg = q0 + ty * 4 + i;
            float mx = -1e30f;
#pragma unroll
            for (int j = 0; j < 4; j++) {
                float sv = sacc[i][j] * scale;
                if (diag && (k0 + tx * 4 + j > rg)) sv = -1e30f;
                sacc[i][j] = sv;
                mx = fmaxf(mx, sv);
            }
#pragma unroll
            for (int off = 1; off < 16; off <<= 1)
                mx = fmaxf(mx, __shfl_xor_sync(0xffffffffu, mx, off));

            const float m_old = m_run[i];
            const float mnew  = fmaxf(m_old, mx);
            const float sf    = expf(m_old - mnew);  // 0 on first tile (m_old=-1e30)
            m_run[i] = mnew;

            float ls = 0.0f;
#pragma unroll
            for (int j = 0; j < 4; j++) {
                float pv = expf(sacc[i][j] - mnew);
                Ps[(ty * 4 + i) * P_STRIDE + tx * 4 + j] = pv;
                ls += pv;
            }
#pragma unroll
            for (int off = 1; off < 16; off <<= 1)
                ls += __shfl_xor_sync(0xffffffffu, ls, off);

            l_run[i] = l_run[i] * sf + ls;
#pragma unroll
            for (int j = 0; j < 8; j++) o[i][j] *= sf;
        }

        __syncthreads();  // Ps written everywhere; K reads done

        // Load V tile (overwrites K buffer)
#pragma unroll
        for (int t = 0; t < 8; t++) {
            int i4 = tid + t * 256;
            int r  = i4 >> 5;
            int c  = (i4 & 31) * 4;
            size_t src = ((((size_t)(b * SEQ + k0 + r)) * 3 + 2) * HEADS + h) * HDIM + c;
            *(float4*)&KVs[r * KV_STRIDE + c] = *(const float4*)(qkv + src);
        }
        __syncthreads();

        // O += P @ V
        for (int kk = 0; kk < 64; kk++) {
            float rp[4];
#pragma unroll
            for (int i = 0; i < 4; i++)
                rp[i] = Ps[(ty * 4 + i) * P_STRIDE + kk];
            float4 rv0 = *(const float4*)&KVs[kk * KV_STRIDE + tx * 8];
            float4 rv1 = *(const float4*)&KVs[kk * KV_STRIDE + tx * 8 + 4];
            float rv[8] = {rv0.x, rv0.y, rv0.z, rv0.w, rv1.x, rv1.y, rv1.z, rv1.w};
#pragma unroll
            for (int i = 0; i < 4; i++)
#pragma unroll
                for (int j = 0; j < 8; j++)
                    o[i][j] = fmaf(rp[i], rv[j], o[i][j]);
        }
    }

    // Final normalize + store ctx[b][s][h*D + d]
#pragma unroll
    for (int i = 0; i < 4; i++) {
        float inv = 1.0f / l_run[i];
        int row = q0 + ty * 4 + i;
        float* dst = ctx + (size_t)(b * SEQ + row) * EMB + h * HDIM + tx * 8;
        float4 v0 = {o[i][0] * inv, o[i][1] * inv, o[i][2] * inv, o[i][3] * inv};
        float4 v1 = {o[i][4] * inv, o[i][5] * inv, o[i][6] * inv, o[i][7] * inv};
        *(float4*)dst = v0;
        *(float4*)(dst + 4) = v1;
    }
}

extern "C" void kernel_launch(void* const* d_in, const int* in_sizes, int n_in,
                              void* d_out, int out_size)
{
    const float* x      = (const float*)d_in[0];
    const float* wqkv_w = (const float*)d_in[1];
    const float* wqkv_b = (const float*)d_in[2];
    const float* out_w  = (const float*)d_in[3];
    const float* out_b  = (const float*)d_in[4];
    float* out = (float*)d_out;

    float *qkv, *ctx;
    cudaGetSymbolAddress((void**)&qkv, g_qkv);
    cudaGetSymbolAddress((void**)&ctx, g_ctx);

    cudaFuncSetAttribute(flash_attn, cudaFuncAttributeMaxDynamicSharedMemorySize,
                         FLASH_SMEM);

    dim3 g1(THREE_E / 128, MROWS / 128);
    sgemm_nt_bias<<<g1, 256>>>(x, wqkv_w, wqkv_b, qkv, MROWS, THREE_E, EMB);

    rope_kernel<<<(BATCH * SEQ * 2 * HEADS * HDIM2 + 255) / 256, 256>>>(qkv);

    dim3 g2(SEQ / 64, BATCH * HEADS);
    flash_attn<<<g2, 256, FLASH_SMEM>>>(qkv, ctx);

    dim3 g3(EMB / 128, MROWS / 128);
    sgemm_nt_bias<<<g3, 256>>>(ctx, out_w, out_b, out, MROWS, EMB, EMB);
}

// round 3
// speedup vs baseline: 1.5757x; 1.5757x over previous
#include <cuda_runtime.h>
#include <cuda_bf16.h>
#include <math.h>
#include <stdint.h>

// Problem constants
#define BATCH 2
#define SEQ   2048
#define EMB   2048
#define HEADS 16
#define HDIM  128
#define HDIM2 64
#define THREE_E 6144
#define MROWS (BATCH*SEQ)  // 4096

// Scratch (no cudaMalloc allowed)
__device__ float g_qkv[(size_t)MROWS * THREE_E];   // [b][s][3][h][d]
__device__ float g_ctx[(size_t)MROWS * EMB];       // [b][s][h*d]

__device__ __forceinline__ uint32_t smem_u32(const void* p) {
    uint32_t a;
    asm("{ .reg .u64 t; cvta.to.shared.u64 t, %1; cvt.u32.u64 %0, t; }"
        : "=r"(a) : "l"(p));
    return a;
}

// fp32 pair -> hi bf16x2 + residual-lo bf16x2 (memory order: f0 low, f1 high)
__device__ __forceinline__ void cvt_pair(float f0, float f1,
                                         uint32_t& h, uint32_t& l) {
    asm("cvt.rn.bf16x2.f32 %0, %1, %2;" : "=r"(h) : "f"(f1), "f"(f0));
    float h0 = __uint_as_float(h << 16);
    float h1 = __uint_as_float(h & 0xffff0000u);
    asm("cvt.rn.bf16x2.f32 %0, %1, %2;" : "=r"(l) : "f"(f1 - h1), "f"(f0 - h0));
}

#define LDMX4(r0, r1, r2, r3, addr) \
    asm volatile("ldmatrix.sync.aligned.m8n8.x4.shared.b16 {%0,%1,%2,%3}, [%4];" \
        : "=r"(r0), "=r"(r1), "=r"(r2), "=r"(r3) : "r"(addr))

#define MMA16816(d, a, b0, b1) \
    asm volatile("mma.sync.aligned.m16n8k16.row.col.f32.bf16.bf16.f32 " \
        "{%0,%1,%2,%3}, {%4,%5,%6,%7}, {%8,%9}, {%0,%1,%2,%3};" \
        : "+f"((d)[0]), "+f"((d)[1]), "+f"((d)[2]), "+f"((d)[3]) \
        : "r"((a)[0]), "r"((a)[1]), "r"((a)[2]), "r"((a)[3]), "r"(b0), "r"(b1))

// ===========================================================================
// Split-bf16 tensor-core GEMM: C[M,N] = A[M,K] @ B[N,K]^T + bias[N]
// BM=BN=128, BK=32 fp32. 256 threads = 8 warps (2m x 4n), warp tile 64x32.
// 3-product split (AhBh + AhBl + AlBh), fp32 accum.
// ===========================================================================
#define LDS 40                     // bf16 elements per smem row (80B, 16B-aligned)
#define TILE_SB (128 * LDS * 2)    // 10240 bytes per bf16 tile
#define STAGE_SB (4 * TILE_SB)     // Ah, Al, Bh, Bl
#define GEMM_SMEM (2 * STAGE_SB)   // 81920 bytes

__global__ __launch_bounds__(256, 1) void gemm_mma(
    const float* __restrict__ A, const float* __restrict__ Bw,
    const float* __restrict__ bias, float* __restrict__ C, int N, int K)
{
    extern __shared__ char dsm[];
    __shared__ float sBias[128];

    const int tid  = threadIdx.x;
    const int lane = tid & 31;
    const int wid  = tid >> 5;
    const int wm   = wid >> 2;        // 0..1
    const int wn   = wid & 3;         // 0..3
    const int m0 = blockIdx.y * 128, n0 = blockIdx.x * 128;

    const uint32_t sbase = smem_u32(dsm);

    if (tid < 128) sBias[tid] = bias[n0 + tid];

    // gmem load mapping: row = tid>>1 (0..127), col base = (tid&1)*16
    const int gr = tid >> 1;
    const int gc = (tid & 1) * 16;
    const float* aptr = A  + (size_t)(m0 + gr) * K + gc;
    const float* bptr = Bw + (size_t)(n0 + gr) * K + gc;
    const uint32_t soff = (uint32_t)(gr * LDS + gc) * 2u;  // byte offset in tile

    float4 va[4], vb[4];
    const int NCH = K >> 5;  // 64

    // ---- preload chunk 0 into stage 0 ----
#pragma unroll
    for (int q = 0; q < 4; q++) {
        va[q] = *(const float4*)(aptr + q * 4);
        vb[q] = *(const float4*)(bptr + q * 4);
    }
    {
        char* st = dsm;
#pragma unroll
        for (int q = 0; q < 4; q++) {
            uint32_t h01, l01, h23, l23;
            cvt_pair(va[q].x, va[q].y, h01, l01);
            cvt_pair(va[q].z, va[q].w, h23, l23);
            *(uint2*)(st + soff + q * 8)             = make_uint2(h01, h23);
            *(uint2*)(st + TILE_SB + soff + q * 8)   = make_uint2(l01, l23);
            cvt_pair(vb[q].x, vb[q].y, h01, l01);
            cvt_pair(vb[q].z, vb[q].w, h23, l23);
            *(uint2*)(st + 2*TILE_SB + soff + q * 8) = make_uint2(h01, h23);
            *(uint2*)(st + 3*TILE_SB + soff + q * 8) = make_uint2(l01, l23);
        }
    }
    __syncthreads();

    float acc[4][4][4];
#pragma unroll
    for (int mt = 0; mt < 4; mt++)
#pragma unroll
        for (int nt = 0; nt < 4; nt++)
#pragma unroll
            for (int r = 0; r < 4; r++) acc[mt][nt][r] = 0.0f;

    // ldmatrix lane addressing (byte offsets within a tile)
    const uint32_t a_row = (uint32_t)(wm * 64 + (lane & 15));
    const uint32_t a_koff = (uint32_t)((lane >> 4) * 8);
    const uint32_t b_row = (uint32_t)(wn * 32 + (lane & 7) + ((lane >> 4) << 3));
    const uint32_t b_koff = (uint32_t)(((lane >> 3) & 1) * 8);

    for (int c = 0; c < NCH; c++) {
        const uint32_t stg = sbase + (uint32_t)(c & 1) * STAGE_SB;

        if (c + 1 < NCH) {
#pragma unroll
            for (int q = 0; q < 4; q++) {
                va[q] = *(const float4*)(aptr + (c + 1) * 32 + q * 4);
                vb[q] = *(const float4*)(bptr + (c + 1) * 32 + q * 4);
            }
        }

#pragma unroll
        for (int ks = 0; ks < 2; ks++) {
            const uint32_t kofs = (uint32_t)(ks * 16);
            uint32_t ah[4][4], al[4][4];
#pragma unroll
            for (int mt = 0; mt < 4; mt++) {
                uint32_t adr = stg + ((a_row + mt * 16) * LDS + kofs + a_koff) * 2;
                LDMX4(ah[mt][0], ah[mt][1], ah[mt][2], ah[mt][3], adr);
                LDMX4(al[mt][0], al[mt][1], al[mt][2], al[mt][3], adr + TILE_SB);
            }
            uint32_t bh[2][4], bl[2][4];
#pragma unroll
            for (int p = 0; p < 2; p++) {
                uint32_t adr = stg + 2 * TILE_SB
                             + ((b_row + p * 16) * LDS + kofs + b_koff) * 2;
                LDMX4(bh[p][0], bh[p][1], bh[p][2], bh[p][3], adr);
                LDMX4(bl[p][0], bl[p][1], bl[p][2], bl[p][3], adr + TILE_SB);
            }
#pragma unroll
            for (int mt = 0; mt < 4; mt++)
#pragma unroll
                for (int nt = 0; nt < 4; nt++) {
                    const int p = nt >> 1, hh = (nt & 1) * 2;
                    MMA16816(acc[mt][nt], ah[mt], bh[p][hh], bh[p][hh + 1]);
                    MMA16816(acc[mt][nt], ah[mt], bl[p][hh], bl[p][hh + 1]);
                    MMA16816(acc[mt][nt], al[mt], bh[p][hh], bh[p][hh + 1]);
                }
        }
        __syncthreads();

        if (c + 1 < NCH) {
            char* st = dsm + ((c + 1) & 1) * STAGE_SB;
#pragma unroll
            for (int q = 0; q < 4; q++) {
                uint32_t h01, l01, h23, l23;
                cvt_pair(va[q].x, va[q].y, h01, l01);
                cvt_pair(va[q].z, va[q].w, h23, l23);
                *(uint2*)(st + soff + q * 8)             = make_uint2(h01, h23);
                *(uint2*)(st + TILE_SB + soff + q * 8)   = make_uint2(l01, l23);
                cvt_pair(vb[q].x, vb[q].y, h01, l01);
                cvt_pair(vb[q].z, vb[q].w, h23, l23);
                *(uint2*)(st + 2*TILE_SB + soff + q * 8) = make_uint2(h01, h23);
                *(uint2*)(st + 3*TILE_SB + soff + q * 8) = make_uint2(l01, l23);
            }
            __syncthreads();
        }
    }

    // Epilogue: acc frag (mt,nt): d0,d1 -> row lane/4, cols 2*(lane%4); d2,d3 -> row+8
    const int erow = wm * 64 + (lane >> 2);
    const int ecol = wn * 32 + (lane & 3) * 2;
#pragma unroll
    for (int mt = 0; mt < 4; mt++) {
#pragma unroll
        for (int nt = 0; nt < 4; nt++) {
            const int cc = ecol + nt * 8;
            const float b0 = sBias[cc], b1 = sBias[cc + 1];
            float* p0 = C + (size_t)(m0 + erow + mt * 16) * N + n0 + cc;
            float* p1 = C + (size_t)(m0 + erow + mt * 16 + 8) * N + n0 + cc;
            float2 v0 = {acc[mt][nt][0] + b0, acc[mt][nt][1] + b1};
            float2 v1 = {acc[mt][nt][2] + b0, acc[mt][nt][3] + b1};
            *(float2*)p0 = v0;
            *(float2*)p1 = v1;
        }
    }
}

// ---------------------------------------------------------------------------
// RoPE on q (slot 0) and k (slot 1), in place.
// ---------------------------------------------------------------------------
__global__ __launch_bounds__(256) void rope_kernel(float* __restrict__ qkv)
{
    const int total = BATCH * SEQ * 2 * HEADS * HDIM2;
    int idx = blockIdx.x * blockDim.x + threadIdx.x;
    if (idx >= total) return;

    int j  = idx % HDIM2;
    int h  = (idx / HDIM2) % HEADS;
    int qk = (idx / (HDIM2 * HEADS)) % 2;
    int s  = (idx / (HDIM2 * HEADS * 2)) % SEQ;
    int b  = idx / (HDIM2 * HEADS * 2 * SEQ);

    size_t base = ((((size_t)(b * SEQ + s)) * 3 + qk) * HEADS + h) * HDIM;

    float inv = powf(10000.0f, -(float)j / 64.0f);
    float ang = (float)s * inv;
    float sn, c;
    sincosf(ang, &sn, &c);

    float x1 = qkv[base + j];
    float x2 = qkv[base + HDIM2 + j];
    qkv[base + j]         = x1 * c - x2 * sn;
    qkv[base + HDIM2 + j] = x1 * sn + x2 * c;
}

// ---------------------------------------------------------------------------
// Flash attention, causal. BM=BN=64, D=128, 256 threads (16x16).
// ---------------------------------------------------------------------------
#define KV_STRIDE 132
#define P_STRIDE  68
#define FLASH_SMEM ((64*128 + 64*KV_STRIDE + 64*P_STRIDE) * (int)sizeof(float))

__global__ __launch_bounds__(256) void flash_attn(
    const float* __restrict__ qkv, float* __restrict__ ctx)
{
    extern __shared__ float sm[];
    float* Qs  = sm;
    float* KVs = sm + 64 * 128;
    float* Ps  = KVs + 64 * KV_STRIDE;

    const int qt = blockIdx.x;
    const int bh = blockIdx.y;
    const int b  = bh / HEADS;
    const int h  = bh % HEADS;
    const int tid = threadIdx.x;
    const int ty  = tid >> 4;
    const int tx  = tid & 15;
    const int q0  = qt * 64;
    const float scale = 0.08838834764831845f;

#pragma unroll
    for (int t = 0; t < 8; t++) {
        int i4 = tid + t * 256;
        int r  = i4 >> 5;
        int c  = (i4 & 31) * 4;
        size_t src = ((((size_t)(b * SEQ + q0 + r)) * 3 + 0) * HEADS + h) * HDIM + c;
        *(float4*)&Qs[r * 128 + c] = *(const float4*)(qkv + src);
    }

    float m_run[4], l_run[4];
    float o[4][8];
#pragma unroll
    for (int i = 0; i < 4; i++) {
        m_run[i] = -1e30f;
        l_run[i] = 0.0f;
#pragma unroll
        for (int j = 0; j < 8; j++) o[i][j] = 0.0f;
    }

    const int nkt = qt + 1;
    for (int kt = 0; kt < nkt; kt++) {
        const int k0 = kt * 64;
        __syncthreads();

#pragma unroll
        for (int t = 0; t < 8; t++) {
            int i4 = tid + t * 256;
            int r  = i4 >> 5;
            int c  = (i4 & 31) * 4;
            size_t src = ((((size_t)(b * SEQ + k0 + r)) * 3 + 1) * HEADS + h) * HDIM + c;
            *(float4*)&KVs[r * KV_STRIDE + c] = *(const float4*)(qkv + src);
        }
        __syncthreads();

        float sacc[4][4];
#pragma unroll
        for (int i = 0; i < 4; i++)
#pragma unroll
            for (int j = 0; j < 4; j++) sacc[i][j] = 0.0f;

        for (int kk = 0; kk < 128; kk += 4) {
            float4 rq[4], rk[4];
#pragma unroll
            for (int i = 0; i < 4; i++)
                rq[i] = *(const float4*)&Qs[(ty * 4 + i) * 128 + kk];
#pragma unroll
            for (int j = 0; j < 4; j++)
                rk[j] = *(const float4*)&KVs[(tx * 4 + j) * KV_STRIDE + kk];
#pragma unroll
            for (int i = 0; i < 4; i++)
#pragma unroll
                for (int j = 0; j < 4; j++) {
                    sacc[i][j] = fmaf(rq[i].x, rk[j].x, sacc[i][j]);
                    sacc[i][j] = fmaf(rq[i].y, rk[j].y, sacc[i][j]);
                    sacc[i][j] = fmaf(rq[i].z, rk[j].z, sacc[i][j]);
                    sacc[i][j] = fmaf(rq[i].w, rk[j].w, sacc[i][j]);
                }
        }

        const bool diag = (kt == qt);
#pragma unroll
        for (int i = 0; i < 4; i++) {
            const int rg = q0 + ty * 4 + i;
            float mx = -1e30f;
#pragma unroll
            for (int j = 0; j < 4; j++) {
                float sv = sacc[i][j] * scale;
                if (diag && (k0 + tx * 4 + j > rg)) sv = -1e30f;
                sacc[i][j] = sv;
                mx = fmaxf(mx, sv);
            }
#pragma unroll
            for (int off = 1; off < 16; off <<= 1)
                mx = fmaxf(mx, __shfl_xor_sync(0xffffffffu, mx, off));

            const float m_old = m_run[i];
            const float mnew  = fmaxf(m_old, mx);
            const float sf    = expf(m_old - mnew);
            m_run[i] = mnew;

            float ls = 0.0f;
#pragma unroll
            for (int j = 0; j < 4; j++) {
                float pv = expf(sacc[i][j] - mnew);
                Ps[(ty * 4 + i) * P_STRIDE + tx * 4 + j] = pv;
                ls += pv;
            }
#pragma unroll
            for (int off = 1; off < 16; off <<= 1)
                ls += __shfl_xor_sync(0xffffffffu, ls, off);

            l_run[i] = l_run[i] * sf + ls;
#pragma unroll
            for (int j = 0; j < 8; j++) o[i][j] *= sf;
        }

        __syncthreads();

#pragma unroll
        for (int t = 0; t < 8; t++) {
            int i4 = tid + t * 256;
            int r  = i4 >> 5;
            int c  = (i4 & 31) * 4;
            size_t src = ((((size_t)(b * SEQ + k0 + r)) * 3 + 2) * HEADS + h) * HDIM + c;
            *(float4*)&KVs[r * KV_STRIDE + c] = *(const float4*)(qkv + src);
        }
        __syncthreads();

        for (int kk = 0; kk < 64; kk++) {
            float rp[4];
#pragma unroll
            for (int i = 0; i < 4; i++)
                rp[i] = Ps[(ty * 4 + i) * P_STRIDE + kk];
            float4 rv0 = *(const float4*)&KVs[kk * KV_STRIDE + tx * 8];
            float4 rv1 = *(const float4*)&KVs[kk * KV_STRIDE + tx * 8 + 4];
            float rv[8] = {rv0.x, rv0.y, rv0.z, rv0.w, rv1.x, rv1.y, rv1.z, rv1.w};
#pragma unroll
            for (int i = 0; i < 4; i++)
#pragma unroll
                for (int j = 0; j < 8; j++)
                    o[i][j] = fmaf(rp[i], rv[j], o[i][j]);
        }
    }

#pragma unroll
    for (int i = 0; i < 4; i++) {
        float inv = 1.0f / l_run[i];
        int row = q0 + ty * 4 + i;
        float* dst = ctx + (size_t)(b * SEQ + row) * EMB + h * HDIM + tx * 8;
        float4 v0 = {o[i][0] * inv, o[i][1] * inv, o[i][2] * inv, o[i][3] * inv};
        float4 v1 = {o[i][4] * inv, o[i][5] * inv, o[i][6] * inv, o[i][7] * inv};
        *(float4*)dst = v0;
        *(float4*)(dst + 4) = v1;
    }
}

extern "C" void kernel_launch(void* const* d_in, const int* in_sizes, int n_in,
                              void* d_out, int out_size)
{
    const float* x      = (const float*)d_in[0];
    const float* wqkv_w = (const float*)d_in[1];
    const float* wqkv_b = (const float*)d_in[2];
    const float* out_w  = (const float*)d_in[3];
    const float* out_b  = (const float*)d_in[4];
    float* out = (float*)d_out;

    float *qkv, *ctx;
    cudaGetSymbolAddress((void**)&qkv, g_qkv);
    cudaGetSymbolAddress((void**)&ctx, g_ctx);

    cudaFuncSetAttribute(gemm_mma, cudaFuncAttributeMaxDynamicSharedMemorySize, GEMM_SMEM);
    cudaFuncSetAttribute(flash_attn, cudaFuncAttributeMaxDynamicSharedMemorySize, FLASH_SMEM);

    dim3 g1(THREE_E / 128, MROWS / 128);
    gemm_mma<<<g1, 256, GEMM_SMEM>>>(x, wqkv_w, wqkv_b, qkv, THREE_E, EMB);

    rope_kernel<<<(BATCH * SEQ * 2 * HEADS * HDIM2 + 255) / 256, 256>>>(qkv);

    dim3 g2(SEQ / 64, BATCH * HEADS);
    flash_attn<<<g2, 256, FLASH_SMEM>>>(qkv, ctx);

    dim3 g3(EMB / 128, MROWS / 128);
    gemm_mma<<<g3, 256, GEMM_SMEM>>>(ctx, out_w, out_b, out, EMB, EMB);
}

// round 4
// speedup vs baseline: 3.2088x; 2.0364x over previous
#include <cuda_runtime.h>
#include <cuda_bf16.h>
#include <math.h>
#include <stdint.h>

#define BATCH 2
#define SEQ   2048
#define EMB   2048
#define HEADS 16
#define HDIM  128
#define THREE_E 6144
#define MROWS (BATCH*SEQ)     // 4096
#define NBH   (BATCH*HEADS)   // 32

// ---------------- scratch (__device__ globals; no cudaMalloc) ----------------
__device__ float g_qkv[(size_t)MROWS * THREE_E];                 // fp32 QKV
__device__ __nv_bfloat16 g_xh[(size_t)MROWS * EMB],   g_xl[(size_t)MROWS * EMB];
__device__ __nv_bfloat16 g_wh[(size_t)THREE_E * EMB], g_wl[(size_t)THREE_E * EMB];
__device__ __nv_bfloat16 g_oh[(size_t)EMB * EMB],     g_ol[(size_t)EMB * EMB];
__device__ __nv_bfloat16 g_qhh[(size_t)NBH*SEQ*HDIM], g_qll[(size_t)NBH*SEQ*HDIM];
__device__ __nv_bfloat16 g_khh[(size_t)NBH*SEQ*HDIM], g_kll[(size_t)NBH*SEQ*HDIM];
__device__ __nv_bfloat16 g_vhh[(size_t)NBH*SEQ*HDIM], g_vll[(size_t)NBH*SEQ*HDIM];
__device__ __nv_bfloat16 g_ch[(size_t)MROWS * EMB],   g_cl[(size_t)MROWS * EMB];

// ---------------- PTX helpers ----------------
__device__ __forceinline__ uint32_t smem_u32(const void* p) {
    uint32_t a;
    asm("{ .reg .u64 t; cvta.to.shared.u64 t, %1; cvt.u32.u64 %0, t; }"
        : "=r"(a) : "l"(p));
    return a;
}
// fp32 pair -> hi bf16x2 + residual-lo bf16x2 (f0 in low half)
__device__ __forceinline__ void cvt_pair(float f0, float f1,
                                         uint32_t& h, uint32_t& l) {
    asm("cvt.rn.bf16x2.f32 %0, %1, %2;" : "=r"(h) : "f"(f1), "f"(f0));
    float h0 = __uint_as_float(h << 16);
    float h1 = __uint_as_float(h & 0xffff0000u);
    asm("cvt.rn.bf16x2.f32 %0, %1, %2;" : "=r"(l) : "f"(f1 - h1), "f"(f0 - h0));
}
#define LDMX4(r0, r1, r2, r3, addr) \
    asm volatile("ldmatrix.sync.aligned.m8n8.x4.shared.b16 {%0,%1,%2,%3}, [%4];" \
        : "=r"(r0), "=r"(r1), "=r"(r2), "=r"(r3) : "r"(addr))
#define LDMT4(r0, r1, r2, r3, addr) \
    asm volatile("ldmatrix.sync.aligned.m8n8.x4.trans.shared.b16 {%0,%1,%2,%3}, [%4];" \
        : "=r"(r0), "=r"(r1), "=r"(r2), "=r"(r3) : "r"(addr))
#define MMA16816(d, a, b0, b1) \
    asm volatile("mma.sync.aligned.m16n8k16.row.col.f32.bf16.bf16.f32 " \
        "{%0,%1,%2,%3}, {%4,%5,%6,%7}, {%8,%9}, {%0,%1,%2,%3};" \
        : "+f"((d)[0]), "+f"((d)[1]), "+f"((d)[2]), "+f"((d)[3]) \
        : "r"((a)[0]), "r"((a)[1]), "r"((a)[2]), "r"((a)[3]), "r"(b0), "r"(b1))
#define CP16(dst, src) \
    asm volatile("cp.async.cg.shared.global [%0], [%1], 16;" :: "r"(dst), "l"(src))
#define CPCOMMIT() asm volatile("cp.async.commit_group;" ::: "memory")
#define CPWAIT0()  asm volatile("cp.async.wait_group 0;" ::: "memory")
#define CPWAIT1()  asm volatile("cp.async.wait_group 1;" ::: "memory")

// ---------------------------------------------------------------------------
// Prep: fp32 -> (hi, lo) bf16 split, vectorized by 4
// ---------------------------------------------------------------------------
__global__ void split_f32(const float4* __restrict__ in,
                          uint2* __restrict__ hi, uint2* __restrict__ lo, int n4)
{
    int i = blockIdx.x * blockDim.x + threadIdx.x;
    if (i >= n4) return;
    float4 v = in[i];
    uint32_t h01, l01, h23, l23;
    cvt_pair(v.x, v.y, h01, l01);
    cvt_pair(v.z, v.w, h23, l23);
    hi[i] = make_uint2(h01, h23);
    lo[i] = make_uint2(l01, l23);
}

// ---------------------------------------------------------------------------
// Split-bf16 tensor GEMM, preconverted operands + cp.async 3-stage pipeline
// C[M,N] = A[M,K] @ B[N,K]^T + bias ; BM=BN=128, BK=32, 256 thr, 8 warps
// ---------------------------------------------------------------------------
#define LDS 40
#define TILE_SB (128 * LDS * 2)     // 10240 B
#define STAGE_SB (4 * TILE_SB)      // Ah, Al, Bh, Bl
#define GEMM_SMEM (3 * STAGE_SB)    // 122880 B

__device__ __forceinline__ void gemm_issue(
    const __nv_bfloat16* Ah, const __nv_bfloat16* Al,
    const __nv_bfloat16* Bh, const __nv_bfloat16* Bl,
    uint32_t sbase, int m0, int n0, int K, int cc, int tid)
{
    const uint32_t stg = sbase + (uint32_t)(cc % 3) * STAGE_SB;
    const int k0 = cc * 32;
#pragma unroll
    for (int i = 0; i < 2; i++) {
        int c  = tid + i * 256;         // 0..511
        int r  = c >> 2;                // 0..127
        int sg = c & 3;                 // 16B segment
        uint32_t dof = (uint32_t)(r * 80 + sg * 16);
        size_t ao = (size_t)(m0 + r) * K + k0 + sg * 8;
        size_t bo = (size_t)(n0 + r) * K + k0 + sg * 8;
        CP16(stg + 0 * TILE_SB + dof, (const char*)(Ah + ao));
        CP16(stg + 1 * TILE_SB + dof, (const char*)(Al + ao));
        CP16(stg + 2 * TILE_SB + dof, (const char*)(Bh + bo));
        CP16(stg + 3 * TILE_SB + dof, (const char*)(Bl + bo));
    }
    CPCOMMIT();
}

__global__ __launch_bounds__(256, 1) void gemm_bf16(
    const __nv_bfloat16* __restrict__ Ah, const __nv_bfloat16* __restrict__ Al,
    const __nv_bfloat16* __restrict__ Bh, const __nv_bfloat16* __restrict__ Bl,
    const float* __restrict__ bias, float* __restrict__ C, int N, int K)
{
    extern __shared__ char dsm[];
    __shared__ float sBias[128];

    const int tid  = threadIdx.x;
    const int lane = tid & 31;
    const int wid  = tid >> 5;
    const int wm   = wid >> 2;
    const int wn   = wid & 3;
    const int m0 = blockIdx.y * 128, n0 = blockIdx.x * 128;
    const uint32_t sbase = smem_u32(dsm);

    if (tid < 128) sBias[tid] = bias[n0 + tid];

    const int NCH = K >> 5;
    gemm_issue(Ah, Al, Bh, Bl, sbase, m0, n0, K, 0, tid);
    gemm_issue(Ah, Al, Bh, Bl, sbase, m0, n0, K, 1, tid);

    float acc[4][4][4];
#pragma unroll
    for (int mt = 0; mt < 4; mt++)
#pragma unroll
        for (int nt = 0; nt < 4; nt++)
#pragma unroll
            for (int r = 0; r < 4; r++) acc[mt][nt][r] = 0.0f;

    const uint32_t a_row  = (uint32_t)(wm * 64 + (lane & 15));
    const uint32_t a_koff = (uint32_t)((lane >> 4) * 8);
    const uint32_t b_row  = (uint32_t)(wn * 32 + (lane & 7) + ((lane >> 4) << 3));
    const uint32_t b_koff = (uint32_t)(((lane >> 3) & 1) * 8);

    for (int c = 0; c < NCH; c++) {
        CPWAIT1();            // group c complete (always exactly 2 pending groups)
        __syncthreads();      // visibility of all threads' copies
        if (c + 2 < NCH) gemm_issue(Ah, Al, Bh, Bl, sbase, m0, n0, K, c + 2, tid);
        else CPCOMMIT();      // keep group count uniform

        const uint32_t stg = sbase + (uint32_t)(c % 3) * STAGE_SB;
#pragma unroll
        for (int ks = 0; ks < 2; ks++) {
            const uint32_t kofs = (uint32_t)(ks * 16);
            uint32_t ah[4][4], al[4][4];
#pragma unroll
            for (int mt = 0; mt < 4; mt++) {
                uint32_t adr = stg + ((a_row + mt * 16) * LDS + kofs + a_koff) * 2;
                LDMX4(ah[mt][0], ah[mt][1], ah[mt][2], ah[mt][3], adr);
                LDMX4(al[mt][0], al[mt][1], al[mt][2], al[mt][3], adr + TILE_SB);
            }
            uint32_t bh[2][4], bl[2][4];
#pragma unroll
            for (int p = 0; p < 2; p++) {
                uint32_t adr = stg + 2 * TILE_SB
                             + ((b_row + p * 16) * LDS + kofs + b_koff) * 2;
                LDMX4(bh[p][0], bh[p][1], bh[p][2], bh[p][3], adr);
                LDMX4(bl[p][0], bl[p][1], bl[p][2], bl[p][3], adr + TILE_SB);
            }
#pragma unroll
            for (int mt = 0; mt < 4; mt++)
#pragma unroll
                for (int nt = 0; nt < 4; nt++) {
                    const int p = nt >> 1, hh = (nt & 1) * 2;
                    MMA16816(acc[mt][nt], ah[mt], bh[p][hh], bh[p][hh + 1]);
                    MMA16816(acc[mt][nt], ah[mt], bl[p][hh], bl[p][hh + 1]);
                    MMA16816(acc[mt][nt], al[mt], bh[p][hh], bh[p][hh + 1]);
                }
        }
    }

    const int erow = wm * 64 + (lane >> 2);
    const int ecol = wn * 32 + (lane & 3) * 2;
#pragma unroll
    for (int mt = 0; mt < 4; mt++) {
#pragma unroll
        for (int nt = 0; nt < 4; nt++) {
            const int cc = ecol + nt * 8;
            const float b0 = sBias[cc], b1 = sBias[cc + 1];
            float* p0 = C + (size_t)(m0 + erow + mt * 16) * N + n0 + cc;
            float* p1 = C + (size_t)(m0 + erow + mt * 16 + 8) * N + n0 + cc;
            float2 v0 = {acc[mt][nt][0] + b0, acc[mt][nt][1] + b1};
            float2 v1 = {acc[mt][nt][2] + b0, acc[mt][nt][3] + b1};
            *(float2*)p0 = v0;
            *(float2*)p1 = v1;
        }
    }
}

// ---------------------------------------------------------------------------
// RoPE + layout change + hi/lo split: g_qkv fp32 [b][s][3][h][d]
//   -> Q/K/V hi/lo bf16 [bh][s][d]; Q pre-scaled by 1/sqrt(D)
// ---------------------------------------------------------------------------
__device__ __forceinline__ void split1(float x, __nv_bfloat16* ph, __nv_bfloat16* pl) {
    __nv_bfloat16 h = __float2bfloat16(x);
    *ph = h;
    *pl = __float2bfloat16(x - __bfloat162float(h));
}

__global__ __launch_bounds__(256) void rope_split(
    const float* __restrict__ qkv,
    __nv_bfloat16* __restrict__ Qh, __nv_bfloat16* __restrict__ Ql,
    __nv_bfloat16* __restrict__ Kh, __nv_bfloat16* __restrict__ Kl,
    __nv_bfloat16* __restrict__ Vh, __nv_bfloat16* __restrict__ Vl)
{
    int idx = blockIdx.x * blockDim.x + threadIdx.x;   // NBH*SEQ*64
    if (idx >= NBH * SEQ * 64) return;
    int j  = idx & 63;
    int s  = (idx >> 6) & (SEQ - 1);
    int bh = idx >> 17;
    int b = bh >> 4, h = bh & 15;

    size_t base = ((size_t)(b * SEQ + s) * 3) * EMB + h * HDIM;
    size_t dst  = ((size_t)bh * SEQ + s) * HDIM + j;
    const float scale = 0.08838834764831845f;

    float inv = powf(10000.0f, -(float)j / 64.0f);
    float ang = (float)s * inv;
    float sn, cs;
    sincosf(ang, &sn, &cs);

    // Q (slot 0), rope + scale
    float q1 = qkv[base + j], q2 = qkv[base + 64 + j];
    split1((q1 * cs - q2 * sn) * scale, Qh + dst, Ql + dst);
    split1((q1 * sn + q2 * cs) * scale, Qh + dst + 64, Ql + dst + 64);
    // K (slot 1), rope
    float k1 = qkv[base + EMB + j], k2 = qkv[base + EMB + 64 + j];
    split1(k1 * cs - k2 * sn, Kh + dst, Kl + dst);
    split1(k1 * sn + k2 * cs, Kh + dst + 64, Kl + dst + 64);
    // V (slot 2), plain split
    float v1 = qkv[base + 2 * EMB + j], v2 = qkv[base + 2 * EMB + 64 + j];
    split1(v1, Vh + dst, Vl + dst);
    split1(v2, Vh + dst + 64, Vl + dst + 64);
}

// ---------------------------------------------------------------------------
// Flash attention on mma.sync, causal, split-bf16 for QK^T and PV.
// 128 threads (4 warps x 16 q-rows), 64x64 KV tiles, D=128.
// Output: ctx hi/lo bf16 [b][s][E].
// ---------------------------------------------------------------------------
#define FL_STRIDE_B 272                  // 136 bf16 per smem row
#define FL_TILE (64 * FL_STRIDE_B)       // 17408 B
#define FLASH_SMEM (6 * FL_TILE)         // Qh Ql Kh Kl Vh Vl = 104448 B

__global__ __launch_bounds__(128, 2) void flash_mma(
    const __nv_bfloat16* __restrict__ Qh, const __nv_bfloat16* __restrict__ Ql,
    const __nv_bfloat16* __restrict__ Kh, const __nv_bfloat16* __restrict__ Kl,
    const __nv_bfloat16* __restrict__ Vh, const __nv_bfloat16* __restrict__ Vl,
    __nv_bfloat16* __restrict__ ctxh, __nv_bfloat16* __restrict__ ctxl)
{
    extern __shared__ char fsm[];
    const int qt = gridDim.x - 1 - blockIdx.x;   // heavy tiles first
    const int bh = blockIdx.y;
    const int tid = threadIdx.x, lane = tid & 31, w = tid >> 5;
    const int q0 = qt * 64;
    const uint32_t sb = smem_u32(fsm);

    // Load Q hi/lo tiles (plain vector loads; visible after first barrier)
    {
        const size_t qo = ((size_t)bh * SEQ + q0) * HDIM;
#pragma unroll
        for (int i = 0; i < 8; i++) {
            int c = tid + i * 128;       // 0..1023
            int r = c >> 4, sg = c & 15;
            *(uint4*)(fsm + 0 * FL_TILE + r * FL_STRIDE_B + sg * 16) =
                *(const uint4*)(Qh + qo + r * HDIM + sg * 8);
            *(uint4*)(fsm + 1 * FL_TILE + r * FL_STRIDE_B + sg * 16) =
                *(const uint4*)(Ql + qo + r * HDIM + sg * 8);
        }
    }

    float m0v = -1e30f, m1v = -1e30f, l0v = 0.0f, l1v = 0.0f;
    float o[16][4];
#pragma unroll
    for (int nt = 0; nt < 16; nt++)
#pragma unroll
        for (int r = 0; r < 4; r++) o[nt][r] = 0.0f;

    const uint32_t a_row  = (uint32_t)(w * 16 + (lane & 15));
    const uint32_t a_koff = (uint32_t)((lane >> 4) * 8);
    const uint32_t b_row  = (uint32_t)((lane & 7) + ((lane >> 4) << 3));
    const uint32_t b_koff = (uint32_t)(((lane >> 3) & 1) * 8);
    const uint32_t v_row  = (uint32_t)(lane & 15);
    const uint32_t v_coff = (uint32_t)((lane >> 4) * 8);

    for (int kt = 0; kt <= qt; kt++) {
        __syncthreads();   // K/V/Q buffers free (prev iter fully consumed)

        // async copy K then V (two groups)
        const size_t ko = ((size_t)bh * SEQ + kt * 64) * HDIM;
#pragma unroll
        for (int i = 0; i < 8; i++) {
            int c = tid + i * 128;
            int r = c >> 4, sg = c & 15;
            uint32_t dof = (uint32_t)(r * FL_STRIDE_B + sg * 16);
            size_t so = ko + r * HDIM + sg * 8;
            CP16(sb + 2 * FL_TILE + dof, (const char*)(Kh + so));
            CP16(sb + 3 * FL_TILE + dof, (const char*)(Kl + so));
        }
        CPCOMMIT();
#pragma unroll
        for (int i = 0; i < 8; i++) {
            int c = tid + i * 128;
            int r = c >> 4, sg = c & 15;
            uint32_t dof = (uint32_t)(r * FL_STRIDE_B + sg * 16);
            size_t so = ko + r * HDIM + sg * 8;
            CP16(sb + 4 * FL_TILE + dof, (const char*)(Vh + so));
            CP16(sb + 5 * FL_TILE + dof, (const char*)(Vl + so));
        }
        CPCOMMIT();

        CPWAIT1();          // K done
        __syncthreads();

        // ---- S = Qh Kh^T + Qh Kl^T + Ql Kh^T ----
        float s[8][4];
#pragma unroll
        for (int nt = 0; nt < 8; nt++)
#pragma unroll
            for (int r = 0; r < 4; r++) s[nt][r] = 0.0f;

#pragma unroll
        for (int ks = 0; ks < 8; ks++) {
            uint32_t qh[4], ql[4];
            uint32_t qadr = sb + 0 * FL_TILE + a_row * FL_STRIDE_B
                          + (ks * 16 + a_koff) * 2;
            LDMX4(qh[0], qh[1], qh[2], qh[3], qadr);
            LDMX4(ql[0], ql[1], ql[2], ql[3], qadr + FL_TILE);
#pragma unroll
            for (int np = 0; np < 4; np++) {
                uint32_t khf[4], klf[4];
                uint32_t kadr = sb + 2 * FL_TILE
                              + (np * 16 + b_row) * FL_STRIDE_B
                              + (ks * 16 + b_koff) * 2;
                LDMX4(khf[0], khf[1], khf[2], khf[3], kadr);
                LDMX4(klf[0], klf[1], klf[2], klf[3], kadr + FL_TILE);
                MMA16816(s[2*np],   qh, khf[0], khf[1]);
                MMA16816(s[2*np],   qh, klf[0], klf[1]);
                MMA16816(s[2*np],   ql, khf[0], khf[1]);
                MMA16816(s[2*np+1], qh, khf[2], khf[3]);
                MMA16816(s[2*np+1], qh, klf[2], klf[3]);
                MMA16816(s[2*np+1], ql, khf[2], khf[3]);
            }
        }

        // ---- causal mask on diagonal tile ----
        if (kt == qt) {
            const int r0 = w * 16 + (lane >> 2);
            const int r1 = r0 + 8;
#pragma unroll
            for (int nt = 0; nt < 8; nt++) {
                const int cb = nt * 8 + (lane & 3) * 2;
                if (cb     > r0) s[nt][0] = -1e30f;
                if (cb + 1 > r0) s[nt][1] = -1e30f;
                if (cb     > r1) s[nt][2] = -1e30f;
                if (cb + 1 > r1) s[nt][3] = -1e30f;
            }
        }

        // ---- online softmax (rows spread over lane quads) ----
        float mx0 = -1e30f, mx1 = -1e30f;
#pragma unroll
        for (int nt = 0; nt < 8; nt++) {
            mx0 = fmaxf(mx0, fmaxf(s[nt][0], s[nt][1]));
            mx1 = fmaxf(mx1, fmaxf(s[nt][2], s[nt][3]));
        }
        mx0 = fmaxf(mx0, __shfl_xor_sync(0xffffffffu, mx0, 1));
        mx0 = fmaxf(mx0, __shfl_xor_sync(0xffffffffu, mx0, 2));
        mx1 = fmaxf(mx1, __shfl_xor_sync(0xffffffffu, mx1, 1));
        mx1 = fmaxf(mx1, __shfl_xor_sync(0xffffffffu, mx1, 2));

        float mn0 = fmaxf(m0v, mx0), mn1 = fmaxf(m1v, mx1);
        float sf0 = __expf(m0v - mn0), sf1 = __expf(m1v - mn1);
        m0v = mn0; m1v = mn1;

        float ls0 = 0.0f, ls1 = 0.0f;
#pragma unroll
        for (int nt = 0; nt < 8; nt++) {
            s[nt][0] = __expf(s[nt][0] - mn0); ls0 += s[nt][0];
            s[nt][1] = __expf(s[nt][1] - mn0); ls0 += s[nt][1];
            s[nt][2] = __expf(s[nt][2] - mn1); ls1 += s[nt][2];
            s[nt][3] = __expf(s[nt][3] - mn1); ls1 += s[nt][3];
        }
        ls0 += __shfl_xor_sync(0xffffffffu, ls0, 1);
        ls0 += __shfl_xor_sync(0xffffffffu, ls0, 2);
        ls1 += __shfl_xor_sync(0xffffffffu, ls1, 1);
        ls1 += __shfl_xor_sync(0xffffffffu, ls1, 2);
        l0v = l0v * sf0 + ls0;
        l1v = l1v * sf1 + ls1;
#pragma unroll
        for (int nt = 0; nt < 16; nt++) {
            o[nt][0] *= sf0; o[nt][1] *= sf0;
            o[nt][2] *= sf1; o[nt][3] *= sf1;
        }

        // ---- P fragments (registers -> bf16 hi/lo A-frags) ----
        uint32_t ph[4][4], pl[4][4];
#pragma unroll
        for (int k2 = 0; k2 < 4; k2++) {
            cvt_pair(s[2*k2][0],   s[2*k2][1],   ph[k2][0], pl[k2][0]);
            cvt_pair(s[2*k2][2],   s[2*k2][3],   ph[k2][1], pl[k2][1]);
            cvt_pair(s[2*k2+1][0], s[2*k2+1][1], ph[k2][2], pl[k2][2]);
            cvt_pair(s[2*k2+1][2], s[2*k2+1][3], ph[k2][3], pl[k2][3]);
        }

        CPWAIT0();          // V done
        __syncthreads();

        // ---- O += Ph Vh + Ph Vl + Pl Vh ----
#pragma unroll
        for (int k2 = 0; k2 < 4; k2++) {
#pragma unroll
            for (int np = 0; np < 8; np++) {
                uint32_t vhf[4], vlf[4];
                uint32_t vadr = sb + 4 * FL_TILE
                              + (k2 * 16 + v_row) * FL_STRIDE_B
                              + (np * 16 + v_coff) * 2;
                LDMT4(vhf[0], vhf[1], vhf[2], vhf[3], vadr);
                LDMT4(vlf[0], vlf[1], vlf[2], vlf[3], vadr + FL_TILE);
                MMA16816(o[2*np],   ph[k2], vhf[0], vhf[1]);
                MMA16816(o[2*np],   ph[k2], vlf[0], vlf[1]);
                MMA16816(o[2*np],   pl[k2], vhf[0], vhf[1]);
                MMA16816(o[2*np+1], ph[k2], vhf[2], vhf[3]);
                MMA16816(o[2*np+1], ph[k2], vlf[2], vlf[3]);
                MMA16816(o[2*np+1], pl[k2], vhf[2], vhf[3]);
            }
        }
    }

    // ---- epilogue: ctx = O / l, split to bf16 hi/lo ----
    const float inv0 = 1.0f / l0v, inv1 = 1.0f / l1v;
    const int b = bh >> 4, h = bh & 15;
    const int gr0 = q0 + w * 16 + (lane >> 2);
    const size_t ro0 = (size_t)(b * SEQ + gr0) * EMB + h * HDIM;
    const size_t ro1 = (size_t)(b * SEQ + gr0 + 8) * EMB + h * HDIM;
#pragma unroll
    for (int nt = 0; nt < 16; nt++) {
        const int col = nt * 8 + (lane & 3) * 2;
        uint32_t hh, ll;
        cvt_pair(o[nt][0] * inv0, o[nt][1] * inv0, hh, ll);
        *(uint32_t*)(ctxh + ro0 + col) = hh;
        *(uint32_t*)(ctxl + ro0 + col) = ll;
        cvt_pair(o[nt][2] * inv1, o[nt][3] * inv1, hh, ll);
        *(uint32_t*)(ctxh + ro1 + col) = hh;
        *(uint32_t*)(ctxl + ro1 + col) = ll;
    }
}

// ---------------------------------------------------------------------------
extern "C" void kernel_launch(void* const* d_in, const int* in_sizes, int n_in,
                              void* d_out, int out_size)
{
    const float* x      = (const float*)d_in[0];
    const float* wqkv_w = (const float*)d_in[1];
    const float* wqkv_b = (const float*)d_in[2];
    const float* out_w  = (const float*)d_in[3];
    const float* out_b  = (const float*)d_in[4];
    float* out = (float*)d_out;

    float* qkv;
    __nv_bfloat16 *xh, *xl, *wh, *wl, *oh, *ol;
    __nv_bfloat16 *qh, *ql, *kh, *kl, *vh, *vl, *ch, *cl;
    cudaGetSymbolAddress((void**)&qkv, g_qkv);
    cudaGetSymbolAddress((void**)&xh, g_xh);  cudaGetSymbolAddress((void**)&xl, g_xl);
    cudaGetSymbolAddress((void**)&wh, g_wh);  cudaGetSymbolAddress((void**)&wl, g_wl);
    cudaGetSymbolAddress((void**)&oh, g_oh);  cudaGetSymbolAddress((void**)&ol, g_ol);
    cudaGetSymbolAddress((void**)&qh, g_qhh); cudaGetSymbolAddress((void**)&ql, g_qll);
    cudaGetSymbolAddress((void**)&kh, g_khh); cudaGetSymbolAddress((void**)&kl, g_kll);
    cudaGetSymbolAddress((void**)&vh, g_vhh); cudaGetSymbolAddress((void**)&vl, g_vll);
    cudaGetSymbolAddress((void**)&ch, g_ch);  cudaGetSymbolAddress((void**)&cl, g_cl);

    cudaFuncSetAttribute(gemm_bf16, cudaFuncAttributeMaxDynamicSharedMemorySize, GEMM_SMEM);
    cudaFuncSetAttribute(flash_mma, cudaFuncAttributeMaxDynamicSharedMemorySize, FLASH_SMEM);

    // hi/lo splits of GEMM operands
    int n4;
    n4 = MROWS * EMB / 4;
    split_f32<<<(n4 + 255) / 256, 256>>>((const float4*)x, (uint2*)xh, (uint2*)xl, n4);
    n4 = THREE_E * EMB / 4;
    split_f32<<<(n4 + 255) / 256, 256>>>((const float4*)wqkv_w, (uint2*)wh, (uint2*)wl, n4);
    n4 = EMB * EMB / 4;
    split_f32<<<(n4 + 255) / 256, 256>>>((const float4*)out_w, (uint2*)oh, (uint2*)ol, n4);

    // QKV projection
    dim3 g1(THREE_E / 128, MROWS / 128);
    gemm_bf16<<<g1, 256, GEMM_SMEM>>>(xh, xl, wh, wl, wqkv_b, qkv, THREE_E, EMB);

    // RoPE + layout + split
    int nr = NBH * SEQ * 64;
    rope_split<<<(nr + 255) / 256, 256>>>(qkv, qh, ql, kh, kl, vh, vl);

    // attention
    dim3 g2(SEQ / 64, NBH);
    flash_mma<<<g2, 128, FLASH_SMEM>>>(qh, ql, kh, kl, vh, vl, ch, cl);

    // output projection
    dim3 g3(EMB / 128, MROWS / 128);
    gemm_bf16<<<g3, 256, GEMM_SMEM>>>(ch, cl, oh, ol, out_b, out, EMB, EMB);
}

// round 5
// speedup vs baseline: 3.4090x; 1.0624x over previous
#include <cuda_runtime.h>
#include <cuda_bf16.h>
#include <math.h>
#include <stdint.h>

#define BATCH 2
#define SEQ   2048
#define EMB   2048
#define HEADS 16
#define HDIM  128
#define THREE_E 6144
#define MROWS (BATCH*SEQ)     // 4096
#define NBH   (BATCH*HEADS)   // 32

// ---------------- scratch (__device__ globals; no cudaMalloc) ----------------
__device__ float g_qkv[(size_t)MROWS * THREE_E];                 // fp32 QKV
__device__ __nv_bfloat16 g_xh[(size_t)MROWS * EMB],   g_xl[(size_t)MROWS * EMB];
__device__ __nv_bfloat16 g_wh[(size_t)THREE_E * EMB], g_wl[(size_t)THREE_E * EMB];
__device__ __nv_bfloat16 g_oh[(size_t)EMB * EMB],     g_ol[(size_t)EMB * EMB];
__device__ __nv_bfloat16 g_qhh[(size_t)NBH*SEQ*HDIM], g_qll[(size_t)NBH*SEQ*HDIM];
__device__ __nv_bfloat16 g_khh[(size_t)NBH*SEQ*HDIM], g_kll[(size_t)NBH*SEQ*HDIM];
__device__ __nv_bfloat16 g_vhh[(size_t)NBH*SEQ*HDIM], g_vll[(size_t)NBH*SEQ*HDIM];
__device__ __nv_bfloat16 g_ch[(size_t)MROWS * EMB],   g_cl[(size_t)MROWS * EMB];

// ---------------- PTX helpers ----------------
__device__ __forceinline__ uint32_t smem_u32(const void* p) {
    uint32_t a;
    asm("{ .reg .u64 t; cvta.to.shared.u64 t, %1; cvt.u32.u64 %0, t; }"
        : "=r"(a) : "l"(p));
    return a;
}
// fp32 pair -> hi bf16x2 + residual-lo bf16x2 (f0 in low half)
__device__ __forceinline__ void cvt_pair(float f0, float f1,
                                         uint32_t& h, uint32_t& l) {
    asm("cvt.rn.bf16x2.f32 %0, %1, %2;" : "=r"(h) : "f"(f1), "f"(f0));
    float h0 = __uint_as_float(h << 16);
    float h1 = __uint_as_float(h & 0xffff0000u);
    asm("cvt.rn.bf16x2.f32 %0, %1, %2;" : "=r"(l) : "f"(f1 - h1), "f"(f0 - h0));
}
#define LDMX4(r0, r1, r2, r3, addr) \
    asm volatile("ldmatrix.sync.aligned.m8n8.x4.shared.b16 {%0,%1,%2,%3}, [%4];" \
        : "=r"(r0), "=r"(r1), "=r"(r2), "=r"(r3) : "r"(addr))
#define LDMT4(r0, r1, r2, r3, addr) \
    asm volatile("ldmatrix.sync.aligned.m8n8.x4.trans.shared.b16 {%0,%1,%2,%3}, [%4];" \
        : "=r"(r0), "=r"(r1), "=r"(r2), "=r"(r3) : "r"(addr))
#define MMA16816(d, a, b0, b1) \
    asm volatile("mma.sync.aligned.m16n8k16.row.col.f32.bf16.bf16.f32 " \
        "{%0,%1,%2,%3}, {%4,%5,%6,%7}, {%8,%9}, {%0,%1,%2,%3};" \
        : "+f"((d)[0]), "+f"((d)[1]), "+f"((d)[2]), "+f"((d)[3]) \
        : "r"((a)[0]), "r"((a)[1]), "r"((a)[2]), "r"((a)[3]), "r"(b0), "r"(b1))
#define CP16(dst, src) \
    asm volatile("cp.async.cg.shared.global [%0], [%1], 16;" :: "r"(dst), "l"(src))
#define CPCOMMIT() asm volatile("cp.async.commit_group;" ::: "memory")
#define CPWAIT0()  asm volatile("cp.async.wait_group 0;" ::: "memory")
#define CPWAIT1()  asm volatile("cp.async.wait_group 1;" ::: "memory")

// ---------------------------------------------------------------------------
// Prep: fp32 -> (hi, lo) bf16 split, vectorized by 4
// ---------------------------------------------------------------------------
__global__ void split_f32(const float4* __restrict__ in,
                          uint2* __restrict__ hi, uint2* __restrict__ lo, int n4)
{
    int i = blockIdx.x * blockDim.x + threadIdx.x;
    if (i >= n4) return;
    float4 v = in[i];
    uint32_t h01, l01, h23, l23;
    cvt_pair(v.x, v.y, h01, l01);
    cvt_pair(v.z, v.w, h23, l23);
    hi[i] = make_uint2(h01, h23);
    lo[i] = make_uint2(l01, l23);
}

// ---------------------------------------------------------------------------
// Split-bf16 tensor GEMM: C[M,N] = A[M,K] @ B[N,K]^T + bias
// BM=128, BN=256, BK=32, 512 threads = 16 warps (2m x 8n), warp tile 64x32.
// 3-stage cp.async pipeline. 3-product split (AhBh + AhBl + AlBh).
// ---------------------------------------------------------------------------
#define LDS 40
#define A_SB (128 * LDS * 2)        // 10240 B per A bf16 tile
#define B_SB (256 * LDS * 2)        // 20480 B per B bf16 tile
#define STAGE_SB (2 * A_SB + 2 * B_SB)   // 61440 B
#define GEMM_SMEM (3 * STAGE_SB)         // 184320 B

__device__ __forceinline__ void gemm_issue(
    const __nv_bfloat16* Ah, const __nv_bfloat16* Al,
    const __nv_bfloat16* Bh, const __nv_bfloat16* Bl,
    uint32_t sbase, int m0, int n0, int K, int cc, int tid)
{
    const uint32_t stg = sbase + (uint32_t)(cc % 3) * STAGE_SB;
    const int k0 = cc * 32;
    // A: 512 segments (128 rows x 4 x 16B) per tile -> 1 per thread
    {
        int r = tid >> 2, sg = tid & 3;
        uint32_t dof = (uint32_t)(r * 80 + sg * 16);
        size_t ao = (size_t)(m0 + r) * K + k0 + sg * 8;
        CP16(stg + dof, (const char*)(Ah + ao));
        CP16(stg + A_SB + dof, (const char*)(Al + ao));
    }
    // B: 1024 segments (256 rows x 4 x 16B) per tile -> 2 per thread
#pragma unroll
    for (int i = 0; i < 2; i++) {
        int c = tid + i * 512;
        int r = c >> 2, sg = c & 3;
        uint32_t dof = (uint32_t)(r * 80 + sg * 16);
        size_t bo = (size_t)(n0 + r) * K + k0 + sg * 8;
        CP16(stg + 2 * A_SB + dof, (const char*)(Bh + bo));
        CP16(stg + 2 * A_SB + B_SB + dof, (const char*)(Bl + bo));
    }
    CPCOMMIT();
}

__global__ __launch_bounds__(512, 1) void gemm_bf16(
    const __nv_bfloat16* __restrict__ Ah, const __nv_bfloat16* __restrict__ Al,
    const __nv_bfloat16* __restrict__ Bh, const __nv_bfloat16* __restrict__ Bl,
    const float* __restrict__ bias, float* __restrict__ C, int N, int K)
{
    extern __shared__ char dsm[];
    __shared__ float sBias[256];

    const int tid  = threadIdx.x;
    const int lane = tid & 31;
    const int wid  = tid >> 5;
    const int wm   = wid >> 3;        // 0..1
    const int wn   = wid & 7;         // 0..7
    const int m0 = blockIdx.y * 128, n0 = blockIdx.x * 256;
    const uint32_t sbase = smem_u32(dsm);

    if (tid < 256) sBias[tid] = bias[n0 + tid];

    const int NCH = K >> 5;
    gemm_issue(Ah, Al, Bh, Bl, sbase, m0, n0, K, 0, tid);
    gemm_issue(Ah, Al, Bh, Bl, sbase, m0, n0, K, 1, tid);

    float acc[4][4][4];
#pragma unroll
    for (int mt = 0; mt < 4; mt++)
#pragma unroll
        for (int nt = 0; nt < 4; nt++)
#pragma unroll
            for (int r = 0; r < 4; r++) acc[mt][nt][r] = 0.0f;

    const uint32_t a_row  = (uint32_t)(wm * 64 + (lane & 15));
    const uint32_t a_koff = (uint32_t)((lane >> 4) * 8);
    const uint32_t b_row  = (uint32_t)(wn * 32 + (lane & 7) + ((lane >> 4) << 3));
    const uint32_t b_koff = (uint32_t)(((lane >> 3) & 1) * 8);

    for (int c = 0; c < NCH; c++) {
        CPWAIT1();            // group c complete (2 groups always pending)
        __syncthreads();
        if (c + 2 < NCH) gemm_issue(Ah, Al, Bh, Bl, sbase, m0, n0, K, c + 2, tid);
        else CPCOMMIT();      // keep group count uniform

        const uint32_t stg = sbase + (uint32_t)(c % 3) * STAGE_SB;
#pragma unroll
        for (int ks = 0; ks < 2; ks++) {
            const uint32_t kofs = (uint32_t)(ks * 16);
            uint32_t ah[4][4], al[4][4];
#pragma unroll
            for (int mt = 0; mt < 4; mt++) {
                uint32_t adr = stg + ((a_row + mt * 16) * LDS + kofs + a_koff) * 2;
                LDMX4(ah[mt][0], ah[mt][1], ah[mt][2], ah[mt][3], adr);
                LDMX4(al[mt][0], al[mt][1], al[mt][2], al[mt][3], adr + A_SB);
            }
            uint32_t bh[2][4], bl[2][4];
#pragma unroll
            for (int p = 0; p < 2; p++) {
                uint32_t adr = stg + 2 * A_SB
                             + ((b_row + p * 16) * LDS + kofs + b_koff) * 2;
                LDMX4(bh[p][0], bh[p][1], bh[p][2], bh[p][3], adr);
                LDMX4(bl[p][0], bl[p][1], bl[p][2], bl[p][3], adr + B_SB);
            }
#pragma unroll
            for (int mt = 0; mt < 4; mt++)
#pragma unroll
                for (int nt = 0; nt < 4; nt++) {
                    const int p = nt >> 1, hh = (nt & 1) * 2;
                    MMA16816(acc[mt][nt], ah[mt], bh[p][hh], bh[p][hh + 1]);
                    MMA16816(acc[mt][nt], ah[mt], bl[p][hh], bl[p][hh + 1]);
                    MMA16816(acc[mt][nt], al[mt], bh[p][hh], bh[p][hh + 1]);
                }
        }
    }

    const int erow = wm * 64 + (lane >> 2);
    const int ecol = wn * 32 + (lane & 3) * 2;
#pragma unroll
    for (int mt = 0; mt < 4; mt++) {
#pragma unroll
        for (int nt = 0; nt < 4; nt++) {
            const int cc = ecol + nt * 8;
            const float b0 = sBias[cc], b1 = sBias[cc + 1];
            float* p0 = C + (size_t)(m0 + erow + mt * 16) * N + n0 + cc;
            float* p1 = C + (size_t)(m0 + erow + mt * 16 + 8) * N + n0 + cc;
            float2 v0 = {acc[mt][nt][0] + b0, acc[mt][nt][1] + b1};
            float2 v1 = {acc[mt][nt][2] + b0, acc[mt][nt][3] + b1};
            *(float2*)p0 = v0;
            *(float2*)p1 = v1;
        }
    }
}

// ---------------------------------------------------------------------------
// RoPE + layout change + hi/lo split: g_qkv fp32 [b][s][3][h][d]
//   -> Q/K/V hi/lo bf16 [bh][s][d]; Q pre-scaled by 1/sqrt(D)
// ---------------------------------------------------------------------------
__device__ __forceinline__ void split1(float x, __nv_bfloat16* ph, __nv_bfloat16* pl) {
    __nv_bfloat16 h = __float2bfloat16(x);
    *ph = h;
    *pl = __float2bfloat16(x - __bfloat162float(h));
}

__global__ __launch_bounds__(256) void rope_split(
    const float* __restrict__ qkv,
    __nv_bfloat16* __restrict__ Qh, __nv_bfloat16* __restrict__ Ql,
    __nv_bfloat16* __restrict__ Kh, __nv_bfloat16* __restrict__ Kl,
    __nv_bfloat16* __restrict__ Vh, __nv_bfloat16* __restrict__ Vl)
{
    int idx = blockIdx.x * blockDim.x + threadIdx.x;   // NBH*SEQ*64
    if (idx >= NBH * SEQ * 64) return;
    int j  = idx & 63;
    int s  = (idx >> 6) & (SEQ - 1);
    int bh = idx >> 17;
    int b = bh >> 4, h = bh & 15;

    size_t base = ((size_t)(b * SEQ + s) * 3) * EMB + h * HDIM;
    size_t dst  = ((size_t)bh * SEQ + s) * HDIM + j;
    const float scale = 0.08838834764831845f;

    float inv = powf(10000.0f, -(float)j / 64.0f);
    float ang = (float)s * inv;
    float sn, cs;
    sincosf(ang, &sn, &cs);

    float q1 = qkv[base + j], q2 = qkv[base + 64 + j];
    split1((q1 * cs - q2 * sn) * scale, Qh + dst, Ql + dst);
    split1((q1 * sn + q2 * cs) * scale, Qh + dst + 64, Ql + dst + 64);
    float k1 = qkv[base + EMB + j], k2 = qkv[base + EMB + 64 + j];
    split1(k1 * cs - k2 * sn, Kh + dst, Kl + dst);
    split1(k1 * sn + k2 * cs, Kh + dst + 64, Kl + dst + 64);
    float v1 = qkv[base + 2 * EMB + j], v2 = qkv[base + 2 * EMB + 64 + j];
    split1(v1, Vh + dst, Vl + dst);
    split1(v2, Vh + dst + 64, Vl + dst + 64);
}

// ---------------------------------------------------------------------------
// Flash attention on mma.sync, causal, split-bf16 for QK^T and PV.
// 128 threads (4 warps x 16 q-rows), 64x64 KV tiles, D=128.
// ---------------------------------------------------------------------------
#define FL_STRIDE_B 272                  // 136 bf16 per smem row
#define FL_TILE (64 * FL_STRIDE_B)       // 17408 B
#define FLASH_SMEM (6 * FL_TILE)         // 104448 B

__global__ __launch_bounds__(128, 2) void flash_mma(
    const __nv_bfloat16* __restrict__ Qh, const __nv_bfloat16* __restrict__ Ql,
    const __nv_bfloat16* __restrict__ Kh, const __nv_bfloat16* __restrict__ Kl,
    const __nv_bfloat16* __restrict__ Vh, const __nv_bfloat16* __restrict__ Vl,
    __nv_bfloat16* __restrict__ ctxh, __nv_bfloat16* __restrict__ ctxl)
{
    extern __shared__ char fsm[];
    const int qt = gridDim.x - 1 - blockIdx.x;   // heavy tiles first
    const int bh = blockIdx.y;
    const int tid = threadIdx.x, lane = tid & 31, w = tid >> 5;
    const int q0 = qt * 64;
    const uint32_t sb = smem_u32(fsm);

    {
        const size_t qo = ((size_t)bh * SEQ + q0) * HDIM;
#pragma unroll
        for (int i = 0; i < 8; i++) {
            int c = tid + i * 128;
            int r = c >> 4, sg = c & 15;
            *(uint4*)(fsm + 0 * FL_TILE + r * FL_STRIDE_B + sg * 16) =
                *(const uint4*)(Qh + qo + r * HDIM + sg * 8);
            *(uint4*)(fsm + 1 * FL_TILE + r * FL_STRIDE_B + sg * 16) =
                *(const uint4*)(Ql + qo + r * HDIM + sg * 8);
        }
    }

    float m0v = -1e30f, m1v = -1e30f, l0v = 0.0f, l1v = 0.0f;
    float o[16][4];
#pragma unroll
    for (int nt = 0; nt < 16; nt++)
#pragma unroll
        for (int r = 0; r < 4; r++) o[nt][r] = 0.0f;

    const uint32_t a_row  = (uint32_t)(w * 16 + (lane & 15));
    const uint32_t a_koff = (uint32_t)((lane >> 4) * 8);
    const uint32_t b_row  = (uint32_t)((lane & 7) + ((lane >> 4) << 3));
    const uint32_t b_koff = (uint32_t)(((lane >> 3) & 1) * 8);
    const uint32_t v_row  = (uint32_t)(lane & 15);
    const uint32_t v_coff = (uint32_t)((lane >> 4) * 8);

    for (int kt = 0; kt <= qt; kt++) {
        __syncthreads();

        const size_t ko = ((size_t)bh * SEQ + kt * 64) * HDIM;
#pragma unroll
        for (int i = 0; i < 8; i++) {
            int c = tid + i * 128;
            int r = c >> 4, sg = c & 15;
            uint32_t dof = (uint32_t)(r * FL_STRIDE_B + sg * 16);
            size_t so = ko + r * HDIM + sg * 8;
            CP16(sb + 2 * FL_TILE + dof, (const char*)(Kh + so));
            CP16(sb + 3 * FL_TILE + dof, (const char*)(Kl + so));
        }
        CPCOMMIT();
#pragma unroll
        for (int i = 0; i < 8; i++) {
            int c = tid + i * 128;
            int r = c >> 4, sg = c & 15;
            uint32_t dof = (uint32_t)(r * FL_STRIDE_B + sg * 16);
            size_t so = ko + r * HDIM + sg * 8;
            CP16(sb + 4 * FL_TILE + dof, (const char*)(Vh + so));
            CP16(sb + 5 * FL_TILE + dof, (const char*)(Vl + so));
        }
        CPCOMMIT();

        CPWAIT1();
        __syncthreads();

        float s[8][4];
#pragma unroll
        for (int nt = 0; nt < 8; nt++)
#pragma unroll
            for (int r = 0; r < 4; r++) s[nt][r] = 0.0f;

#pragma unroll
        for (int ks = 0; ks < 8; ks++) {
            uint32_t qh[4], ql[4];
            uint32_t qadr = sb + 0 * FL_TILE + a_row * FL_STRIDE_B
                          + (ks * 16 + a_koff) * 2;
            LDMX4(qh[0], qh[1], qh[2], qh[3], qadr);
            LDMX4(ql[0], ql[1], ql[2], ql[3], qadr + FL_TILE);
#pragma unroll
            for (int np = 0; np < 4; np++) {
                uint32_t khf[4], klf[4];
                uint32_t kadr = sb + 2 * FL_TILE
                              + (np * 16 + b_row) * FL_STRIDE_B
                              + (ks * 16 + b_koff) * 2;
                LDMX4(khf[0], khf[1], khf[2], khf[3], kadr);
                LDMX4(klf[0], klf[1], klf[2], klf[3], kadr + FL_TILE);
                MMA16816(s[2*np],   qh, khf[0], khf[1]);
                MMA16816(s[2*np],   qh, klf[0], klf[1]);
                MMA16816(s[2*np],   ql, khf[0], khf[1]);
                MMA16816(s[2*np+1], qh, khf[2], khf[3]);
                MMA16816(s[2*np+1], qh, klf[2], klf[3]);
                MMA16816(s[2*np+1], ql, khf[2], khf[3]);
            }
        }

        if (kt == qt) {
            const int r0 = w * 16 + (lane >> 2);
            const int r1 = r0 + 8;
#pragma unroll
            for (int nt = 0; nt < 8; nt++) {
                const int cb = nt * 8 + (lane & 3) * 2;
                if (cb     > r0) s[nt][0] = -1e30f;
                if (cb + 1 > r0) s[nt][1] = -1e30f;
                if (cb     > r1) s[nt][2] = -1e30f;
                if (cb + 1 > r1) s[nt][3] = -1e30f;
            }
        }

        float mx0 = -1e30f, mx1 = -1e30f;
#pragma unroll
        for (int nt = 0; nt < 8; nt++) {
            mx0 = fmaxf(mx0, fmaxf(s[nt][0], s[nt][1]));
            mx1 = fmaxf(mx1, fmaxf(s[nt][2], s[nt][3]));
        }
        mx0 = fmaxf(mx0, __shfl_xor_sync(0xffffffffu, mx0, 1));
        mx0 = fmaxf(mx0, __shfl_xor_sync(0xffffffffu, mx0, 2));
        mx1 = fmaxf(mx1, __shfl_xor_sync(0xffffffffu, mx1, 1));
        mx1 = fmaxf(mx1, __shfl_xor_sync(0xffffffffu, mx1, 2));

        float mn0 = fmaxf(m0v, mx0), mn1 = fmaxf(m1v, mx1);
        float sf0 = __expf(m0v - mn0), sf1 = __expf(m1v - mn1);
        m0v = mn0; m1v = mn1;

        float ls0 = 0.0f, ls1 = 0.0f;
#pragma unroll
        for (int nt = 0; nt < 8; nt++) {
            s[nt][0] = __expf(s[nt][0] - mn0); ls0 += s[nt][0];
            s[nt][1] = __expf(s[nt][1] - mn0); ls0 += s[nt][1];
            s[nt][2] = __expf(s[nt][2] - mn1); ls1 += s[nt][2];
            s[nt][3] = __expf(s[nt][3] - mn1); ls1 += s[nt][3];
        }
        ls0 += __shfl_xor_sync(0xffffffffu, ls0, 1);
        ls0 += __shfl_xor_sync(0xffffffffu, ls0, 2);
        ls1 += __shfl_xor_sync(0xffffffffu, ls1, 1);
        ls1 += __shfl_xor_sync(0xffffffffu, ls1, 2);
        l0v = l0v * sf0 + ls0;
        l1v = l1v * sf1 + ls1;
#pragma unroll
        for (int nt = 0; nt < 16; nt++) {
            o[nt][0] *= sf0; o[nt][1] *= sf0;
            o[nt][2] *= sf1; o[nt][3] *= sf1;
        }

        uint32_t ph[4][4], pl[4][4];
#pragma unroll
        for (int k2 = 0; k2 < 4; k2++) {
            cvt_pair(s[2*k2][0],   s[2*k2][1],   ph[k2][0], pl[k2][0]);
            cvt_pair(s[2*k2][2],   s[2*k2][3],   ph[k2][1], pl[k2][1]);
            cvt_pair(s[2*k2+1][0], s[2*k2+1][1], ph[k2][2], pl[k2][2]);
            cvt_pair(s[2*k2+1][2], s[2*k2+1][3], ph[k2][3], pl[k2][3]);
        }

        CPWAIT0();
        __syncthreads();

#pragma unroll
        for (int k2 = 0; k2 < 4; k2++) {
#pragma unroll
            for (int np = 0; np < 8; np++) {
                uint32_t vhf[4], vlf[4];
                uint32_t vadr = sb + 4 * FL_TILE
                              + (k2 * 16 + v_row) * FL_STRIDE_B
                              + (np * 16 + v_coff) * 2;
                LDMT4(vhf[0], vhf[1], vhf[2], vhf[3], vadr);
                LDMT4(vlf[0], vlf[1], vlf[2], vlf[3], vadr + FL_TILE);
                MMA16816(o[2*np],   ph[k2], vhf[0], vhf[1]);
                MMA16816(o[2*np],   ph[k2], vlf[0], vlf[1]);
                MMA16816(o[2*np],   pl[k2], vhf[0], vhf[1]);
                MMA16816(o[2*np+1], ph[k2], vhf[2], vhf[3]);
                MMA16816(o[2*np+1], ph[k2], vlf[2], vlf[3]);
                MMA16816(o[2*np+1], pl[k2], vhf[2], vhf[3]);
            }
        }
    }

    const float inv0 = 1.0f / l0v, inv1 = 1.0f / l1v;
    const int b = bh >> 4, h = bh & 15;
    const int gr0 = q0 + w * 16 + (lane >> 2);
    const size_t ro0 = (size_t)(b * SEQ + gr0) * EMB + h * HDIM;
    const size_t ro1 = (size_t)(b * SEQ + gr0 + 8) * EMB + h * HDIM;
#pragma unroll
    for (int nt = 0; nt < 16; nt++) {
        const int col = nt * 8 + (lane & 3) * 2;
        uint32_t hh, ll;
        cvt_pair(o[nt][0] * inv0, o[nt][1] * inv0, hh, ll);
        *(uint32_t*)(ctxh + ro0 + col) = hh;
        *(uint32_t*)(ctxl + ro0 + col) = ll;
        cvt_pair(o[nt][2] * inv1, o[nt][3] * inv1, hh, ll);
        *(uint32_t*)(ctxh + ro1 + col) = hh;
        *(uint32_t*)(ctxl + ro1 + col) = ll;
    }
}

// ---------------------------------------------------------------------------
extern "C" void kernel_launch(void* const* d_in, const int* in_sizes, int n_in,
                              void* d_out, int out_size)
{
    const float* x      = (const float*)d_in[0];
    const float* wqkv_w = (const float*)d_in[1];
    const float* wqkv_b = (const float*)d_in[2];
    const float* out_w  = (const float*)d_in[3];
    const float* out_b  = (const float*)d_in[4];
    float* out = (float*)d_out;

    float* qkv;
    __nv_bfloat16 *xh, *xl, *wh, *wl, *oh, *ol;
    __nv_bfloat16 *qh, *ql, *kh, *kl, *vh, *vl, *ch, *cl;
    cudaGetSymbolAddress((void**)&qkv, g_qkv);
    cudaGetSymbolAddress((void**)&xh, g_xh);  cudaGetSymbolAddress((void**)&xl, g_xl);
    cudaGetSymbolAddress((void**)&wh, g_wh);  cudaGetSymbolAddress((void**)&wl, g_wl);
    cudaGetSymbolAddress((void**)&oh, g_oh);  cudaGetSymbolAddress((void**)&ol, g_ol);
    cudaGetSymbolAddress((void**)&qh, g_qhh); cudaGetSymbolAddress((void**)&ql, g_qll);
    cudaGetSymbolAddress((void**)&kh, g_khh); cudaGetSymbolAddress((void**)&kl, g_kll);
    cudaGetSymbolAddress((void**)&vh, g_vhh); cudaGetSymbolAddress((void**)&vl, g_vll);
    cudaGetSymbolAddress((void**)&ch, g_ch);  cudaGetSymbolAddress((void**)&cl, g_cl);

    cudaFuncSetAttribute(gemm_bf16, cudaFuncAttributeMaxDynamicSharedMemorySize, GEMM_SMEM);
    cudaFuncSetAttribute(flash_mma, cudaFuncAttributeMaxDynamicSharedMemorySize, FLASH_SMEM);

    int n4;
    n4 = MROWS * EMB / 4;
    split_f32<<<(n4 + 255) / 256, 256>>>((const float4*)x, (uint2*)xh, (uint2*)xl, n4);
    n4 = THREE_E * EMB / 4;
    split_f32<<<(n4 + 255) / 256, 256>>>((const float4*)wqkv_w, (uint2*)wh, (uint2*)wl, n4);
    n4 = EMB * EMB / 4;
    split_f32<<<(n4 + 255) / 256, 256>>>((const float4*)out_w, (uint2*)oh, (uint2*)ol, n4);

    // QKV projection: tiles 128 (M) x 256 (N)
    dim3 g1(THREE_E / 256, MROWS / 128);
    gemm_bf16<<<g1, 512, GEMM_SMEM>>>(xh, xl, wh, wl, wqkv_b, qkv, THREE_E, EMB);

    int nr = NBH * SEQ * 64;
    rope_split<<<(nr + 255) / 256, 256>>>(qkv, qh, ql, kh, kl, vh, vl);

    dim3 g2(SEQ / 64, NBH);
    flash_mma<<<g2, 128, FLASH_SMEM>>>(qh, ql, kh, kl, vh, vl, ch, cl);

    dim3 g3(EMB / 256, MROWS / 128);
    gemm_bf16<<<g3, 512, GEMM_SMEM>>>(ch, cl, oh, ol, out_b, out, EMB, EMB);
}

// round 6
// speedup vs baseline: 3.4109x; 1.0006x over previous
#include <cuda_runtime.h>
#include <cuda_bf16.h>
#include <math.h>
#include <stdint.h>

#define BATCH 2
#define SEQ   2048
#define EMB   2048
#define HEADS 16
#define HDIM  128
#define THREE_E 6144
#define MROWS (BATCH*SEQ)     // 4096
#define NBH   (BATCH*HEADS)   // 32

// ---------------- scratch (__device__ globals; no cudaMalloc) ----------------
__device__ float g_qkv[(size_t)MROWS * THREE_E];                 // fp32 QKV
__device__ __nv_bfloat16 g_xh[(size_t)MROWS * EMB],   g_xl[(size_t)MROWS * EMB];
__device__ __nv_bfloat16 g_wh[(size_t)THREE_E * EMB], g_wl[(size_t)THREE_E * EMB];
__device__ __nv_bfloat16 g_oh[(size_t)EMB * EMB],     g_ol[(size_t)EMB * EMB];
__device__ __nv_bfloat16 g_qhh[(size_t)NBH*SEQ*HDIM], g_qll[(size_t)NBH*SEQ*HDIM];
__device__ __nv_bfloat16 g_khh[(size_t)NBH*SEQ*HDIM], g_kll[(size_t)NBH*SEQ*HDIM];
__device__ __nv_bfloat16 g_vhh[(size_t)NBH*SEQ*HDIM], g_vll[(size_t)NBH*SEQ*HDIM];
__device__ __nv_bfloat16 g_ch[(size_t)MROWS * EMB],   g_cl[(size_t)MROWS * EMB];

// ---------------- PTX helpers ----------------
__device__ __forceinline__ uint32_t smem_u32(const void* p) {
    uint32_t a;
    asm("{ .reg .u64 t; cvta.to.shared.u64 t, %1; cvt.u32.u64 %0, t; }"
        : "=r"(a) : "l"(p));
    return a;
}
// fp32 pair -> hi bf16x2 + residual-lo bf16x2 (f0 in low half)
__device__ __forceinline__ void cvt_pair(float f0, float f1,
                                         uint32_t& h, uint32_t& l) {
    asm("cvt.rn.bf16x2.f32 %0, %1, %2;" : "=r"(h) : "f"(f1), "f"(f0));
    float h0 = __uint_as_float(h << 16);
    float h1 = __uint_as_float(h & 0xffff0000u);
    asm("cvt.rn.bf16x2.f32 %0, %1, %2;" : "=r"(l) : "f"(f1 - h1), "f"(f0 - h0));
}
#define LDMX4(r0, r1, r2, r3, addr) \
    asm volatile("ldmatrix.sync.aligned.m8n8.x4.shared.b16 {%0,%1,%2,%3}, [%4];" \
        : "=r"(r0), "=r"(r1), "=r"(r2), "=r"(r3) : "r"(addr))
#define LDMT4(r0, r1, r2, r3, addr) \
    asm volatile("ldmatrix.sync.aligned.m8n8.x4.trans.shared.b16 {%0,%1,%2,%3}, [%4];" \
        : "=r"(r0), "=r"(r1), "=r"(r2), "=r"(r3) : "r"(addr))
#define MMA16816(d, a, b0, b1) \
    asm volatile("mma.sync.aligned.m16n8k16.row.col.f32.bf16.bf16.f32 " \
        "{%0,%1,%2,%3}, {%4,%5,%6,%7}, {%8,%9}, {%0,%1,%2,%3};" \
        : "+f"((d)[0]), "+f"((d)[1]), "+f"((d)[2]), "+f"((d)[3]) \
        : "r"((a)[0]), "r"((a)[1]), "r"((a)[2]), "r"((a)[3]), "r"(b0), "r"(b1))
#define CP16(dst, src) \
    asm volatile("cp.async.cg.shared.global [%0], [%1], 16;" :: "r"(dst), "l"(src))
#define CPCOMMIT() asm volatile("cp.async.commit_group;" ::: "memory")
#define CPWAIT0()  asm volatile("cp.async.wait_group 0;" ::: "memory")
#define CPWAIT1()  asm volatile("cp.async.wait_group 1;" ::: "memory")

// ---------------------------------------------------------------------------
// Prep: fp32 -> (hi, lo) bf16 split, vectorized by 4
// ---------------------------------------------------------------------------
__global__ void split_f32(const float4* __restrict__ in,
                          uint2* __restrict__ hi, uint2* __restrict__ lo, int n4)
{
    int i = blockIdx.x * blockDim.x + threadIdx.x;
    if (i >= n4) return;
    float4 v = in[i];
    uint32_t h01, l01, h23, l23;
    cvt_pair(v.x, v.y, h01, l01);
    cvt_pair(v.z, v.w, h23, l23);
    hi[i] = make_uint2(h01, h23);
    lo[i] = make_uint2(l01, l23);
}

// ---------------------------------------------------------------------------
// Split-bf16 tensor GEMM: C[M,N] = A[M,K] @ B[N,K]^T + bias
// BM=128, BN=256, BK=32, 512 threads = 16 warps (2m x 8n), warp tile 64x32.
// 3-stage cp.async pipeline. Product-major MMA ordering (RAW distance 16).
// ---------------------------------------------------------------------------
#define LDS 40
#define A_SB (128 * LDS * 2)        // 10240 B per A bf16 tile
#define B_SB (256 * LDS * 2)        // 20480 B per B bf16 tile
#define STAGE_SB (2 * A_SB + 2 * B_SB)   // 61440 B
#define GEMM_SMEM (3 * STAGE_SB)         // 184320 B

__device__ __forceinline__ void gemm_issue(
    const __nv_bfloat16* Ah, const __nv_bfloat16* Al,
    const __nv_bfloat16* Bh, const __nv_bfloat16* Bl,
    uint32_t sbase, int m0, int n0, int K, int cc, int tid)
{
    const uint32_t stg = sbase + (uint32_t)(cc % 3) * STAGE_SB;
    const int k0 = cc * 32;
    {
        int r = tid >> 2, sg = tid & 3;
        uint32_t dof = (uint32_t)(r * 80 + sg * 16);
        size_t ao = (size_t)(m0 + r) * K + k0 + sg * 8;
        CP16(stg + dof, (const char*)(Ah + ao));
        CP16(stg + A_SB + dof, (const char*)(Al + ao));
    }
#pragma unroll
    for (int i = 0; i < 2; i++) {
        int c = tid + i * 512;
        int r = c >> 2, sg = c & 3;
        uint32_t dof = (uint32_t)(r * 80 + sg * 16);
        size_t bo = (size_t)(n0 + r) * K + k0 + sg * 8;
        CP16(stg + 2 * A_SB + dof, (const char*)(Bh + bo));
        CP16(stg + 2 * A_SB + B_SB + dof, (const char*)(Bl + bo));
    }
    CPCOMMIT();
}

__global__ __launch_bounds__(512, 1) void gemm_bf16(
    const __nv_bfloat16* __restrict__ Ah, const __nv_bfloat16* __restrict__ Al,
    const __nv_bfloat16* __restrict__ Bh, const __nv_bfloat16* __restrict__ Bl,
    const float* __restrict__ bias, float* __restrict__ C, int N, int K)
{
    extern __shared__ char dsm[];
    __shared__ float sBias[256];

    const int tid  = threadIdx.x;
    const int lane = tid & 31;
    const int wid  = tid >> 5;
    const int wm   = wid >> 3;        // 0..1
    const int wn   = wid & 7;         // 0..7
    const int m0 = blockIdx.y * 128, n0 = blockIdx.x * 256;
    const uint32_t sbase = smem_u32(dsm);

    if (tid < 256) sBias[tid] = bias[n0 + tid];

    const int NCH = K >> 5;
    gemm_issue(Ah, Al, Bh, Bl, sbase, m0, n0, K, 0, tid);
    gemm_issue(Ah, Al, Bh, Bl, sbase, m0, n0, K, 1, tid);

    float acc[4][4][4];
#pragma unroll
    for (int mt = 0; mt < 4; mt++)
#pragma unroll
        for (int nt = 0; nt < 4; nt++)
#pragma unroll
            for (int r = 0; r < 4; r++) acc[mt][nt][r] = 0.0f;

    const uint32_t a_row  = (uint32_t)(wm * 64 + (lane & 15));
    const uint32_t a_koff = (uint32_t)((lane >> 4) * 8);
    const uint32_t b_row  = (uint32_t)(wn * 32 + (lane & 7) + ((lane >> 4) << 3));
    const uint32_t b_koff = (uint32_t)(((lane >> 3) & 1) * 8);

    for (int c = 0; c < NCH; c++) {
        CPWAIT1();            // group c complete (2 groups always pending)
        __syncthreads();
        if (c + 2 < NCH) gemm_issue(Ah, Al, Bh, Bl, sbase, m0, n0, K, c + 2, tid);
        else CPCOMMIT();      // keep group count uniform

        const uint32_t stg = sbase + (uint32_t)(c % 3) * STAGE_SB;
#pragma unroll
        for (int ks = 0; ks < 2; ks++) {
            const uint32_t kofs = (uint32_t)(ks * 16);
            uint32_t ah[4][4], al[4][4];
#pragma unroll
            for (int mt = 0; mt < 4; mt++) {
                uint32_t adr = stg + ((a_row + mt * 16) * LDS + kofs + a_koff) * 2;
                LDMX4(ah[mt][0], ah[mt][1], ah[mt][2], ah[mt][3], adr);
                LDMX4(al[mt][0], al[mt][1], al[mt][2], al[mt][3], adr + A_SB);
            }
            uint32_t bh[2][4], bl[2][4];
#pragma unroll
            for (int p = 0; p < 2; p++) {
                uint32_t adr = stg + 2 * A_SB
                             + ((b_row + p * 16) * LDS + kofs + b_koff) * 2;
                LDMX4(bh[p][0], bh[p][1], bh[p][2], bh[p][3], adr);
                LDMX4(bl[p][0], bl[p][1], bl[p][2], bl[p][3], adr + B_SB);
            }
            // Product-major: 16 independent accumulators between same-acc reuse
#pragma unroll
            for (int mt = 0; mt < 4; mt++)
#pragma unroll
                for (int nt = 0; nt < 4; nt++) {
                    const int p = nt >> 1, hh = (nt & 1) * 2;
                    MMA16816(acc[mt][nt], ah[mt], bh[p][hh], bh[p][hh + 1]);
                }
#pragma unroll
            for (int mt = 0; mt < 4; mt++)
#pragma unroll
                for (int nt = 0; nt < 4; nt++) {
                    const int p = nt >> 1, hh = (nt & 1) * 2;
                    MMA16816(acc[mt][nt], ah[mt], bl[p][hh], bl[p][hh + 1]);
                }
#pragma unroll
            for (int mt = 0; mt < 4; mt++)
#pragma unroll
                for (int nt = 0; nt < 4; nt++) {
                    const int p = nt >> 1, hh = (nt & 1) * 2;
                    MMA16816(acc[mt][nt], al[mt], bh[p][hh], bh[p][hh + 1]);
                }
        }
    }

    const int erow = wm * 64 + (lane >> 2);
    const int ecol = wn * 32 + (lane & 3) * 2;
#pragma unroll
    for (int mt = 0; mt < 4; mt++) {
#pragma unroll
        for (int nt = 0; nt < 4; nt++) {
            const int cc = ecol + nt * 8;
            const float b0 = sBias[cc], b1 = sBias[cc + 1];
            float* p0 = C + (size_t)(m0 + erow + mt * 16) * N + n0 + cc;
            float* p1 = C + (size_t)(m0 + erow + mt * 16 + 8) * N + n0 + cc;
            float2 v0 = {acc[mt][nt][0] + b0, acc[mt][nt][1] + b1};
            float2 v1 = {acc[mt][nt][2] + b0, acc[mt][nt][3] + b1};
            *(float2*)p0 = v0;
            *(float2*)p1 = v1;
        }
    }
}

// ---------------------------------------------------------------------------
// RoPE + layout change + hi/lo split
// ---------------------------------------------------------------------------
__device__ __forceinline__ void split1(float x, __nv_bfloat16* ph, __nv_bfloat16* pl) {
    __nv_bfloat16 h = __float2bfloat16(x);
    *ph = h;
    *pl = __float2bfloat16(x - __bfloat162float(h));
}

__global__ __launch_bounds__(256) void rope_split(
    const float* __restrict__ qkv,
    __nv_bfloat16* __restrict__ Qh, __nv_bfloat16* __restrict__ Ql,
    __nv_bfloat16* __restrict__ Kh, __nv_bfloat16* __restrict__ Kl,
    __nv_bfloat16* __restrict__ Vh, __nv_bfloat16* __restrict__ Vl)
{
    int idx = blockIdx.x * blockDim.x + threadIdx.x;   // NBH*SEQ*64
    if (idx >= NBH * SEQ * 64) return;
    int j  = idx & 63;
    int s  = (idx >> 6) & (SEQ - 1);
    int bh = idx >> 17;
    int b = bh >> 4, h = bh & 15;

    size_t base = ((size_t)(b * SEQ + s) * 3) * EMB + h * HDIM;
    size_t dst  = ((size_t)bh * SEQ + s) * HDIM + j;
    const float scale = 0.08838834764831845f;

    float inv = powf(10000.0f, -(float)j / 64.0f);
    float ang = (float)s * inv;
    float sn, cs;
    sincosf(ang, &sn, &cs);

    float q1 = qkv[base + j], q2 = qkv[base + 64 + j];
    split1((q1 * cs - q2 * sn) * scale, Qh + dst, Ql + dst);
    split1((q1 * sn + q2 * cs) * scale, Qh + dst + 64, Ql + dst + 64);
    float k1 = qkv[base + EMB + j], k2 = qkv[base + EMB + 64 + j];
    split1(k1 * cs - k2 * sn, Kh + dst, Kl + dst);
    split1(k1 * sn + k2 * cs, Kh + dst + 64, Kl + dst + 64);
    float v1 = qkv[base + 2 * EMB + j], v2 = qkv[base + 2 * EMB + 64 + j];
    split1(v1, Vh + dst, Vl + dst);
    split1(v2, Vh + dst + 64, Vl + dst + 64);
}

// ---------------------------------------------------------------------------
// Flash attention on mma.sync, causal, split-bf16, product-major MMA order.
// 128 threads (4 warps x 16 q-rows), 64x64 KV tiles, D=128.
// ---------------------------------------------------------------------------
#define FL_STRIDE_B 272                  // 136 bf16 per smem row
#define FL_TILE (64 * FL_STRIDE_B)       // 17408 B
#define FLASH_SMEM (6 * FL_TILE)         // 104448 B

__global__ __launch_bounds__(128, 2) void flash_mma(
    const __nv_bfloat16* __restrict__ Qh, const __nv_bfloat16* __restrict__ Ql,
    const __nv_bfloat16* __restrict__ Kh, const __nv_bfloat16* __restrict__ Kl,
    const __nv_bfloat16* __restrict__ Vh, const __nv_bfloat16* __restrict__ Vl,
    __nv_bfloat16* __restrict__ ctxh, __nv_bfloat16* __restrict__ ctxl)
{
    extern __shared__ char fsm[];
    const int qt = gridDim.x - 1 - blockIdx.x;   // heavy tiles first
    const int bh = blockIdx.y;
    const int tid = threadIdx.x, lane = tid & 31, w = tid >> 5;
    const int q0 = qt * 64;
    const uint32_t sb = smem_u32(fsm);

    {
        const size_t qo = ((size_t)bh * SEQ + q0) * HDIM;
#pragma unroll
        for (int i = 0; i < 8; i++) {
            int c = tid + i * 128;
            int r = c >> 4, sg = c & 15;
            *(uint4*)(fsm + 0 * FL_TILE + r * FL_STRIDE_B + sg * 16) =
                *(const uint4*)(Qh + qo + r * HDIM + sg * 8);
            *(uint4*)(fsm + 1 * FL_TILE + r * FL_STRIDE_B + sg * 16) =
                *(const uint4*)(Ql + qo + r * HDIM + sg * 8);
        }
    }

    float m0v = -1e30f, m1v = -1e30f, l0v = 0.0f, l1v = 0.0f;
    float o[16][4];
#pragma unroll
    for (int nt = 0; nt < 16; nt++)
#pragma unroll
        for (int r = 0; r < 4; r++) o[nt][r] = 0.0f;

    const uint32_t a_row  = (uint32_t)(w * 16 + (lane & 15));
    const uint32_t a_koff = (uint32_t)((lane >> 4) * 8);
    const uint32_t b_row  = (uint32_t)((lane & 7) + ((lane >> 4) << 3));
    const uint32_t b_koff = (uint32_t)(((lane >> 3) & 1) * 8);
    const uint32_t v_row  = (uint32_t)(lane & 15);
    const uint32_t v_coff = (uint32_t)((lane >> 4) * 8);

    for (int kt = 0; kt <= qt; kt++) {
        __syncthreads();

        const size_t ko = ((size_t)bh * SEQ + kt * 64) * HDIM;
#pragma unroll
        for (int i = 0; i < 8; i++) {
            int c = tid + i * 128;
            int r = c >> 4, sg = c & 15;
            uint32_t dof = (uint32_t)(r * FL_STRIDE_B + sg * 16);
            size_t so = ko + r * HDIM + sg * 8;
            CP16(sb + 2 * FL_TILE + dof, (const char*)(Kh + so));
            CP16(sb + 3 * FL_TILE + dof, (const char*)(Kl + so));
        }
        CPCOMMIT();
#pragma unroll
        for (int i = 0; i < 8; i++) {
            int c = tid + i * 128;
            int r = c >> 4, sg = c & 15;
            uint32_t dof = (uint32_t)(r * FL_STRIDE_B + sg * 16);
            size_t so = ko + r * HDIM + sg * 8;
            CP16(sb + 4 * FL_TILE + dof, (const char*)(Vh + so));
            CP16(sb + 5 * FL_TILE + dof, (const char*)(Vl + so));
        }
        CPCOMMIT();

        CPWAIT1();
        __syncthreads();

        float s[8][4];
#pragma unroll
        for (int nt = 0; nt < 8; nt++)
#pragma unroll
            for (int r = 0; r < 4; r++) s[nt][r] = 0.0f;

#pragma unroll
        for (int ks = 0; ks < 8; ks++) {
            uint32_t qh[4], ql[4];
            uint32_t qadr = sb + 0 * FL_TILE + a_row * FL_STRIDE_B
                          + (ks * 16 + a_koff) * 2;
            LDMX4(qh[0], qh[1], qh[2], qh[3], qadr);
            LDMX4(ql[0], ql[1], ql[2], ql[3], qadr + FL_TILE);
            uint32_t khf[4][4], klf[4][4];
#pragma unroll
            for (int np = 0; np < 4; np++) {
                uint32_t kadr = sb + 2 * FL_TILE
                              + (np * 16 + b_row) * FL_STRIDE_B
                              + (ks * 16 + b_koff) * 2;
                LDMX4(khf[np][0], khf[np][1], khf[np][2], khf[np][3], kadr);
                LDMX4(klf[np][0], klf[np][1], klf[np][2], klf[np][3], kadr + FL_TILE);
            }
            // Product-major: 8 independent accumulators between same-acc reuse
#pragma unroll
            for (int np = 0; np < 4; np++) {
                MMA16816(s[2*np],   qh, khf[np][0], khf[np][1]);
                MMA16816(s[2*np+1], qh, khf[np][2], khf[np][3]);
            }
#pragma unroll
            for (int np = 0; np < 4; np++) {
                MMA16816(s[2*np],   qh, klf[np][0], klf[np][1]);
                MMA16816(s[2*np+1], qh, klf[np][2], klf[np][3]);
            }
#pragma unroll
            for (int np = 0; np < 4; np++) {
                MMA16816(s[2*np],   ql, khf[np][0], khf[np][1]);
                MMA16816(s[2*np+1], ql, khf[np][2], khf[np][3]);
            }
        }

        if (kt == qt) {
            const int r0 = w * 16 + (lane >> 2);
            const int r1 = r0 + 8;
#pragma unroll
            for (int nt = 0; nt < 8; nt++) {
                const int cb = nt * 8 + (lane & 3) * 2;
                if (cb     > r0) s[nt][0] = -1e30f;
                if (cb + 1 > r0) s[nt][1] = -1e30f;
                if (cb     > r1) s[nt][2] = -1e30f;
                if (cb + 1 > r1) s[nt][3] = -1e30f;
            }
        }

        float mx0 = -1e30f, mx1 = -1e30f;
#pragma unroll
        for (int nt = 0; nt < 8; nt++) {
            mx0 = fmaxf(mx0, fmaxf(s[nt][0], s[nt][1]));
            mx1 = fmaxf(mx1, fmaxf(s[nt][2], s[nt][3]));
        }
        mx0 = fmaxf(mx0, __shfl_xor_sync(0xffffffffu, mx0, 1));
        mx0 = fmaxf(mx0, __shfl_xor_sync(0xffffffffu, mx0, 2));
        mx1 = fmaxf(mx1, __shfl_xor_sync(0xffffffffu, mx1, 1));
        mx1 = fmaxf(mx1, __shfl_xor_sync(0xffffffffu, mx1, 2));

        float mn0 = fmaxf(m0v, mx0), mn1 = fmaxf(m1v, mx1);
        float sf0 = __expf(m0v - mn0), sf1 = __expf(m1v - mn1);
        m0v = mn0; m1v = mn1;

        float ls0 = 0.0f, ls1 = 0.0f;
#pragma unroll
        for (int nt = 0; nt < 8; nt++) {
            s[nt][0] = __expf(s[nt][0] - mn0); ls0 += s[nt][0];
            s[nt][1] = __expf(s[nt][1] - mn0); ls0 += s[nt][1];
            s[nt][2] = __expf(s[nt][2] - mn1); ls1 += s[nt][2];
            s[nt][3] = __expf(s[nt][3] - mn1); ls1 += s[nt][3];
        }
        ls0 += __shfl_xor_sync(0xffffffffu, ls0, 1);
        ls0 += __shfl_xor_sync(0xffffffffu, ls0, 2);
        ls1 += __shfl_xor_sync(0xffffffffu, ls1, 1);
        ls1 += __shfl_xor_sync(0xffffffffu, ls1, 2);
        l0v = l0v * sf0 + ls0;
        l1v = l1v * sf1 + ls1;
#pragma unroll
        for (int nt = 0; nt < 16; nt++) {
            o[nt][0] *= sf0; o[nt][1] *= sf0;
            o[nt][2] *= sf1; o[nt][3] *= sf1;
        }

        uint32_t ph[4][4], pl[4][4];
#pragma unroll
        for (int k2 = 0; k2 < 4; k2++) {
            cvt_pair(s[2*k2][0],   s[2*k2][1],   ph[k2][0], pl[k2][0]);
            cvt_pair(s[2*k2][2],   s[2*k2][3],   ph[k2][1], pl[k2][1]);
            cvt_pair(s[2*k2+1][0], s[2*k2+1][1], ph[k2][2], pl[k2][2]);
            cvt_pair(s[2*k2+1][2], s[2*k2+1][3], ph[k2][3], pl[k2][3]);
        }

        CPWAIT0();
        __syncthreads();

        // PV: np in pairs, product-major inside pair (4 accs between reuse)
#pragma unroll
        for (int k2 = 0; k2 < 4; k2++) {
#pragma unroll
            for (int npp = 0; npp < 4; npp++) {
                const int np0 = 2 * npp, np1 = 2 * npp + 1;
                uint32_t vh0[4], vl0[4], vh1[4], vl1[4];
                uint32_t va0 = sb + 4 * FL_TILE
                             + (k2 * 16 + v_row) * FL_STRIDE_B
                             + (np0 * 16 + v_coff) * 2;
                uint32_t va1 = va0 + 32;   // np1 = np0+1 -> +16 cols = +32 B
                LDMT4(vh0[0], vh0[1], vh0[2], vh0[3], va0);
                LDMT4(vl0[0], vl0[1], vl0[2], vl0[3], va0 + FL_TILE);
                LDMT4(vh1[0], vh1[1], vh1[2], vh1[3], va1);
                LDMT4(vl1[0], vl1[1], vl1[2], vl1[3], va1 + FL_TILE);
                MMA16816(o[2*np0],   ph[k2], vh0[0], vh0[1]);
                MMA16816(o[2*np0+1], ph[k2], vh0[2], vh0[3]);
                MMA16816(o[2*np1],   ph[k2], vh1[0], vh1[1]);
                MMA16816(o[2*np1+1], ph[k2], vh1[2], vh1[3]);
                MMA16816(o[2*np0],   ph[k2], vl0[0], vl0[1]);
                MMA16816(o[2*np0+1], ph[k2], vl0[2], vl0[3]);
                MMA16816(o[2*np1],   ph[k2], vl1[0], vl1[1]);
                MMA16816(o[2*np1+1], ph[k2], vl1[2], vl1[3]);
                MMA16816(o[2*np0],   pl[k2], vh0[0], vh0[1]);
                MMA16816(o[2*np0+1], pl[k2], vh0[2], vh0[3]);
                MMA16816(o[2*np1],   pl[k2], vh1[0], vh1[1]);
                MMA16816(o[2*np1+1], pl[k2], vh1[2], vh1[3]);
            }
        }
    }

    const float inv0 = 1.0f / l0v, inv1 = 1.0f / l1v;
    const int b = bh >> 4, h = bh & 15;
    const int gr0 = q0 + w * 16 + (lane >> 2);
    const size_t ro0 = (size_t)(b * SEQ + gr0) * EMB + h * HDIM;
    const size_t ro1 = (size_t)(b * SEQ + gr0 + 8) * EMB + h * HDIM;
#pragma unroll
    for (int nt = 0; nt < 16; nt++) {
        const int col = nt * 8 + (lane & 3) * 2;
        uint32_t hh, ll;
        cvt_pair(o[nt][0] * inv0, o[nt][1] * inv0, hh, ll);
        *(uint32_t*)(ctxh + ro0 + col) = hh;
        *(uint32_t*)(ctxl + ro0 + col) = ll;
        cvt_pair(o[nt][2] * inv1, o[nt][3] * inv1, hh, ll);
        *(uint32_t*)(ctxh + ro1 + col) = hh;
        *(uint32_t*)(ctxl + ro1 + col) = ll;
    }
}

// ---------------------------------------------------------------------------
extern "C" void kernel_launch(void* const* d_in, const int* in_sizes, int n_in,
                              void* d_out, int out_size)
{
    const float* x      = (const float*)d_in[0];
    const float* wqkv_w = (const float*)d_in[1];
    const float* wqkv_b = (const float*)d_in[2];
    const float* out_w  = (const float*)d_in[3];
    const float* out_b  = (const float*)d_in[4];
    float* out = (float*)d_out;

    float* qkv;
    __nv_bfloat16 *xh, *xl, *wh, *wl, *oh, *ol;
    __nv_bfloat16 *qh, *ql, *kh, *kl, *vh, *vl, *ch, *cl;
    cudaGetSymbolAddress((void**)&qkv, g_qkv);
    cudaGetSymbolAddress((void**)&xh, g_xh);  cudaGetSymbolAddress((void**)&xl, g_xl);
    cudaGetSymbolAddress((void**)&wh, g_wh);  cudaGetSymbolAddress((void**)&wl, g_wl);
    cudaGetSymbolAddress((void**)&oh, g_oh);  cudaGetSymbolAddress((void**)&ol, g_ol);
    cudaGetSymbolAddress((void**)&qh, g_qhh); cudaGetSymbolAddress((void**)&ql, g_qll);
    cudaGetSymbolAddress((void**)&kh, g_khh); cudaGetSymbolAddress((void**)&kl, g_kll);
    cudaGetSymbolAddress((void**)&vh, g_vhh); cudaGetSymbolAddress((void**)&vl, g_vll);
    cudaGetSymbolAddress((void**)&ch, g_ch);  cudaGetSymbolAddress((void**)&cl, g_cl);

    cudaFuncSetAttribute(gemm_bf16, cudaFuncAttributeMaxDynamicSharedMemorySize, GEMM_SMEM);
    cudaFuncSetAttribute(flash_mma, cudaFuncAttributeMaxDynamicSharedMemorySize, FLASH_SMEM);

    int n4;
    n4 = MROWS * EMB / 4;
    split_f32<<<(n4 + 255) / 256, 256>>>((const float4*)x, (uint2*)xh, (uint2*)xl, n4);
    n4 = THREE_E * EMB / 4;
    split_f32<<<(n4 + 255) / 256, 256>>>((const float4*)wqkv_w, (uint2*)wh, (uint2*)wl, n4);
    n4 = EMB * EMB / 4;
    split_f32<<<(n4 + 255) / 256, 256>>>((const float4*)out_w, (uint2*)oh, (uint2*)ol, n4);

    dim3 g1(THREE_E / 256, MROWS / 128);
    gemm_bf16<<<g1, 512, GEMM_SMEM>>>(xh, xl, wh, wl, wqkv_b, qkv, THREE_E, EMB);

    int nr = NBH * SEQ * 64;
    rope_split<<<(nr + 255) / 256, 256>>>(qkv, qh, ql, kh, kl, vh, vl);

    dim3 g2(SEQ / 64, NBH);
    flash_mma<<<g2, 128, FLASH_SMEM>>>(qh, ql, kh, kl, vh, vl, ch, cl);

    dim3 g3(EMB / 256, MROWS / 128);
    gemm_bf16<<<g3, 512, GEMM_SMEM>>>(ch, cl, oh, ol, out_b, out, EMB, EMB);
}

// round 7
// speedup vs baseline: 4.2274x; 1.2394x over previous
#include <cuda_runtime.h>
#include <cuda_fp16.h>
#include <math.h>
#include <stdint.h>

#define BATCH 2
#define SEQ   2048
#define EMB   2048
#define HEADS 16
#define HDIM  128
#define THREE_E 6144
#define MROWS (BATCH*SEQ)     // 4096
#define NBH   (BATCH*HEADS)   // 32

// ---------------- scratch (__device__ globals; no cudaMalloc) ----------------
__device__ float g_qkv[(size_t)MROWS * THREE_E];                 // fp32 QKV
__device__ __half g_x16[(size_t)MROWS * EMB];                    // x plain fp16
__device__ __half g_wh[(size_t)THREE_E * EMB], g_wl[(size_t)THREE_E * EMB];
__device__ __half g_oh[(size_t)EMB * EMB],     g_ol[(size_t)EMB * EMB];
__device__ __half g_qhh[(size_t)NBH*SEQ*HDIM], g_qll[(size_t)NBH*SEQ*HDIM];
__device__ __half g_khh[(size_t)NBH*SEQ*HDIM], g_kll[(size_t)NBH*SEQ*HDIM];
__device__ __half g_vhh[(size_t)NBH*SEQ*HDIM], g_vll[(size_t)NBH*SEQ*HDIM];
__device__ __half g_c16[(size_t)MROWS * EMB];                    // ctx plain fp16

// ---------------- PTX helpers ----------------
__device__ __forceinline__ uint32_t smem_u32(const void* p) {
    uint32_t a;
    asm("{ .reg .u64 t; cvta.to.shared.u64 t, %1; cvt.u32.u64 %0, t; }"
        : "=r"(a) : "l"(p));
    return a;
}
// fp32 pair -> hi fp16x2 + residual-lo fp16x2 (f0 in low half)
__device__ __forceinline__ void cvt_pair_h(float f0, float f1,
                                           uint32_t& h, uint32_t& l) {
    asm("cvt.rn.f16x2.f32 %0, %1, %2;" : "=r"(h) : "f"(f1), "f"(f0));
    __half2 hh = *reinterpret_cast<__half2*>(&h);
    float2 hf = __half22float2(hh);
    __half2 lh = __floats2half2_rn(f0 - hf.x, f1 - hf.y);
    l = *reinterpret_cast<uint32_t*>(&lh);
}
__device__ __forceinline__ uint32_t cvt_plain_h(float f0, float f1) {
    uint32_t h;
    asm("cvt.rn.f16x2.f32 %0, %1, %2;" : "=r"(h) : "f"(f1), "f"(f0));
    return h;
}
#define LDMX4(r0, r1, r2, r3, addr) \
    asm volatile("ldmatrix.sync.aligned.m8n8.x4.shared.b16 {%0,%1,%2,%3}, [%4];" \
        : "=r"(r0), "=r"(r1), "=r"(r2), "=r"(r3) : "r"(addr))
#define LDMT4(r0, r1, r2, r3, addr) \
    asm volatile("ldmatrix.sync.aligned.m8n8.x4.trans.shared.b16 {%0,%1,%2,%3}, [%4];" \
        : "=r"(r0), "=r"(r1), "=r"(r2), "=r"(r3) : "r"(addr))
#define MMA16816(d, a, b0, b1) \
    asm volatile("mma.sync.aligned.m16n8k16.row.col.f32.f16.f16.f32 " \
        "{%0,%1,%2,%3}, {%4,%5,%6,%7}, {%8,%9}, {%0,%1,%2,%3};" \
        : "+f"((d)[0]), "+f"((d)[1]), "+f"((d)[2]), "+f"((d)[3]) \
        : "r"((a)[0]), "r"((a)[1]), "r"((a)[2]), "r"((a)[3]), "r"(b0), "r"(b1))
#define CP16(dst, src) \
    asm volatile("cp.async.cg.shared.global [%0], [%1], 16;" :: "r"(dst), "l"(src))
#define CPCOMMIT() asm volatile("cp.async.commit_group;" ::: "memory")
#define CPWAIT0()  asm volatile("cp.async.wait_group 0;" ::: "memory")
#define CPWAIT1()  asm volatile("cp.async.wait_group 1;" ::: "memory")

// ---------------------------------------------------------------------------
// Prep kernels
// ---------------------------------------------------------------------------
__global__ void split_f32_h(const float4* __restrict__ in,
                            uint2* __restrict__ hi, uint2* __restrict__ lo, int n4)
{
    int i = blockIdx.x * blockDim.x + threadIdx.x;
    if (i >= n4) return;
    float4 v = in[i];
    uint32_t h01, l01, h23, l23;
    cvt_pair_h(v.x, v.y, h01, l01);
    cvt_pair_h(v.z, v.w, h23, l23);
    hi[i] = make_uint2(h01, h23);
    lo[i] = make_uint2(l01, l23);
}
__global__ void cvt_f32_h(const float4* __restrict__ in,
                          uint2* __restrict__ o16, int n4)
{
    int i = blockIdx.x * blockDim.x + threadIdx.x;
    if (i >= n4) return;
    float4 v = in[i];
    o16[i] = make_uint2(cvt_plain_h(v.x, v.y), cvt_plain_h(v.z, v.w));
}

// ---------------------------------------------------------------------------
// fp16 2-product tensor GEMM: C[M,N] = A[M,K] @ (Bh+Bl)[N,K]^T + bias
// A plain fp16, B split hi/lo. BM=128, BN=256, BK=32, 512 threads, 16 warps.
// ---------------------------------------------------------------------------
#define LDS 40
#define A_SB (128 * LDS * 2)        // 10240 B  (plain A tile)
#define B_SB (256 * LDS * 2)        // 20480 B per B tile
#define STAGE_SB (A_SB + 2 * B_SB)  // 51200 B
#define GEMM_SMEM (3 * STAGE_SB)    // 153600 B

__device__ __forceinline__ void gemm_issue(
    const __half* A, const __half* Bh, const __half* Bl,
    uint32_t sbase, int m0, int n0, int K, int cc, int tid)
{
    const uint32_t stg = sbase + (uint32_t)(cc % 3) * STAGE_SB;
    const int k0 = cc * 32;
    {
        int r = tid >> 2, sg = tid & 3;
        uint32_t dof = (uint32_t)(r * 80 + sg * 16);
        size_t ao = (size_t)(m0 + r) * K + k0 + sg * 8;
        CP16(stg + dof, (const char*)(A + ao));
    }
#pragma unroll
    for (int i = 0; i < 2; i++) {
        int c = tid + i * 512;
        int r = c >> 2, sg = c & 3;
        uint32_t dof = (uint32_t)(r * 80 + sg * 16);
        size_t bo = (size_t)(n0 + r) * K + k0 + sg * 8;
        CP16(stg + A_SB + dof, (const char*)(Bh + bo));
        CP16(stg + A_SB + B_SB + dof, (const char*)(Bl + bo));
    }
    CPCOMMIT();
}

__global__ __launch_bounds__(512, 1) void gemm_fp16(
    const __half* __restrict__ A,
    const __half* __restrict__ Bh, const __half* __restrict__ Bl,
    const float* __restrict__ bias, float* __restrict__ C, int N, int K)
{
    extern __shared__ char dsm[];
    __shared__ float sBias[256];

    const int tid  = threadIdx.x;
    const int lane = tid & 31;
    const int wid  = tid >> 5;
    const int wm   = wid >> 3;        // 0..1
    const int wn   = wid & 7;         // 0..7
    const int m0 = blockIdx.y * 128, n0 = blockIdx.x * 256;
    const uint32_t sbase = smem_u32(dsm);

    if (tid < 256) sBias[tid] = bias[n0 + tid];

    const int NCH = K >> 5;
    gemm_issue(A, Bh, Bl, sbase, m0, n0, K, 0, tid);
    gemm_issue(A, Bh, Bl, sbase, m0, n0, K, 1, tid);

    float acc[4][4][4];
#pragma unroll
    for (int mt = 0; mt < 4; mt++)
#pragma unroll
        for (int nt = 0; nt < 4; nt++)
#pragma unroll
            for (int r = 0; r < 4; r++) acc[mt][nt][r] = 0.0f;

    const uint32_t a_row  = (uint32_t)(wm * 64 + (lane & 15));
    const uint32_t a_koff = (uint32_t)((lane >> 4) * 8);
    const uint32_t b_row  = (uint32_t)(wn * 32 + (lane & 7) + ((lane >> 4) << 3));
    const uint32_t b_koff = (uint32_t)(((lane >> 3) & 1) * 8);

    for (int c = 0; c < NCH; c++) {
        CPWAIT1();
        __syncthreads();
        if (c + 2 < NCH) gemm_issue(A, Bh, Bl, sbase, m0, n0, K, c + 2, tid);
        else CPCOMMIT();

        const uint32_t stg = sbase + (uint32_t)(c % 3) * STAGE_SB;
#pragma unroll
        for (int ks = 0; ks < 2; ks++) {
            const uint32_t kofs = (uint32_t)(ks * 16);
            uint32_t a[4][4];
#pragma unroll
            for (int mt = 0; mt < 4; mt++) {
                uint32_t adr = stg + ((a_row + mt * 16) * LDS + kofs + a_koff) * 2;
                LDMX4(a[mt][0], a[mt][1], a[mt][2], a[mt][3], adr);
            }
            uint32_t bh[2][4], bl[2][4];
#pragma unroll
            for (int p = 0; p < 2; p++) {
                uint32_t adr = stg + A_SB
                             + ((b_row + p * 16) * LDS + kofs + b_koff) * 2;
                LDMX4(bh[p][0], bh[p][1], bh[p][2], bh[p][3], adr);
                LDMX4(bl[p][0], bl[p][1], bl[p][2], bl[p][3], adr + B_SB);
            }
#pragma unroll
            for (int mt = 0; mt < 4; mt++)
#pragma unroll
                for (int nt = 0; nt < 4; nt++) {
                    const int p = nt >> 1, hh = (nt & 1) * 2;
                    MMA16816(acc[mt][nt], a[mt], bh[p][hh], bh[p][hh + 1]);
                }
#pragma unroll
            for (int mt = 0; mt < 4; mt++)
#pragma unroll
                for (int nt = 0; nt < 4; nt++) {
                    const int p = nt >> 1, hh = (nt & 1) * 2;
                    MMA16816(acc[mt][nt], a[mt], bl[p][hh], bl[p][hh + 1]);
                }
        }
    }

    const int erow = wm * 64 + (lane >> 2);
    const int ecol = wn * 32 + (lane & 3) * 2;
#pragma unroll
    for (int mt = 0; mt < 4; mt++) {
#pragma unroll
        for (int nt = 0; nt < 4; nt++) {
            const int cc = ecol + nt * 8;
            const float b0 = sBias[cc], b1 = sBias[cc + 1];
            float* p0 = C + (size_t)(m0 + erow + mt * 16) * N + n0 + cc;
            float* p1 = C + (size_t)(m0 + erow + mt * 16 + 8) * N + n0 + cc;
            float2 v0 = {acc[mt][nt][0] + b0, acc[mt][nt][1] + b1};
            float2 v1 = {acc[mt][nt][2] + b0, acc[mt][nt][3] + b1};
            *(float2*)p0 = v0;
            *(float2*)p1 = v1;
        }
    }
}

// ---------------------------------------------------------------------------
// RoPE + layout + fp16 hi/lo split (Q scaled by 1/sqrt(D))
// ---------------------------------------------------------------------------
__device__ __forceinline__ void split1h(float x, __half* ph, __half* pl) {
    __half h = __float2half_rn(x);
    *ph = h;
    *pl = __float2half_rn(x - __half2float(h));
}

__global__ __launch_bounds__(256) void rope_split(
    const float* __restrict__ qkv,
    __half* __restrict__ Qh, __half* __restrict__ Ql,
    __half* __restrict__ Kh, __half* __restrict__ Kl,
    __half* __restrict__ Vh, __half* __restrict__ Vl)
{
    int idx = blockIdx.x * blockDim.x + threadIdx.x;   // NBH*SEQ*64
    if (idx >= NBH * SEQ * 64) return;
    int j  = idx & 63;
    int s  = (idx >> 6) & (SEQ - 1);
    int bh = idx >> 17;
    int b = bh >> 4, h = bh & 15;

    size_t base = ((size_t)(b * SEQ + s) * 3) * EMB + h * HDIM;
    size_t dst  = ((size_t)bh * SEQ + s) * HDIM + j;
    const float scale = 0.08838834764831845f;

    float inv = powf(10000.0f, -(float)j / 64.0f);
    float ang = (float)s * inv;
    float sn, cs;
    sincosf(ang, &sn, &cs);

    float q1 = qkv[base + j], q2 = qkv[base + 64 + j];
    split1h((q1 * cs - q2 * sn) * scale, Qh + dst, Ql + dst);
    split1h((q1 * sn + q2 * cs) * scale, Qh + dst + 64, Ql + dst + 64);
    float k1 = qkv[base + EMB + j], k2 = qkv[base + EMB + 64 + j];
    split1h(k1 * cs - k2 * sn, Kh + dst, Kl + dst);
    split1h(k1 * sn + k2 * cs, Kh + dst + 64, Kl + dst + 64);
    float v1 = qkv[base + 2 * EMB + j], v2 = qkv[base + 2 * EMB + 64 + j];
    split1h(v1, Vh + dst, Vl + dst);
    split1h(v2, Vh + dst + 64, Vl + dst + 64);
}

// ---------------------------------------------------------------------------
// Flash attention, fp16 3-product (near-exact), causal. ctx -> plain fp16.
// 128 threads (4 warps x 16 q-rows), 64x64 KV tiles, D=128.
// ---------------------------------------------------------------------------
#define FL_STRIDE_B 272                  // 136 fp16 per smem row
#define FL_TILE (64 * FL_STRIDE_B)       // 17408 B
#define FLASH_SMEM (6 * FL_TILE)         // 104448 B

__global__ __launch_bounds__(128, 2) void flash_mma(
    const __half* __restrict__ Qh, const __half* __restrict__ Ql,
    const __half* __restrict__ Kh, const __half* __restrict__ Kl,
    const __half* __restrict__ Vh, const __half* __restrict__ Vl,
    __half* __restrict__ ctx)
{
    extern __shared__ char fsm[];
    const int qt = gridDim.x - 1 - blockIdx.x;   // heavy tiles first
    const int bh = blockIdx.y;
    const int tid = threadIdx.x, lane = tid & 31, w = tid >> 5;
    const int q0 = qt * 64;
    const uint32_t sb = smem_u32(fsm);

    {
        const size_t qo = ((size_t)bh * SEQ + q0) * HDIM;
#pragma unroll
        for (int i = 0; i < 8; i++) {
            int c = tid + i * 128;
            int r = c >> 4, sg = c & 15;
            *(uint4*)(fsm + 0 * FL_TILE + r * FL_STRIDE_B + sg * 16) =
                *(const uint4*)(Qh + qo + r * HDIM + sg * 8);
            *(uint4*)(fsm + 1 * FL_TILE + r * FL_STRIDE_B + sg * 16) =
                *(const uint4*)(Ql + qo + r * HDIM + sg * 8);
        }
    }

    float m0v = -1e30f, m1v = -1e30f, l0v = 0.0f, l1v = 0.0f;
    float o[16][4];
#pragma unroll
    for (int nt = 0; nt < 16; nt++)
#pragma unroll
        for (int r = 0; r < 4; r++) o[nt][r] = 0.0f;

    const uint32_t a_row  = (uint32_t)(w * 16 + (lane & 15));
    const uint32_t a_koff = (uint32_t)((lane >> 4) * 8);
    const uint32_t b_row  = (uint32_t)((lane & 7) + ((lane >> 4) << 3));
    const uint32_t b_koff = (uint32_t)(((lane >> 3) & 1) * 8);
    const uint32_t v_row  = (uint32_t)(lane & 15);
    const uint32_t v_coff = (uint32_t)((lane >> 4) * 8);

    for (int kt = 0; kt <= qt; kt++) {
        __syncthreads();

        const size_t ko = ((size_t)bh * SEQ + kt * 64) * HDIM;
#pragma unroll
        for (int i = 0; i < 8; i++) {
            int c = tid + i * 128;
            int r = c >> 4, sg = c & 15;
            uint32_t dof = (uint32_t)(r * FL_STRIDE_B + sg * 16);
            size_t so = ko + r * HDIM + sg * 8;
            CP16(sb + 2 * FL_TILE + dof, (const char*)(Kh + so));
            CP16(sb + 3 * FL_TILE + dof, (const char*)(Kl + so));
        }
        CPCOMMIT();
#pragma unroll
        for (int i = 0; i < 8; i++) {
            int c = tid + i * 128;
            int r = c >> 4, sg = c & 15;
            uint32_t dof = (uint32_t)(r * FL_STRIDE_B + sg * 16);
            size_t so = ko + r * HDIM + sg * 8;
            CP16(sb + 4 * FL_TILE + dof, (const char*)(Vh + so));
            CP16(sb + 5 * FL_TILE + dof, (const char*)(Vl + so));
        }
        CPCOMMIT();

        CPWAIT1();
        __syncthreads();

        float s[8][4];
#pragma unroll
        for (int nt = 0; nt < 8; nt++)
#pragma unroll
            for (int r = 0; r < 4; r++) s[nt][r] = 0.0f;

#pragma unroll
        for (int ks = 0; ks < 8; ks++) {
            uint32_t qh[4], ql[4];
            uint32_t qadr = sb + 0 * FL_TILE + a_row * FL_STRIDE_B
                          + (ks * 16 + a_koff) * 2;
            LDMX4(qh[0], qh[1], qh[2], qh[3], qadr);
            LDMX4(ql[0], ql[1], ql[2], ql[3], qadr + FL_TILE);
            uint32_t khf[4][4], klf[4][4];
#pragma unroll
            for (int np = 0; np < 4; np++) {
                uint32_t kadr = sb + 2 * FL_TILE
                              + (np * 16 + b_row) * FL_STRIDE_B
                              + (ks * 16 + b_koff) * 2;
                LDMX4(khf[np][0], khf[np][1], khf[np][2], khf[np][3], kadr);
                LDMX4(klf[np][0], klf[np][1], klf[np][2], klf[np][3], kadr + FL_TILE);
            }
#pragma unroll
            for (int np = 0; np < 4; np++) {
                MMA16816(s[2*np],   qh, khf[np][0], khf[np][1]);
                MMA16816(s[2*np+1], qh, khf[np][2], khf[np][3]);
            }
#pragma unroll
            for (int np = 0; np < 4; np++) {
                MMA16816(s[2*np],   qh, klf[np][0], klf[np][1]);
                MMA16816(s[2*np+1], qh, klf[np][2], klf[np][3]);
            }
#pragma unroll
            for (int np = 0; np < 4; np++) {
                MMA16816(s[2*np],   ql, khf[np][0], khf[np][1]);
                MMA16816(s[2*np+1], ql, khf[np][2], khf[np][3]);
            }
        }

        if (kt == qt) {
            const int r0 = w * 16 + (lane >> 2);
            const int r1 = r0 + 8;
#pragma unroll
            for (int nt = 0; nt < 8; nt++) {
                const int cb = nt * 8 + (lane & 3) * 2;
                if (cb     > r0) s[nt][0] = -1e30f;
                if (cb + 1 > r0) s[nt][1] = -1e30f;
                if (cb     > r1) s[nt][2] = -1e30f;
                if (cb + 1 > r1) s[nt][3] = -1e30f;
            }
        }

        float mx0 = -1e30f, mx1 = -1e30f;
#pragma unroll
        for (int nt = 0; nt < 8; nt++) {
            mx0 = fmaxf(mx0, fmaxf(s[nt][0], s[nt][1]));
            mx1 = fmaxf(mx1, fmaxf(s[nt][2], s[nt][3]));
        }
        mx0 = fmaxf(mx0, __shfl_xor_sync(0xffffffffu, mx0, 1));
        mx0 = fmaxf(mx0, __shfl_xor_sync(0xffffffffu, mx0, 2));
        mx1 = fmaxf(mx1, __shfl_xor_sync(0xffffffffu, mx1, 1));
        mx1 = fmaxf(mx1, __shfl_xor_sync(0xffffffffu, mx1, 2));

        float mn0 = fmaxf(m0v, mx0), mn1 = fmaxf(m1v, mx1);
        float sf0 = __expf(m0v - mn0), sf1 = __expf(m1v - mn1);
        m0v = mn0; m1v = mn1;

        float ls0 = 0.0f, ls1 = 0.0f;
#pragma unroll
        for (int nt = 0; nt < 8; nt++) {
            s[nt][0] = __expf(s[nt][0] - mn0); ls0 += s[nt][0];
            s[nt][1] = __expf(s[nt][1] - mn0); ls0 += s[nt][1];
            s[nt][2] = __expf(s[nt][2] - mn1); ls1 += s[nt][2];
            s[nt][3] = __expf(s[nt][3] - mn1); ls1 += s[nt][3];
        }
        ls0 += __shfl_xor_sync(0xffffffffu, ls0, 1);
        ls0 += __shfl_xor_sync(0xffffffffu, ls0, 2);
        ls1 += __shfl_xor_sync(0xffffffffu, ls1, 1);
        ls1 += __shfl_xor_sync(0xffffffffu, ls1, 2);
        l0v = l0v * sf0 + ls0;
        l1v = l1v * sf1 + ls1;
#pragma unroll
        for (int nt = 0; nt < 16; nt++) {
            o[nt][0] *= sf0; o[nt][1] *= sf0;
            o[nt][2] *= sf1; o[nt][3] *= sf1;
        }

        uint32_t ph[4][4], pl[4][4];
#pragma unroll
        for (int k2 = 0; k2 < 4; k2++) {
            cvt_pair_h(s[2*k2][0],   s[2*k2][1],   ph[k2][0], pl[k2][0]);
            cvt_pair_h(s[2*k2][2],   s[2*k2][3],   ph[k2][1], pl[k2][1]);
            cvt_pair_h(s[2*k2+1][0], s[2*k2+1][1], ph[k2][2], pl[k2][2]);
            cvt_pair_h(s[2*k2+1][2], s[2*k2+1][3], ph[k2][3], pl[k2][3]);
        }

        CPWAIT0();
        __syncthreads();

#pragma unroll
        for (int k2 = 0; k2 < 4; k2++) {
#pragma unroll
            for (int npp = 0; npp < 4; npp++) {
                const int np0 = 2 * npp, np1 = 2 * npp + 1;
                uint32_t vh0[4], vl0[4], vh1[4], vl1[4];
                uint32_t va0 = sb + 4 * FL_TILE
                             + (k2 * 16 + v_row) * FL_STRIDE_B
                             + (np0 * 16 + v_coff) * 2;
                uint32_t va1 = va0 + 32;
                LDMT4(vh0[0], vh0[1], vh0[2], vh0[3], va0);
                LDMT4(vl0[0], vl0[1], vl0[2], vl0[3], va0 + FL_TILE);
                LDMT4(vh1[0], vh1[1], vh1[2], vh1[3], va1);
                LDMT4(vl1[0], vl1[1], vl1[2], vl1[3], va1 + FL_TILE);
                MMA16816(o[2*np0],   ph[k2], vh0[0], vh0[1]);
                MMA16816(o[2*np0+1], ph[k2], vh0[2], vh0[3]);
                MMA16816(o[2*np1],   ph[k2], vh1[0], vh1[1]);
                MMA16816(o[2*np1+1], ph[k2], vh1[2], vh1[3]);
                MMA16816(o[2*np0],   ph[k2], vl0[0], vl0[1]);
                MMA16816(o[2*np0+1], ph[k2], vl0[2], vl0[3]);
                MMA16816(o[2*np1],   ph[k2], vl1[0], vl1[1]);
                MMA16816(o[2*np1+1], ph[k2], vl1[2], vl1[3]);
                MMA16816(o[2*np0],   pl[k2], vh0[0], vh0[1]);
                MMA16816(o[2*np0+1], pl[k2], vh0[2], vh0[3]);
                MMA16816(o[2*np1],   pl[k2], vh1[0], vh1[1]);
                MMA16816(o[2*np1+1], pl[k2], vh1[2], vh1[3]);
            }
        }
    }

    // epilogue: ctx = O / l -> plain fp16
    const float inv0 = 1.0f / l0v, inv1 = 1.0f / l1v;
    const int b = bh >> 4, h = bh & 15;
    const int gr0 = q0 + w * 16 + (lane >> 2);
    const size_t ro0 = (size_t)(b * SEQ + gr0) * EMB + h * HDIM;
    const size_t ro1 = (size_t)(b * SEQ + gr0 + 8) * EMB + h * HDIM;
#pragma unroll
    for (int nt = 0; nt < 16; nt++) {
        const int col = nt * 8 + (lane & 3) * 2;
        *(uint32_t*)(ctx + ro0 + col) = cvt_plain_h(o[nt][0] * inv0, o[nt][1] * inv0);
        *(uint32_t*)(ctx + ro1 + col) = cvt_plain_h(o[nt][2] * inv1, o[nt][3] * inv1);
    }
}

// ---------------------------------------------------------------------------
extern "C" void kernel_launch(void* const* d_in, const int* in_sizes, int n_in,
                              void* d_out, int out_size)
{
    const float* x      = (const float*)d_in[0];
    const float* wqkv_w = (const float*)d_in[1];
    const float* wqkv_b = (const float*)d_in[2];
    const float* out_w  = (const float*)d_in[3];
    const float* out_b  = (const float*)d_in[4];
    float* out = (float*)d_out;

    float* qkv;
    __half *x16, *wh, *wl, *oh, *ol;
    __half *qh, *ql, *kh, *kl, *vh, *vl, *c16;
    cudaGetSymbolAddress((void**)&qkv, g_qkv);
    cudaGetSymbolAddress((void**)&x16, g_x16);
    cudaGetSymbolAddress((void**)&wh, g_wh);  cudaGetSymbolAddress((void**)&wl, g_wl);
    cudaGetSymbolAddress((void**)&oh, g_oh);  cudaGetSymbolAddress((void**)&ol, g_ol);
    cudaGetSymbolAddress((void**)&qh, g_qhh); cudaGetSymbolAddress((void**)&ql, g_qll);
    cudaGetSymbolAddress((void**)&kh, g_khh); cudaGetSymbolAddress((void**)&kl, g_kll);
    cudaGetSymbolAddress((void**)&vh, g_vhh); cudaGetSymbolAddress((void**)&vl, g_vll);
    cudaGetSymbolAddress((void**)&c16, g_c16);

    cudaFuncSetAttribute(gemm_fp16, cudaFuncAttributeMaxDynamicSharedMemorySize, GEMM_SMEM);
    cudaFuncSetAttribute(flash_mma, cudaFuncAttributeMaxDynamicSharedMemorySize, FLASH_SMEM);

    int n4;
    n4 = MROWS * EMB / 4;
    cvt_f32_h<<<(n4 + 255) / 256, 256>>>((const float4*)x, (uint2*)x16, n4);
    n4 = THREE_E * EMB / 4;
    split_f32_h<<<(n4 + 255) / 256, 256>>>((const float4*)wqkv_w, (uint2*)wh, (uint2*)wl, n4);
    n4 = EMB * EMB / 4;
    split_f32_h<<<(n4 + 255) / 256, 256>>>((const float4*)out_w, (uint2*)oh, (uint2*)ol, n4);

    dim3 g1(THREE_E / 256, MROWS / 128);
    gemm_fp16<<<g1, 512, GEMM_SMEM>>>(x16, wh, wl, wqkv_b, qkv, THREE_E, EMB);

    int nr = NBH * SEQ * 64;
    rope_split<<<(nr + 255) / 256, 256>>>(qkv, qh, ql, kh, kl, vh, vl);

    dim3 g2(SEQ / 64, NBH);
    flash_mma<<<g2, 128, FLASH_SMEM>>>(qh, ql, kh, kl, vh, vl, c16);

    dim3 g3(EMB / 256, MROWS / 128);
    gemm_fp16<<<g3, 512, GEMM_SMEM>>>(c16, oh, ol, out_b, out, EMB, EMB);
}

// round 8
// speedup vs baseline: 4.5904x; 1.0859x over previous
#include <cuda_runtime.h>
#include <cuda_fp16.h>
#include <math.h>
#include <stdint.h>

#define BATCH 2
#define SEQ   2048
#define EMB   2048
#define HEADS 16
#define HDIM  128
#define THREE_E 6144
#define MROWS (BATCH*SEQ)     // 4096
#define NBH   (BATCH*HEADS)   // 32

// ---------------- scratch (__device__ globals; no cudaMalloc) ----------------
__device__ float g_qkv[(size_t)MROWS * THREE_E];                 // fp32 QKV
__device__ __half g_x16[(size_t)MROWS * EMB];                    // x plain fp16
__device__ __half g_wh[(size_t)THREE_E * EMB], g_wl[(size_t)THREE_E * EMB];
__device__ __half g_oh[(size_t)EMB * EMB],     g_ol[(size_t)EMB * EMB];
__device__ __half g_qhh[(size_t)NBH*SEQ*HDIM], g_qll[(size_t)NBH*SEQ*HDIM];
__device__ __half g_khh[(size_t)NBH*SEQ*HDIM], g_kll[(size_t)NBH*SEQ*HDIM];
__device__ __half g_vhh[(size_t)NBH*SEQ*HDIM], g_vll[(size_t)NBH*SEQ*HDIM];
__device__ __half g_c16[(size_t)MROWS * EMB];                    // ctx plain fp16

// ---------------- PTX helpers ----------------
__device__ __forceinline__ uint32_t smem_u32(const void* p) {
    uint32_t a;
    asm("{ .reg .u64 t; cvta.to.shared.u64 t, %1; cvt.u32.u64 %0, t; }"
        : "=r"(a) : "l"(p));
    return a;
}
// fp32 pair -> hi fp16x2 + residual-lo fp16x2 (f0 in low half)
__device__ __forceinline__ void cvt_pair_h(float f0, float f1,
                                           uint32_t& h, uint32_t& l) {
    asm("cvt.rn.f16x2.f32 %0, %1, %2;" : "=r"(h) : "f"(f1), "f"(f0));
    __half2 hh = *reinterpret_cast<__half2*>(&h);
    float2 hf = __half22float2(hh);
    __half2 lh = __floats2half2_rn(f0 - hf.x, f1 - hf.y);
    l = *reinterpret_cast<uint32_t*>(&lh);
}
__device__ __forceinline__ uint32_t cvt_plain_h(float f0, float f1) {
    uint32_t h;
    asm("cvt.rn.f16x2.f32 %0, %1, %2;" : "=r"(h) : "f"(f1), "f"(f0));
    return h;
}
#define LDMX4(r0, r1, r2, r3, addr) \
    asm volatile("ldmatrix.sync.aligned.m8n8.x4.shared.b16 {%0,%1,%2,%3}, [%4];" \
        : "=r"(r0), "=r"(r1), "=r"(r2), "=r"(r3) : "r"(addr))
#define LDMT4(r0, r1, r2, r3, addr) \
    asm volatile("ldmatrix.sync.aligned.m8n8.x4.trans.shared.b16 {%0,%1,%2,%3}, [%4];" \
        : "=r"(r0), "=r"(r1), "=r"(r2), "=r"(r3) : "r"(addr))
#define MMA16816(d, a, b0, b1) \
    asm volatile("mma.sync.aligned.m16n8k16.row.col.f32.f16.f16.f32 " \
        "{%0,%1,%2,%3}, {%4,%5,%6,%7}, {%8,%9}, {%0,%1,%2,%3};" \
        : "+f"((d)[0]), "+f"((d)[1]), "+f"((d)[2]), "+f"((d)[3]) \
        : "r"((a)[0]), "r"((a)[1]), "r"((a)[2]), "r"((a)[3]), "r"(b0), "r"(b1))
#define CP16(dst, src) \
    asm volatile("cp.async.cg.shared.global [%0], [%1], 16;" :: "r"(dst), "l"(src))
#define CPCOMMIT() asm volatile("cp.async.commit_group;" ::: "memory")
#define CPWAIT0()  asm volatile("cp.async.wait_group 0;" ::: "memory")
#define CPWAIT1()  asm volatile("cp.async.wait_group 1;" ::: "memory")

// ---------------------------------------------------------------------------
// Prep kernels
// ---------------------------------------------------------------------------
__global__ void split_f32_h(const float4* __restrict__ in,
                            uint2* __restrict__ hi, uint2* __restrict__ lo, int n4)
{
    int i = blockIdx.x * blockDim.x + threadIdx.x;
    if (i >= n4) return;
    float4 v = in[i];
    uint32_t h01, l01, h23, l23;
    cvt_pair_h(v.x, v.y, h01, l01);
    cvt_pair_h(v.z, v.w, h23, l23);
    hi[i] = make_uint2(h01, h23);
    lo[i] = make_uint2(l01, l23);
}
__global__ void cvt_f32_h(const float4* __restrict__ in,
                          uint2* __restrict__ o16, int n4)
{
    int i = blockIdx.x * blockDim.x + threadIdx.x;
    if (i >= n4) return;
    float4 v = in[i];
    o16[i] = make_uint2(cvt_plain_h(v.x, v.y), cvt_plain_h(v.z, v.w));
}

// ---------------------------------------------------------------------------
// fp16 2-product tensor GEMM: C[M,N] = A[M,K] @ (Bh+Bl)[N,K]^T + bias
// BM=BN=128, BK=32, 256 threads = 8 warps (2m x 4n), warp tile 64x32.
// 3-stage cp.async pipeline; 2 CTAs per SM for cross-CTA latency hiding.
// ---------------------------------------------------------------------------
#define LDS 40
#define A_SB (128 * LDS * 2)        // 10240 B
#define B_SB (128 * LDS * 2)        // 10240 B per B tile
#define STAGE_SB (A_SB + 2 * B_SB)  // 30720 B
#define GEMM_SMEM (3 * STAGE_SB)    // 92160 B  -> 2 CTAs/SM

__device__ __forceinline__ void gemm_issue(
    const __half* A, const __half* Bh, const __half* Bl,
    uint32_t sbase, int m0, int n0, int K, int cc, int tid)
{
    const uint32_t stg = sbase + (uint32_t)(cc % 3) * STAGE_SB;
    const int k0 = cc * 32;
#pragma unroll
    for (int i = 0; i < 2; i++) {
        int c = tid + i * 256;      // 0..511
        int r = c >> 2, sg = c & 3;
        uint32_t dof = (uint32_t)(r * 80 + sg * 16);
        size_t ao = (size_t)(m0 + r) * K + k0 + sg * 8;
        size_t bo = (size_t)(n0 + r) * K + k0 + sg * 8;
        CP16(stg + dof, (const char*)(A + ao));
        CP16(stg + A_SB + dof, (const char*)(Bh + bo));
        CP16(stg + A_SB + B_SB + dof, (const char*)(Bl + bo));
    }
    CPCOMMIT();
}

__global__ __launch_bounds__(256, 2) void gemm_fp16(
    const __half* __restrict__ A,
    const __half* __restrict__ Bh, const __half* __restrict__ Bl,
    const float* __restrict__ bias, float* __restrict__ C, int N, int K)
{
    extern __shared__ char dsm[];
    __shared__ float sBias[128];

    const int tid  = threadIdx.x;
    const int lane = tid & 31;
    const int wid  = tid >> 5;
    const int wm   = wid >> 2;        // 0..1
    const int wn   = wid & 3;         // 0..3
    const int m0 = blockIdx.y * 128, n0 = blockIdx.x * 128;
    const uint32_t sbase = smem_u32(dsm);

    if (tid < 128) sBias[tid] = bias[n0 + tid];

    const int NCH = K >> 5;
    gemm_issue(A, Bh, Bl, sbase, m0, n0, K, 0, tid);
    gemm_issue(A, Bh, Bl, sbase, m0, n0, K, 1, tid);

    float acc[4][4][4];
#pragma unroll
    for (int mt = 0; mt < 4; mt++)
#pragma unroll
        for (int nt = 0; nt < 4; nt++)
#pragma unroll
            for (int r = 0; r < 4; r++) acc[mt][nt][r] = 0.0f;

    const uint32_t a_row  = (uint32_t)(wm * 64 + (lane & 15));
    const uint32_t a_koff = (uint32_t)((lane >> 4) * 8);
    const uint32_t b_row  = (uint32_t)(wn * 32 + (lane & 7) + ((lane >> 4) << 3));
    const uint32_t b_koff = (uint32_t)(((lane >> 3) & 1) * 8);

    for (int c = 0; c < NCH; c++) {
        CPWAIT1();
        __syncthreads();
        if (c + 2 < NCH) gemm_issue(A, Bh, Bl, sbase, m0, n0, K, c + 2, tid);
        else CPCOMMIT();

        const uint32_t stg = sbase + (uint32_t)(c % 3) * STAGE_SB;
#pragma unroll
        for (int ks = 0; ks < 2; ks++) {
            const uint32_t kofs = (uint32_t)(ks * 16);
            uint32_t a[4][4];
#pragma unroll
            for (int mt = 0; mt < 4; mt++) {
                uint32_t adr = stg + ((a_row + mt * 16) * LDS + kofs + a_koff) * 2;
                LDMX4(a[mt][0], a[mt][1], a[mt][2], a[mt][3], adr);
            }
            uint32_t bh[2][4], bl[2][4];
#pragma unroll
            for (int p = 0; p < 2; p++) {
                uint32_t adr = stg + A_SB
                             + ((b_row + p * 16) * LDS + kofs + b_koff) * 2;
                LDMX4(bh[p][0], bh[p][1], bh[p][2], bh[p][3], adr);
                LDMX4(bl[p][0], bl[p][1], bl[p][2], bl[p][3], adr + B_SB);
            }
#pragma unroll
            for (int mt = 0; mt < 4; mt++)
#pragma unroll
                for (int nt = 0; nt < 4; nt++) {
                    const int p = nt >> 1, hh = (nt & 1) * 2;
                    MMA16816(acc[mt][nt], a[mt], bh[p][hh], bh[p][hh + 1]);
                }
#pragma unroll
            for (int mt = 0; mt < 4; mt++)
#pragma unroll
                for (int nt = 0; nt < 4; nt++) {
                    const int p = nt >> 1, hh = (nt & 1) * 2;
                    MMA16816(acc[mt][nt], a[mt], bl[p][hh], bl[p][hh + 1]);
                }
        }
    }

    const int erow = wm * 64 + (lane >> 2);
    const int ecol = wn * 32 + (lane & 3) * 2;
#pragma unroll
    for (int mt = 0; mt < 4; mt++) {
#pragma unroll
        for (int nt = 0; nt < 4; nt++) {
            const int cc = ecol + nt * 8;
            const float b0 = sBias[cc], b1 = sBias[cc + 1];
            float* p0 = C + (size_t)(m0 + erow + mt * 16) * N + n0 + cc;
            float* p1 = C + (size_t)(m0 + erow + mt * 16 + 8) * N + n0 + cc;
            float2 v0 = {acc[mt][nt][0] + b0, acc[mt][nt][1] + b1};
            float2 v1 = {acc[mt][nt][2] + b0, acc[mt][nt][3] + b1};
            *(float2*)p0 = v0;
            *(float2*)p1 = v1;
        }
    }
}

// ---------------------------------------------------------------------------
// RoPE + layout + fp16 hi/lo split (Q scaled by 1/sqrt(D))
// ---------------------------------------------------------------------------
__device__ __forceinline__ void split1h(float x, __half* ph, __half* pl) {
    __half h = __float2half_rn(x);
    *ph = h;
    *pl = __float2half_rn(x - __half2float(h));
}

__global__ __launch_bounds__(256) void rope_split(
    const float* __restrict__ qkv,
    __half* __restrict__ Qh, __half* __restrict__ Ql,
    __half* __restrict__ Kh, __half* __restrict__ Kl,
    __half* __restrict__ Vh, __half* __restrict__ Vl)
{
    int idx = blockIdx.x * blockDim.x + threadIdx.x;   // NBH*SEQ*64
    if (idx >= NBH * SEQ * 64) return;
    int j  = idx & 63;
    int s  = (idx >> 6) & (SEQ - 1);
    int bh = idx >> 17;
    int b = bh >> 4, h = bh & 15;

    size_t base = ((size_t)(b * SEQ + s) * 3) * EMB + h * HDIM;
    size_t dst  = ((size_t)bh * SEQ + s) * HDIM + j;
    const float scale = 0.08838834764831845f;

    float inv = powf(10000.0f, -(float)j / 64.0f);
    float ang = (float)s * inv;
    float sn, cs;
    sincosf(ang, &sn, &cs);

    float q1 = qkv[base + j], q2 = qkv[base + 64 + j];
    split1h((q1 * cs - q2 * sn) * scale, Qh + dst, Ql + dst);
    split1h((q1 * sn + q2 * cs) * scale, Qh + dst + 64, Ql + dst + 64);
    float k1 = qkv[base + EMB + j], k2 = qkv[base + EMB + 64 + j];
    split1h(k1 * cs - k2 * sn, Kh + dst, Kl + dst);
    split1h(k1 * sn + k2 * cs, Kh + dst + 64, Kl + dst + 64);
    float v1 = qkv[base + 2 * EMB + j], v2 = qkv[base + 2 * EMB + 64 + j];
    split1h(v1, Vh + dst, Vl + dst);
    split1h(v2, Vh + dst + 64, Vl + dst + 64);
}

// ---------------------------------------------------------------------------
// Flash attention, fp16 3-product (near-exact), causal. ctx -> plain fp16.
// 128 threads (4 warps x 16 q-rows), 64x64 KV tiles, D=128, 2 CTAs/SM.
// ---------------------------------------------------------------------------
#define FL_STRIDE_B 272                  // 136 fp16 per smem row
#define FL_TILE (64 * FL_STRIDE_B)       // 17408 B
#define FLASH_SMEM (6 * FL_TILE)         // 104448 B

__global__ __launch_bounds__(128, 2) void flash_mma(
    const __half* __restrict__ Qh, const __half* __restrict__ Ql,
    const __half* __restrict__ Kh, const __half* __restrict__ Kl,
    const __half* __restrict__ Vh, const __half* __restrict__ Vl,
    __half* __restrict__ ctx)
{
    extern __shared__ char fsm[];
    const int qt = gridDim.x - 1 - blockIdx.x;   // heavy tiles first
    const int bh = blockIdx.y;
    const int tid = threadIdx.x, lane = tid & 31, w = tid >> 5;
    const int q0 = qt * 64;
    const uint32_t sb = smem_u32(fsm);

    {
        const size_t qo = ((size_t)bh * SEQ + q0) * HDIM;
#pragma unroll
        for (int i = 0; i < 8; i++) {
            int c = tid + i * 128;
            int r = c >> 4, sg = c & 15;
            *(uint4*)(fsm + 0 * FL_TILE + r * FL_STRIDE_B + sg * 16) =
                *(const uint4*)(Qh + qo + r * HDIM + sg * 8);
            *(uint4*)(fsm + 1 * FL_TILE + r * FL_STRIDE_B + sg * 16) =
                *(const uint4*)(Ql + qo + r * HDIM + sg * 8);
        }
    }

    float m0v = -1e30f, m1v = -1e30f, l0v = 0.0f, l1v = 0.0f;
    float o[16][4];
#pragma unroll
    for (int nt = 0; nt < 16; nt++)
#pragma unroll
        for (int r = 0; r < 4; r++) o[nt][r] = 0.0f;

    const uint32_t a_row  = (uint32_t)(w * 16 + (lane & 15));
    const uint32_t a_koff = (uint32_t)((lane >> 4) * 8);
    const uint32_t b_row  = (uint32_t)((lane & 7) + ((lane >> 4) << 3));
    const uint32_t b_koff = (uint32_t)(((lane >> 3) & 1) * 8);
    const uint32_t v_row  = (uint32_t)(lane & 15);
    const uint32_t v_coff = (uint32_t)((lane >> 4) * 8);

    for (int kt = 0; kt <= qt; kt++) {
        __syncthreads();

        const size_t ko = ((size_t)bh * SEQ + kt * 64) * HDIM;
#pragma unroll
        for (int i = 0; i < 8; i++) {
            int c = tid + i * 128;
            int r = c >> 4, sg = c & 15;
            uint32_t dof = (uint32_t)(r * FL_STRIDE_B + sg * 16);
            size_t so = ko + r * HDIM + sg * 8;
            CP16(sb + 2 * FL_TILE + dof, (const char*)(Kh + so));
            CP16(sb + 3 * FL_TILE + dof, (const char*)(Kl + so));
        }
        CPCOMMIT();
#pragma unroll
        for (int i = 0; i < 8; i++) {
            int c = tid + i * 128;
            int r = c >> 4, sg = c & 15;
            uint32_t dof = (uint32_t)(r * FL_STRIDE_B + sg * 16);
            size_t so = ko + r * HDIM + sg * 8;
            CP16(sb + 4 * FL_TILE + dof, (const char*)(Vh + so));
            CP16(sb + 5 * FL_TILE + dof, (const char*)(Vl + so));
        }
        CPCOMMIT();

        CPWAIT1();
        __syncthreads();

        float s[8][4];
#pragma unroll
        for (int nt = 0; nt < 8; nt++)
#pragma unroll
            for (int r = 0; r < 4; r++) s[nt][r] = 0.0f;

#pragma unroll
        for (int ks = 0; ks < 8; ks++) {
            uint32_t qh[4], ql[4];
            uint32_t qadr = sb + 0 * FL_TILE + a_row * FL_STRIDE_B
                          + (ks * 16 + a_koff) * 2;
            LDMX4(qh[0], qh[1], qh[2], qh[3], qadr);
            LDMX4(ql[0], ql[1], ql[2], ql[3], qadr + FL_TILE);
            uint32_t khf[4][4], klf[4][4];
#pragma unroll
            for (int np = 0; np < 4; np++) {
                uint32_t kadr = sb + 2 * FL_TILE
                              + (np * 16 + b_row) * FL_STRIDE_B
                              + (ks * 16 + b_koff) * 2;
                LDMX4(khf[np][0], khf[np][1], khf[np][2], khf[np][3], kadr);
                LDMX4(klf[np][0], klf[np][1], klf[np][2], klf[np][3], kadr + FL_TILE);
            }
#pragma unroll
            for (int np = 0; np < 4; np++) {
                MMA16816(s[2*np],   qh, khf[np][0], khf[np][1]);
                MMA16816(s[2*np+1], qh, khf[np][2], khf[np][3]);
            }
#pragma unroll
            for (int np = 0; np < 4; np++) {
                MMA16816(s[2*np],   qh, klf[np][0], klf[np][1]);
                MMA16816(s[2*np+1], qh, klf[np][2], klf[np][3]);
            }
#pragma unroll
            for (int np = 0; np < 4; np++) {
                MMA16816(s[2*np],   ql, khf[np][0], khf[np][1]);
                MMA16816(s[2*np+1], ql, khf[np][2], khf[np][3]);
            }
        }

        if (kt == qt) {
            const int r0 = w * 16 + (lane >> 2);
            const int r1 = r0 + 8;
#pragma unroll
            for (int nt = 0; nt < 8; nt++) {
                const int cb = nt * 8 + (lane & 3) * 2;
                if (cb     > r0) s[nt][0] = -1e30f;
                if (cb + 1 > r0) s[nt][1] = -1e30f;
                if (cb     > r1) s[nt][2] = -1e30f;
                if (cb + 1 > r1) s[nt][3] = -1e30f;
            }
        }

        float mx0 = -1e30f, mx1 = -1e30f;
#pragma unroll
        for (int nt = 0; nt < 8; nt++) {
            mx0 = fmaxf(mx0, fmaxf(s[nt][0], s[nt][1]));
            mx1 = fmaxf(mx1, fmaxf(s[nt][2], s[nt][3]));
        }
        mx0 = fmaxf(mx0, __shfl_xor_sync(0xffffffffu, mx0, 1));
        mx0 = fmaxf(mx0, __shfl_xor_sync(0xffffffffu, mx0, 2));
        mx1 = fmaxf(mx1, __shfl_xor_sync(0xffffffffu, mx1, 1));
        mx1 = fmaxf(mx1, __shfl_xor_sync(0xffffffffu, mx1, 2));

        float mn0 = fmaxf(m0v, mx0), mn1 = fmaxf(m1v, mx1);
        float sf0 = __expf(m0v - mn0), sf1 = __expf(m1v - mn1);
        m0v = mn0; m1v = mn1;

        float ls0 = 0.0f, ls1 = 0.0f;
#pragma unroll
        for (int nt = 0; nt < 8; nt++) {
            s[nt][0] = __expf(s[nt][0] - mn0); ls0 += s[nt][0];
            s[nt][1] = __expf(s[nt][1] - mn0); ls0 += s[nt][1];
            s[nt][2] = __expf(s[nt][2] - mn1); ls1 += s[nt][2];
            s[nt][3] = __expf(s[nt][3] - mn1); ls1 += s[nt][3];
        }
        ls0 += __shfl_xor_sync(0xffffffffu, ls0, 1);
        ls0 += __shfl_xor_sync(0xffffffffu, ls0, 2);
        ls1 += __shfl_xor_sync(0xffffffffu, ls1, 1);
        ls1 += __shfl_xor_sync(0xffffffffu, ls1, 2);
        l0v = l0v * sf0 + ls0;
        l1v = l1v * sf1 + ls1;
#pragma unroll
        for (int nt = 0; nt < 16; nt++) {
            o[nt][0] *= sf0; o[nt][1] *= sf0;
            o[nt][2] *= sf1; o[nt][3] *= sf1;
        }

        uint32_t ph[4][4], pl[4][4];
#pragma unroll
        for (int k2 = 0; k2 < 4; k2++) {
            cvt_pair_h(s[2*k2][0],   s[2*k2][1],   ph[k2][0], pl[k2][0]);
            cvt_pair_h(s[2*k2][2],   s[2*k2][3],   ph[k2][1], pl[k2][1]);
            cvt_pair_h(s[2*k2+1][0], s[2*k2+1][1], ph[k2][2], pl[k2][2]);
            cvt_pair_h(s[2*k2+1][2], s[2*k2+1][3], ph[k2][3], pl[k2][3]);
        }

        CPWAIT0();
        __syncthreads();

#pragma unroll
        for (int k2 = 0; k2 < 4; k2++) {
#pragma unroll
            for (int npp = 0; npp < 4; npp++) {
                const int np0 = 2 * npp, np1 = 2 * npp + 1;
                uint32_t vh0[4], vl0[4], vh1[4], vl1[4];
                uint32_t va0 = sb + 4 * FL_TILE
                             + (k2 * 16 + v_row) * FL_STRIDE_B
                             + (np0 * 16 + v_coff) * 2;
                uint32_t va1 = va0 + 32;
                LDMT4(vh0[0], vh0[1], vh0[2], vh0[3], va0);
                LDMT4(vl0[0], vl0[1], vl0[2], vl0[3], va0 + FL_TILE);
                LDMT4(vh1[0], vh1[1], vh1[2], vh1[3], va1);
                LDMT4(vl1[0], vl1[1], vl1[2], vl1[3], va1 + FL_TILE);
                MMA16816(o[2*np0],   ph[k2], vh0[0], vh0[1]);
                MMA16816(o[2*np0+1], ph[k2], vh0[2], vh0[3]);
                MMA16816(o[2*np1],   ph[k2], vh1[0], vh1[1]);
                MMA16816(o[2*np1+1], ph[k2], vh1[2], vh1[3]);
                MMA16816(o[2*np0],   ph[k2], vl0[0], vl0[1]);
                MMA16816(o[2*np0+1], ph[k2], vl0[2], vl0[3]);
                MMA16816(o[2*np1],   ph[k2], vl1[0], vl1[1]);
                MMA16816(o[2*np1+1], ph[k2], vl1[2], vl1[3]);
                MMA16816(o[2*np0],   pl[k2], vh0[0], vh0[1]);
                MMA16816(o[2*np0+1], pl[k2], vh0[2], vh0[3]);
                MMA16816(o[2*np1],   pl[k2], vh1[0], vh1[1]);
                MMA16816(o[2*np1+1], pl[k2], vh1[2], vh1[3]);
            }
        }
    }

    // epilogue: ctx = O / l -> plain fp16
    const float inv0 = 1.0f / l0v, inv1 = 1.0f / l1v;
    const int b = bh >> 4, h = bh & 15;
    const int gr0 = q0 + w * 16 + (lane >> 2);
    const size_t ro0 = (size_t)(b * SEQ + gr0) * EMB + h * HDIM;
    const size_t ro1 = (size_t)(b * SEQ + gr0 + 8) * EMB + h * HDIM;
#pragma unroll
    for (int nt = 0; nt < 16; nt++) {
        const int col = nt * 8 + (lane & 3) * 2;
        *(uint32_t*)(ctx + ro0 + col) = cvt_plain_h(o[nt][0] * inv0, o[nt][1] * inv0);
        *(uint32_t*)(ctx + ro1 + col) = cvt_plain_h(o[nt][2] * inv1, o[nt][3] * inv1);
    }
}

// ---------------------------------------------------------------------------
extern "C" void kernel_launch(void* const* d_in, const int* in_sizes, int n_in,
                              void* d_out, int out_size)
{
    const float* x      = (const float*)d_in[0];
    const float* wqkv_w = (const float*)d_in[1];
    const float* wqkv_b = (const float*)d_in[2];
    const float* out_w  = (const float*)d_in[3];
    const float* out_b  = (const float*)d_in[4];
    float* out = (float*)d_out;

    float* qkv;
    __half *x16, *wh, *wl, *oh, *ol;
    __half *qh, *ql, *kh, *kl, *vh, *vl, *c16;
    cudaGetSymbolAddress((void**)&qkv, g_qkv);
    cudaGetSymbolAddress((void**)&x16, g_x16);
    cudaGetSymbolAddress((void**)&wh, g_wh);  cudaGetSymbolAddress((void**)&wl, g_wl);
    cudaGetSymbolAddress((void**)&oh, g_oh);  cudaGetSymbolAddress((void**)&ol, g_ol);
    cudaGetSymbolAddress((void**)&qh, g_qhh); cudaGetSymbolAddress((void**)&ql, g_qll);
    cudaGetSymbolAddress((void**)&kh, g_khh); cudaGetSymbolAddress((void**)&kl, g_kll);
    cudaGetSymbolAddress((void**)&vh, g_vhh); cudaGetSymbolAddress((void**)&vl, g_vll);
    cudaGetSymbolAddress((void**)&c16, g_c16);

    cudaFuncSetAttribute(gemm_fp16, cudaFuncAttributeMaxDynamicSharedMemorySize, GEMM_SMEM);
    cudaFuncSetAttribute(flash_mma, cudaFuncAttributeMaxDynamicSharedMemorySize, FLASH_SMEM);

    int n4;
    n4 = MROWS * EMB / 4;
    cvt_f32_h<<<(n4 + 255) / 256, 256>>>((const float4*)x, (uint2*)x16, n4);
    n4 = THREE_E * EMB / 4;
    split_f32_h<<<(n4 + 255) / 256, 256>>>((const float4*)wqkv_w, (uint2*)wh, (uint2*)wl, n4);
    n4 = EMB * EMB / 4;
    split_f32_h<<<(n4 + 255) / 256, 256>>>((const float4*)out_w, (uint2*)oh, (uint2*)ol, n4);

    dim3 g1(THREE_E / 128, MROWS / 128);
    gemm_fp16<<<g1, 256, GEMM_SMEM>>>(x16, wh, wl, wqkv_b, qkv, THREE_E, EMB);

    int nr = NBH * SEQ * 64;
    rope_split<<<(nr + 255) / 256, 256>>>(qkv, qh, ql, kh, kl, vh, vl);

    dim3 g2(SEQ / 64, NBH);
    flash_mma<<<g2, 128, FLASH_SMEM>>>(qh, ql, kh, kl, vh, vl, c16);

    dim3 g3(EMB / 128, MROWS / 128);
    gemm_fp16<<<g3, 256, GEMM_SMEM>>>(c16, oh, ol, out_b, out, EMB, EMB);
}

// round 9
// speedup vs baseline: 4.8921x; 1.0657x over previous
#include <cuda_runtime.h>
#include <cuda_fp16.h>
#include <math.h>
#include <stdint.h>

#define BATCH 2
#define SEQ   2048
#define EMB   2048
#define HEADS 16
#define HDIM  128
#define THREE_E 6144
#define MROWS (BATCH*SEQ)     // 4096
#define NBH   (BATCH*HEADS)   // 32

// ---------------- scratch (__device__ globals; no cudaMalloc) ----------------
__device__ float g_qkv[(size_t)MROWS * THREE_E];                 // fp32 QKV
__device__ __half g_x16[(size_t)MROWS * EMB];                    // x plain fp16
__device__ __half g_wh[(size_t)THREE_E * EMB], g_wl[(size_t)THREE_E * EMB];
__device__ __half g_oh[(size_t)EMB * EMB],     g_ol[(size_t)EMB * EMB];
__device__ __half g_qp[(size_t)NBH*SEQ*HDIM];                    // Q plain fp16
__device__ __half g_khh[(size_t)NBH*SEQ*HDIM], g_kll[(size_t)NBH*SEQ*HDIM];
__device__ __half g_vhh[(size_t)NBH*SEQ*HDIM], g_vll[(size_t)NBH*SEQ*HDIM];
__device__ __half g_c16[(size_t)MROWS * EMB];                    // ctx plain fp16

// ---------------- PTX helpers ----------------
__device__ __forceinline__ uint32_t smem_u32(const void* p) {
    uint32_t a;
    asm("{ .reg .u64 t; cvta.to.shared.u64 t, %1; cvt.u32.u64 %0, t; }"
        : "=r"(a) : "l"(p));
    return a;
}
// fp32 pair -> hi fp16x2 + residual-lo fp16x2 (f0 in low half)
__device__ __forceinline__ void cvt_pair_h(float f0, float f1,
                                           uint32_t& h, uint32_t& l) {
    asm("cvt.rn.f16x2.f32 %0, %1, %2;" : "=r"(h) : "f"(f1), "f"(f0));
    __half2 hh = *reinterpret_cast<__half2*>(&h);
    float2 hf = __half22float2(hh);
    __half2 lh = __floats2half2_rn(f0 - hf.x, f1 - hf.y);
    l = *reinterpret_cast<uint32_t*>(&lh);
}
__device__ __forceinline__ uint32_t cvt_plain_h(float f0, float f1) {
    uint32_t h;
    asm("cvt.rn.f16x2.f32 %0, %1, %2;" : "=r"(h) : "f"(f1), "f"(f0));
    return h;
}
#define LDMX4(r0, r1, r2, r3, addr) \
    asm volatile("ldmatrix.sync.aligned.m8n8.x4.shared.b16 {%0,%1,%2,%3}, [%4];" \
        : "=r"(r0), "=r"(r1), "=r"(r2), "=r"(r3) : "r"(addr))
#define LDMT4(r0, r1, r2, r3, addr) \
    asm volatile("ldmatrix.sync.aligned.m8n8.x4.trans.shared.b16 {%0,%1,%2,%3}, [%4];" \
        : "=r"(r0), "=r"(r1), "=r"(r2), "=r"(r3) : "r"(addr))
#define MMA16816(d, a, b0, b1) \
    asm volatile("mma.sync.aligned.m16n8k16.row.col.f32.f16.f16.f32 " \
        "{%0,%1,%2,%3}, {%4,%5,%6,%7}, {%8,%9}, {%0,%1,%2,%3};" \
        : "+f"((d)[0]), "+f"((d)[1]), "+f"((d)[2]), "+f"((d)[3]) \
        : "r"((a)[0]), "r"((a)[1]), "r"((a)[2]), "r"((a)[3]), "r"(b0), "r"(b1))
#define CP16(dst, src) \
    asm volatile("cp.async.cg.shared.global [%0], [%1], 16;" :: "r"(dst), "l"(src))
#define CPCOMMIT() asm volatile("cp.async.commit_group;" ::: "memory")
#define CPWAIT0()  asm volatile("cp.async.wait_group 0;" ::: "memory")
#define CPWAIT1()  asm volatile("cp.async.wait_group 1;" ::: "memory")

// ---------------------------------------------------------------------------
// Prep kernels
// ---------------------------------------------------------------------------
__global__ void split_f32_h(const float4* __restrict__ in,
                            uint2* __restrict__ hi, uint2* __restrict__ lo, int n4)
{
    int i = blockIdx.x * blockDim.x + threadIdx.x;
    if (i >= n4) return;
    float4 v = in[i];
    uint32_t h01, l01, h23, l23;
    cvt_pair_h(v.x, v.y, h01, l01);
    cvt_pair_h(v.z, v.w, h23, l23);
    hi[i] = make_uint2(h01, h23);
    lo[i] = make_uint2(l01, l23);
}
__global__ void cvt_f32_h(const float4* __restrict__ in,
                          uint2* __restrict__ o16, int n4)
{
    int i = blockIdx.x * blockDim.x + threadIdx.x;
    if (i >= n4) return;
    float4 v = in[i];
    o16[i] = make_uint2(cvt_plain_h(v.x, v.y), cvt_plain_h(v.z, v.w));
}

// ---------------------------------------------------------------------------
// fp16 2-product tensor GEMM: C[M,N] = A[M,K] @ (Bh+Bl)[N,K]^T + bias
// BM=BN=128, BK=32, 256 threads = 8 warps (2m x 4n), warp tile 64x32.
// 3-stage cp.async pipeline; 2 CTAs per SM.
// ---------------------------------------------------------------------------
#define LDS 40
#define A_SB (128 * LDS * 2)        // 10240 B
#define B_SB (128 * LDS * 2)        // 10240 B per B tile
#define STAGE_SB (A_SB + 2 * B_SB)  // 30720 B
#define GEMM_SMEM (3 * STAGE_SB)    // 92160 B  -> 2 CTAs/SM

__device__ __forceinline__ void gemm_issue(
    const __half* A, const __half* Bh, const __half* Bl,
    uint32_t sbase, int m0, int n0, int K, int cc, int tid)
{
    const uint32_t stg = sbase + (uint32_t)(cc % 3) * STAGE_SB;
    const int k0 = cc * 32;
#pragma unroll
    for (int i = 0; i < 2; i++) {
        int c = tid + i * 256;      // 0..511
        int r = c >> 2, sg = c & 3;
        uint32_t dof = (uint32_t)(r * 80 + sg * 16);
        size_t ao = (size_t)(m0 + r) * K + k0 + sg * 8;
        size_t bo = (size_t)(n0 + r) * K + k0 + sg * 8;
        CP16(stg + dof, (const char*)(A + ao));
        CP16(stg + A_SB + dof, (const char*)(Bh + bo));
        CP16(stg + A_SB + B_SB + dof, (const char*)(Bl + bo));
    }
    CPCOMMIT();
}

__global__ __launch_bounds__(256, 2) void gemm_fp16(
    const __half* __restrict__ A,
    const __half* __restrict__ Bh, const __half* __restrict__ Bl,
    const float* __restrict__ bias, float* __restrict__ C, int N, int K)
{
    extern __shared__ char dsm[];
    __shared__ float sBias[128];

    const int tid  = threadIdx.x;
    const int lane = tid & 31;
    const int wid  = tid >> 5;
    const int wm   = wid >> 2;        // 0..1
    const int wn   = wid & 3;         // 0..3
    const int m0 = blockIdx.y * 128, n0 = blockIdx.x * 128;
    const uint32_t sbase = smem_u32(dsm);

    if (tid < 128) sBias[tid] = bias[n0 + tid];

    const int NCH = K >> 5;
    gemm_issue(A, Bh, Bl, sbase, m0, n0, K, 0, tid);
    gemm_issue(A, Bh, Bl, sbase, m0, n0, K, 1, tid);

    float acc[4][4][4];
#pragma unroll
    for (int mt = 0; mt < 4; mt++)
#pragma unroll
        for (int nt = 0; nt < 4; nt++)
#pragma unroll
            for (int r = 0; r < 4; r++) acc[mt][nt][r] = 0.0f;

    const uint32_t a_row  = (uint32_t)(wm * 64 + (lane & 15));
    const uint32_t a_koff = (uint32_t)((lane >> 4) * 8);
    const uint32_t b_row  = (uint32_t)(wn * 32 + (lane & 7) + ((lane >> 4) << 3));
    const uint32_t b_koff = (uint32_t)(((lane >> 3) & 1) * 8);

    for (int c = 0; c < NCH; c++) {
        CPWAIT1();
        __syncthreads();
        if (c + 2 < NCH) gemm_issue(A, Bh, Bl, sbase, m0, n0, K, c + 2, tid);
        else CPCOMMIT();

        const uint32_t stg = sbase + (uint32_t)(c % 3) * STAGE_SB;
#pragma unroll
        for (int ks = 0; ks < 2; ks++) {
            const uint32_t kofs = (uint32_t)(ks * 16);
            uint32_t a[4][4];
#pragma unroll
            for (int mt = 0; mt < 4; mt++) {
                uint32_t adr = stg + ((a_row + mt * 16) * LDS + kofs + a_koff) * 2;
                LDMX4(a[mt][0], a[mt][1], a[mt][2], a[mt][3], adr);
            }
            uint32_t bh[2][4], bl[2][4];
#pragma unroll
            for (int p = 0; p < 2; p++) {
                uint32_t adr = stg + A_SB
                             + ((b_row + p * 16) * LDS + kofs + b_koff) * 2;
                LDMX4(bh[p][0], bh[p][1], bh[p][2], bh[p][3], adr);
                LDMX4(bl[p][0], bl[p][1], bl[p][2], bl[p][3], adr + B_SB);
            }
#pragma unroll
            for (int mt = 0; mt < 4; mt++)
#pragma unroll
                for (int nt = 0; nt < 4; nt++) {
                    const int p = nt >> 1, hh = (nt & 1) * 2;
                    MMA16816(acc[mt][nt], a[mt], bh[p][hh], bh[p][hh + 1]);
                }
#pragma unroll
            for (int mt = 0; mt < 4; mt++)
#pragma unroll
                for (int nt = 0; nt < 4; nt++) {
                    const int p = nt >> 1, hh = (nt & 1) * 2;
                    MMA16816(acc[mt][nt], a[mt], bl[p][hh], bl[p][hh + 1]);
                }
        }
    }

    const int erow = wm * 64 + (lane >> 2);
    const int ecol = wn * 32 + (lane & 3) * 2;
#pragma unroll
    for (int mt = 0; mt < 4; mt++) {
#pragma unroll
        for (int nt = 0; nt < 4; nt++) {
            const int cc = ecol + nt * 8;
            const float b0 = sBias[cc], b1 = sBias[cc + 1];
            float* p0 = C + (size_t)(m0 + erow + mt * 16) * N + n0 + cc;
            float* p1 = C + (size_t)(m0 + erow + mt * 16 + 8) * N + n0 + cc;
            float2 v0 = {acc[mt][nt][0] + b0, acc[mt][nt][1] + b1};
            float2 v1 = {acc[mt][nt][2] + b0, acc[mt][nt][3] + b1};
            *(float2*)p0 = v0;
            *(float2*)p1 = v1;
        }
    }
}

// ---------------------------------------------------------------------------
// RoPE + layout: Q plain fp16 (scaled), K hi/lo, V hi/lo
// ---------------------------------------------------------------------------
__device__ __forceinline__ void split1h(float x, __half* ph, __half* pl) {
    __half h = __float2half_rn(x);
    *ph = h;
    *pl = __float2half_rn(x - __half2float(h));
}

__global__ __launch_bounds__(256) void rope_split(
    const float* __restrict__ qkv,
    __half* __restrict__ Qp,
    __half* __restrict__ Kh, __half* __restrict__ Kl,
    __half* __restrict__ Vh, __half* __restrict__ Vl)
{
    int idx = blockIdx.x * blockDim.x + threadIdx.x;   // NBH*SEQ*64
    if (idx >= NBH * SEQ * 64) return;
    int j  = idx & 63;
    int s  = (idx >> 6) & (SEQ - 1);
    int bh = idx >> 17;
    int b = bh >> 4, h = bh & 15;

    size_t base = ((size_t)(b * SEQ + s) * 3) * EMB + h * HDIM;
    size_t dst  = ((size_t)bh * SEQ + s) * HDIM + j;
    const float scale = 0.08838834764831845f;

    float inv = powf(10000.0f, -(float)j / 64.0f);
    float ang = (float)s * inv;
    float sn, cs;
    sincosf(ang, &sn, &cs);

    float q1 = qkv[base + j], q2 = qkv[base + 64 + j];
    Qp[dst]      = __float2half_rn((q1 * cs - q2 * sn) * scale);
    Qp[dst + 64] = __float2half_rn((q1 * sn + q2 * cs) * scale);
    float k1 = qkv[base + EMB + j], k2 = qkv[base + EMB + 64 + j];
    split1h(k1 * cs - k2 * sn, Kh + dst, Kl + dst);
    split1h(k1 * sn + k2 * cs, Kh + dst + 64, Kl + dst + 64);
    float v1 = qkv[base + 2 * EMB + j], v2 = qkv[base + 2 * EMB + 64 + j];
    split1h(v1, Vh + dst, Vl + dst);
    split1h(v2, Vh + dst + 64, Vl + dst + 64);
}

// ---------------------------------------------------------------------------
// Flash attention: Q plain fp16, K/V hi-lo (2 products each side), causal.
// 128 threads (4 warps x 16 q-rows), 64x64 KV tiles, D=128, 2 CTAs/SM.
// smem tiles: Q, Kh, Kl, Vh, Vl
// ---------------------------------------------------------------------------
#define FL_STRIDE_B 272                  // 136 fp16 per smem row
#define FL_TILE (64 * FL_STRIDE_B)       // 17408 B
#define FLASH_SMEM (5 * FL_TILE)         // 87040 B

__global__ __launch_bounds__(128, 2) void flash_mma(
    const __half* __restrict__ Qp,
    const __half* __restrict__ Kh, const __half* __restrict__ Kl,
    const __half* __restrict__ Vh, const __half* __restrict__ Vl,
    __half* __restrict__ ctx)
{
    extern __shared__ char fsm[];
    const int qt = gridDim.x - 1 - blockIdx.x;   // heavy tiles first
    const int bh = blockIdx.y;
    const int tid = threadIdx.x, lane = tid & 31, w = tid >> 5;
    const int q0 = qt * 64;
    const uint32_t sb = smem_u32(fsm);

    {
        const size_t qo = ((size_t)bh * SEQ + q0) * HDIM;
#pragma unroll
        for (int i = 0; i < 8; i++) {
            int c = tid + i * 128;
            int r = c >> 4, sg = c & 15;
            *(uint4*)(fsm + r * FL_STRIDE_B + sg * 16) =
                *(const uint4*)(Qp + qo + r * HDIM + sg * 8);
        }
    }

    float m0v = -1e30f, m1v = -1e30f, l0v = 0.0f, l1v = 0.0f;
    float o[16][4];
#pragma unroll
    for (int nt = 0; nt < 16; nt++)
#pragma unroll
        for (int r = 0; r < 4; r++) o[nt][r] = 0.0f;

    const uint32_t a_row  = (uint32_t)(w * 16 + (lane & 15));
    const uint32_t a_koff = (uint32_t)((lane >> 4) * 8);
    const uint32_t b_row  = (uint32_t)((lane & 7) + ((lane >> 4) << 3));
    const uint32_t b_koff = (uint32_t)(((lane >> 3) & 1) * 8);
    const uint32_t v_row  = (uint32_t)(lane & 15);
    const uint32_t v_coff = (uint32_t)((lane >> 4) * 8);

    for (int kt = 0; kt <= qt; kt++) {
        __syncthreads();

        const size_t ko = ((size_t)bh * SEQ + kt * 64) * HDIM;
#pragma unroll
        for (int i = 0; i < 8; i++) {
            int c = tid + i * 128;
            int r = c >> 4, sg = c & 15;
            uint32_t dof = (uint32_t)(r * FL_STRIDE_B + sg * 16);
            size_t so = ko + r * HDIM + sg * 8;
            CP16(sb + 1 * FL_TILE + dof, (const char*)(Kh + so));
            CP16(sb + 2 * FL_TILE + dof, (const char*)(Kl + so));
        }
        CPCOMMIT();
#pragma unroll
        for (int i = 0; i < 8; i++) {
            int c = tid + i * 128;
            int r = c >> 4, sg = c & 15;
            uint32_t dof = (uint32_t)(r * FL_STRIDE_B + sg * 16);
            size_t so = ko + r * HDIM + sg * 8;
            CP16(sb + 3 * FL_TILE + dof, (const char*)(Vh + so));
            CP16(sb + 4 * FL_TILE + dof, (const char*)(Vl + so));
        }
        CPCOMMIT();

        CPWAIT1();
        __syncthreads();

        float s[8][4];
#pragma unroll
        for (int nt = 0; nt < 8; nt++)
#pragma unroll
            for (int r = 0; r < 4; r++) s[nt][r] = 0.0f;

#pragma unroll
        for (int ks = 0; ks < 8; ks++) {
            uint32_t q[4];
            uint32_t qadr = sb + a_row * FL_STRIDE_B + (ks * 16 + a_koff) * 2;
            LDMX4(q[0], q[1], q[2], q[3], qadr);
            uint32_t khf[4][4], klf[4][4];
#pragma unroll
            for (int np = 0; np < 4; np++) {
                uint32_t kadr = sb + 1 * FL_TILE
                              + (np * 16 + b_row) * FL_STRIDE_B
                              + (ks * 16 + b_koff) * 2;
                LDMX4(khf[np][0], khf[np][1], khf[np][2], khf[np][3], kadr);
                LDMX4(klf[np][0], klf[np][1], klf[np][2], klf[np][3], kadr + FL_TILE);
            }
#pragma unroll
            for (int np = 0; np < 4; np++) {
                MMA16816(s[2*np],   q, khf[np][0], khf[np][1]);
                MMA16816(s[2*np+1], q, khf[np][2], khf[np][3]);
            }
#pragma unroll
            for (int np = 0; np < 4; np++) {
                MMA16816(s[2*np],   q, klf[np][0], klf[np][1]);
                MMA16816(s[2*np+1], q, klf[np][2], klf[np][3]);
            }
        }

        if (kt == qt) {
            const int r0 = w * 16 + (lane >> 2);
            const int r1 = r0 + 8;
#pragma unroll
            for (int nt = 0; nt < 8; nt++) {
                const int cb = nt * 8 + (lane & 3) * 2;
                if (cb     > r0) s[nt][0] = -1e30f;
                if (cb + 1 > r0) s[nt][1] = -1e30f;
                if (cb     > r1) s[nt][2] = -1e30f;
                if (cb + 1 > r1) s[nt][3] = -1e30f;
            }
        }

        float mx0 = -1e30f, mx1 = -1e30f;
#pragma unroll
        for (int nt = 0; nt < 8; nt++) {
            mx0 = fmaxf(mx0, fmaxf(s[nt][0], s[nt][1]));
            mx1 = fmaxf(mx1, fmaxf(s[nt][2], s[nt][3]));
        }
        mx0 = fmaxf(mx0, __shfl_xor_sync(0xffffffffu, mx0, 1));
        mx0 = fmaxf(mx0, __shfl_xor_sync(0xffffffffu, mx0, 2));
        mx1 = fmaxf(mx1, __shfl_xor_sync(0xffffffffu, mx1, 1));
        mx1 = fmaxf(mx1, __shfl_xor_sync(0xffffffffu, mx1, 2));

        float mn0 = fmaxf(m0v, mx0), mn1 = fmaxf(m1v, mx1);
        float sf0 = __expf(m0v - mn0), sf1 = __expf(m1v - mn1);
        m0v = mn0; m1v = mn1;

        float ls0 = 0.0f, ls1 = 0.0f;
#pragma unroll
        for (int nt = 0; nt < 8; nt++) {
            s[nt][0] = __expf(s[nt][0] - mn0); ls0 += s[nt][0];
            s[nt][1] = __expf(s[nt][1] - mn0); ls0 += s[nt][1];
            s[nt][2] = __expf(s[nt][2] - mn1); ls1 += s[nt][2];
            s[nt][3] = __expf(s[nt][3] - mn1); ls1 += s[nt][3];
        }
        ls0 += __shfl_xor_sync(0xffffffffu, ls0, 1);
        ls0 += __shfl_xor_sync(0xffffffffu, ls0, 2);
        ls1 += __shfl_xor_sync(0xffffffffu, ls1, 1);
        ls1 += __shfl_xor_sync(0xffffffffu, ls1, 2);
        l0v = l0v * sf0 + ls0;
        l1v = l1v * sf1 + ls1;
#pragma unroll
        for (int nt = 0; nt < 16; nt++) {
            o[nt][0] *= sf0; o[nt][1] *= sf0;
            o[nt][2] *= sf1; o[nt][3] *= sf1;
        }

        // P fragments (plain fp16)
        uint32_t ph[4][4];
#pragma unroll
        for (int k2 = 0; k2 < 4; k2++) {
            ph[k2][0] = cvt_plain_h(s[2*k2][0],   s[2*k2][1]);
            ph[k2][1] = cvt_plain_h(s[2*k2][2],   s[2*k2][3]);
            ph[k2][2] = cvt_plain_h(s[2*k2+1][0], s[2*k2+1][1]);
            ph[k2][3] = cvt_plain_h(s[2*k2+1][2], s[2*k2+1][3]);
        }

        CPWAIT0();
        __syncthreads();

        // O += P (Vh + Vl)
#pragma unroll
        for (int k2 = 0; k2 < 4; k2++) {
#pragma unroll
            for (int npp = 0; npp < 4; npp++) {
                const int np0 = 2 * npp, np1 = 2 * npp + 1;
                uint32_t vh0[4], vl0[4], vh1[4], vl1[4];
                uint32_t va0 = sb + 3 * FL_TILE
                             + (k2 * 16 + v_row) * FL_STRIDE_B
                             + (np0 * 16 + v_coff) * 2;
                uint32_t va1 = va0 + 32;
                LDMT4(vh0[0], vh0[1], vh0[2], vh0[3], va0);
                LDMT4(vl0[0], vl0[1], vl0[2], vl0[3], va0 + FL_TILE);
                LDMT4(vh1[0], vh1[1], vh1[2], vh1[3], va1);
                LDMT4(vl1[0], vl1[1], vl1[2], vl1[3], va1 + FL_TILE);
                MMA16816(o[2*np0],   ph[k2], vh0[0], vh0[1]);
                MMA16816(o[2*np0+1], ph[k2], vh0[2], vh0[3]);
                MMA16816(o[2*np1],   ph[k2], vh1[0], vh1[1]);
                MMA16816(o[2*np1+1], ph[k2], vh1[2], vh1[3]);
                MMA16816(o[2*np0],   ph[k2], vl0[0], vl0[1]);
                MMA16816(o[2*np0+1], ph[k2], vl0[2], vl0[3]);
                MMA16816(o[2*np1],   ph[k2], vl1[0], vl1[1]);
                MMA16816(o[2*np1+1], ph[k2], vl1[2], vl1[3]);
            }
        }
    }

    // epilogue: ctx = O / l -> plain fp16
    const float inv0 = 1.0f / l0v, inv1 = 1.0f / l1v;
    const int b = bh >> 4, h = bh & 15;
    const int gr0 = q0 + w * 16 + (lane >> 2);
    const size_t ro0 = (size_t)(b * SEQ + gr0) * EMB + h * HDIM;
    const size_t ro1 = (size_t)(b * SEQ + gr0 + 8) * EMB + h * HDIM;
#pragma unroll
    for (int nt = 0; nt < 16; nt++) {
        const int col = nt * 8 + (lane & 3) * 2;
        *(uint32_t*)(ctx + ro0 + col) = cvt_plain_h(o[nt][0] * inv0, o[nt][1] * inv0);
        *(uint32_t*)(ctx + ro1 + col) = cvt_plain_h(o[nt][2] * inv1, o[nt][3] * inv1);
    }
}

// ---------------------------------------------------------------------------
extern "C" void kernel_launch(void* const* d_in, const int* in_sizes, int n_in,
                              void* d_out, int out_size)
{
    const float* x      = (const float*)d_in[0];
    const float* wqkv_w = (const float*)d_in[1];
    const float* wqkv_b = (const float*)d_in[2];
    const float* out_w  = (const float*)d_in[3];
    const float* out_b  = (const float*)d_in[4];
    float* out = (float*)d_out;

    float* qkv;
    __half *x16, *wh, *wl, *oh, *ol;
    __half *qp, *kh, *kl, *vh, *vl, *c16;
    cudaGetSymbolAddress((void**)&qkv, g_qkv);
    cudaGetSymbolAddress((void**)&x16, g_x16);
    cudaGetSymbolAddress((void**)&wh, g_wh);  cudaGetSymbolAddress((void**)&wl, g_wl);
    cudaGetSymbolAddress((void**)&oh, g_oh);  cudaGetSymbolAddress((void**)&ol, g_ol);
    cudaGetSymbolAddress((void**)&qp, g_qp);
    cudaGetSymbolAddress((void**)&kh, g_khh); cudaGetSymbolAddress((void**)&kl, g_kll);
    cudaGetSymbolAddress((void**)&vh, g_vhh); cudaGetSymbolAddress((void**)&vl, g_vll);
    cudaGetSymbolAddress((void**)&c16, g_c16);

    cudaFuncSetAttribute(gemm_fp16, cudaFuncAttributeMaxDynamicSharedMemorySize, GEMM_SMEM);
    cudaFuncSetAttribute(flash_mma, cudaFuncAttributeMaxDynamicSharedMemorySize, FLASH_SMEM);

    int n4;
    n4 = MROWS * EMB / 4;
    cvt_f32_h<<<(n4 + 255) / 256, 256>>>((const float4*)x, (uint2*)x16, n4);
    n4 = THREE_E * EMB / 4;
    split_f32_h<<<(n4 + 255) / 256, 256>>>((const float4*)wqkv_w, (uint2*)wh, (uint2*)wl, n4);
    n4 = EMB * EMB / 4;
    split_f32_h<<<(n4 + 255) / 256, 256>>>((const float4*)out_w, (uint2*)oh, (uint2*)ol, n4);

    dim3 g1(THREE_E / 128, MROWS / 128);
    gemm_fp16<<<g1, 256, GEMM_SMEM>>>(x16, wh, wl, wqkv_b, qkv, THREE_E, EMB);

    int nr = NBH * SEQ * 64;
    rope_split<<<(nr + 255) / 256, 256>>>(qkv, qp, kh, kl, vh, vl);

    dim3 g2(SEQ / 64, NBH);
    flash_mma<<<g2, 128, FLASH_SMEM>>>(qp, kh, kl, vh, vl, c16);

    dim3 g3(EMB / 128, MROWS / 128);
    gemm_fp16<<<g3, 256, GEMM_SMEM>>>(c16, oh, ol, out_b, out, EMB, EMB);
}

// round 10
// speedup vs baseline: 7.1496x; 1.4615x over previous
#include <cuda_runtime.h>
#include <cuda_fp16.h>
#include <math.h>
#include <stdint.h>

#define BATCH 2
#define SEQ   2048
#define EMB   2048
#define HEADS 16
#define HDIM  128
#define THREE_E 6144
#define MROWS (BATCH*SEQ)     // 4096
#define NBH   (BATCH*HEADS)   // 32

// ---------------- scratch (__device__ globals; no cudaMalloc) ----------------
__device__ float g_qkv[(size_t)MROWS * THREE_E];                 // fp32 QKV
__device__ __half g_x16[(size_t)MROWS * EMB];                    // x plain fp16
__device__ __half g_w16[(size_t)THREE_E * EMB];                  // wqkv plain fp16
__device__ __half g_o16w[(size_t)EMB * EMB];                     // out_w plain fp16
__device__ __half g_qp[(size_t)NBH*SEQ*HDIM];                    // Q plain fp16
__device__ __half g_khh[(size_t)NBH*SEQ*HDIM], g_kll[(size_t)NBH*SEQ*HDIM];
__device__ __half g_vhh[(size_t)NBH*SEQ*HDIM], g_vll[(size_t)NBH*SEQ*HDIM];
__device__ __half g_c16[(size_t)MROWS * EMB];                    // ctx plain fp16

// ---------------- PTX helpers ----------------
__device__ __forceinline__ uint32_t smem_u32(const void* p) {
    uint32_t a;
    asm("{ .reg .u64 t; cvta.to.shared.u64 t, %1; cvt.u32.u64 %0, t; }"
        : "=r"(a) : "l"(p));
    return a;
}
// fp32 pair -> hi fp16x2 + residual-lo fp16x2 (f0 in low half)
__device__ __forceinline__ void cvt_pair_h(float f0, float f1,
                                           uint32_t& h, uint32_t& l) {
    asm("cvt.rn.f16x2.f32 %0, %1, %2;" : "=r"(h) : "f"(f1), "f"(f0));
    __half2 hh = *reinterpret_cast<__half2*>(&h);
    float2 hf = __half22float2(hh);
    __half2 lh = __floats2half2_rn(f0 - hf.x, f1 - hf.y);
    l = *reinterpret_cast<uint32_t*>(&lh);
}
__device__ __forceinline__ uint32_t cvt_plain_h(float f0, float f1) {
    uint32_t h;
    asm("cvt.rn.f16x2.f32 %0, %1, %2;" : "=r"(h) : "f"(f1), "f"(f0));
    return h;
}
#define LDMX4(r0, r1, r2, r3, addr) \
    asm volatile("ldmatrix.sync.aligned.m8n8.x4.shared.b16 {%0,%1,%2,%3}, [%4];" \
        : "=r"(r0), "=r"(r1), "=r"(r2), "=r"(r3) : "r"(addr))
#define LDMT4(r0, r1, r2, r3, addr) \
    asm volatile("ldmatrix.sync.aligned.m8n8.x4.trans.shared.b16 {%0,%1,%2,%3}, [%4];" \
        : "=r"(r0), "=r"(r1), "=r"(r2), "=r"(r3) : "r"(addr))
#define MMA16816(d, a, b0, b1) \
    asm volatile("mma.sync.aligned.m16n8k16.row.col.f32.f16.f16.f32 " \
        "{%0,%1,%2,%3}, {%4,%5,%6,%7}, {%8,%9}, {%0,%1,%2,%3};" \
        : "+f"((d)[0]), "+f"((d)[1]), "+f"((d)[2]), "+f"((d)[3]) \
        : "r"((a)[0]), "r"((a)[1]), "r"((a)[2]), "r"((a)[3]), "r"(b0), "r"(b1))
#define CP16(dst, src) \
    asm volatile("cp.async.cg.shared.global [%0], [%1], 16;" :: "r"(dst), "l"(src))
#define CPCOMMIT() asm volatile("cp.async.commit_group;" ::: "memory")
#define CPWAIT0()  asm volatile("cp.async.wait_group 0;" ::: "memory")
#define CPWAIT1()  asm volatile("cp.async.wait_group 1;" ::: "memory")

// ---------------------------------------------------------------------------
// Prep kernels
// ---------------------------------------------------------------------------
__global__ void cvt_f32_h(const float4* __restrict__ in,
                          uint2* __restrict__ o16, int n4)
{
    int i = blockIdx.x * blockDim.x + threadIdx.x;
    if (i >= n4) return;
    float4 v = in[i];
    o16[i] = make_uint2(cvt_plain_h(v.x, v.y), cvt_plain_h(v.z, v.w));
}

// ---------------------------------------------------------------------------
// fp16 single-product tensor GEMM: C[M,N] = A[M,K] @ B[N,K]^T + bias
// A, B plain fp16. BM=BN=128, BK=32, 256 threads = 8 warps (2m x 4n).
// 3-stage cp.async pipeline; 2 CTAs per SM.
// ---------------------------------------------------------------------------
#define LDS 40
#define A_SB (128 * LDS * 2)        // 10240 B
#define B_SB (128 * LDS * 2)        // 10240 B
#define STAGE_SB (A_SB + B_SB)      // 20480 B
#define GEMM_SMEM (3 * STAGE_SB)    // 61440 B  -> 2 CTAs/SM

__device__ __forceinline__ void gemm_issue(
    const __half* A, const __half* B,
    uint32_t sbase, int m0, int n0, int K, int cc, int tid)
{
    const uint32_t stg = sbase + (uint32_t)(cc % 3) * STAGE_SB;
    const int k0 = cc * 32;
#pragma unroll
    for (int i = 0; i < 2; i++) {
        int c = tid + i * 256;      // 0..511
        int r = c >> 2, sg = c & 3;
        uint32_t dof = (uint32_t)(r * 80 + sg * 16);
        size_t ao = (size_t)(m0 + r) * K + k0 + sg * 8;
        size_t bo = (size_t)(n0 + r) * K + k0 + sg * 8;
        CP16(stg + dof, (const char*)(A + ao));
        CP16(stg + A_SB + dof, (const char*)(B + bo));
    }
    CPCOMMIT();
}

__global__ __launch_bounds__(256, 2) void gemm_fp16(
    const __half* __restrict__ A, const __half* __restrict__ B,
    const float* __restrict__ bias, float* __restrict__ C, int N, int K)
{
    extern __shared__ char dsm[];
    __shared__ float sBias[128];

    const int tid  = threadIdx.x;
    const int lane = tid & 31;
    const int wid  = tid >> 5;
    const int wm   = wid >> 2;        // 0..1
    const int wn   = wid & 3;         // 0..3
    const int m0 = blockIdx.y * 128, n0 = blockIdx.x * 128;
    const uint32_t sbase = smem_u32(dsm);

    if (tid < 128) sBias[tid] = bias[n0 + tid];

    const int NCH = K >> 5;
    gemm_issue(A, B, sbase, m0, n0, K, 0, tid);
    gemm_issue(A, B, sbase, m0, n0, K, 1, tid);

    float acc[4][4][4];
#pragma unroll
    for (int mt = 0; mt < 4; mt++)
#pragma unroll
        for (int nt = 0; nt < 4; nt++)
#pragma unroll
            for (int r = 0; r < 4; r++) acc[mt][nt][r] = 0.0f;

    const uint32_t a_row  = (uint32_t)(wm * 64 + (lane & 15));
    const uint32_t a_koff = (uint32_t)((lane >> 4) * 8);
    const uint32_t b_row  = (uint32_t)(wn * 32 + (lane & 7) + ((lane >> 4) << 3));
    const uint32_t b_koff = (uint32_t)(((lane >> 3) & 1) * 8);

    for (int c = 0; c < NCH; c++) {
        CPWAIT1();
        __syncthreads();
        if (c + 2 < NCH) gemm_issue(A, B, sbase, m0, n0, K, c + 2, tid);
        else CPCOMMIT();

        const uint32_t stg = sbase + (uint32_t)(c % 3) * STAGE_SB;
#pragma unroll
        for (int ks = 0; ks < 2; ks++) {
            const uint32_t kofs = (uint32_t)(ks * 16);
            uint32_t a[4][4];
#pragma unroll
            for (int mt = 0; mt < 4; mt++) {
                uint32_t adr = stg + ((a_row + mt * 16) * LDS + kofs + a_koff) * 2;
                LDMX4(a[mt][0], a[mt][1], a[mt][2], a[mt][3], adr);
            }
            uint32_t b[2][4];
#pragma unroll
            for (int p = 0; p < 2; p++) {
                uint32_t adr = stg + A_SB
                             + ((b_row + p * 16) * LDS + kofs + b_koff) * 2;
                LDMX4(b[p][0], b[p][1], b[p][2], b[p][3], adr);
            }
#pragma unroll
            for (int mt = 0; mt < 4; mt++)
#pragma unroll
                for (int nt = 0; nt < 4; nt++) {
                    const int p = nt >> 1, hh = (nt & 1) * 2;
                    MMA16816(acc[mt][nt], a[mt], b[p][hh], b[p][hh + 1]);
                }
        }
    }

    const int erow = wm * 64 + (lane >> 2);
    const int ecol = wn * 32 + (lane & 3) * 2;
#pragma unroll
    for (int mt = 0; mt < 4; mt++) {
#pragma unroll
        for (int nt = 0; nt < 4; nt++) {
            const int cc = ecol + nt * 8;
            const float b0 = sBias[cc], b1 = sBias[cc + 1];
            float* p0 = C + (size_t)(m0 + erow + mt * 16) * N + n0 + cc;
            float* p1 = C + (size_t)(m0 + erow + mt * 16 + 8) * N + n0 + cc;
            float2 v0 = {acc[mt][nt][0] + b0, acc[mt][nt][1] + b1};
            float2 v1 = {acc[mt][nt][2] + b0, acc[mt][nt][3] + b1};
            *(float2*)p0 = v0;
            *(float2*)p1 = v1;
        }
    }
}

// ---------------------------------------------------------------------------
// RoPE + layout: Q plain fp16 (scaled), K hi/lo, V hi/lo
// ---------------------------------------------------------------------------
__device__ __forceinline__ void split1h(float x, __half* ph, __half* pl) {
    __half h = __float2half_rn(x);
    *ph = h;
    *pl = __float2half_rn(x - __half2float(h));
}

__global__ __launch_bounds__(256) void rope_split(
    const float* __restrict__ qkv,
    __half* __restrict__ Qp,
    __half* __restrict__ Kh, __half* __restrict__ Kl,
    __half* __restrict__ Vh, __half* __restrict__ Vl)
{
    int idx = blockIdx.x * blockDim.x + threadIdx.x;   // NBH*SEQ*64
    if (idx >= NBH * SEQ * 64) return;
    int j  = idx & 63;
    int s  = (idx >> 6) & (SEQ - 1);
    int bh = idx >> 17;
    int b = bh >> 4, h = bh & 15;

    size_t base = ((size_t)(b * SEQ + s) * 3) * EMB + h * HDIM;
    size_t dst  = ((size_t)bh * SEQ + s) * HDIM + j;
    const float scale = 0.08838834764831845f;

    float inv = powf(10000.0f, -(float)j / 64.0f);
    float ang = (float)s * inv;
    float sn, cs;
    sincosf(ang, &sn, &cs);

    float q1 = qkv[base + j], q2 = qkv[base + 64 + j];
    Qp[dst]      = __float2half_rn((q1 * cs - q2 * sn) * scale);
    Qp[dst + 64] = __float2half_rn((q1 * sn + q2 * cs) * scale);
    float k1 = qkv[base + EMB + j], k2 = qkv[base + EMB + 64 + j];
    split1h(k1 * cs - k2 * sn, Kh + dst, Kl + dst);
    split1h(k1 * sn + k2 * cs, Kh + dst + 64, Kl + dst + 64);
    float v1 = qkv[base + 2 * EMB + j], v2 = qkv[base + 2 * EMB + 64 + j];
    split1h(v1, Vh + dst, Vl + dst);
    split1h(v2, Vh + dst + 64, Vl + dst + 64);
}

// ---------------------------------------------------------------------------
// Flash attention: Q plain fp16, K/V hi-lo (2 products each side), causal.
// 128 threads (4 warps x 16 q-rows), 64x64 KV tiles, D=128, 2 CTAs/SM.
// smem tiles: Q, Kh, Kl, Vh, Vl
// ---------------------------------------------------------------------------
#define FL_STRIDE_B 272                  // 136 fp16 per smem row
#define FL_TILE (64 * FL_STRIDE_B)       // 17408 B
#define FLASH_SMEM (5 * FL_TILE)         // 87040 B

__global__ __launch_bounds__(128, 2) void flash_mma(
    const __half* __restrict__ Qp,
    const __half* __restrict__ Kh, const __half* __restrict__ Kl,
    const __half* __restrict__ Vh, const __half* __restrict__ Vl,
    __half* __restrict__ ctx)
{
    extern __shared__ char fsm[];
    const int qt = gridDim.x - 1 - blockIdx.x;   // heavy tiles first
    const int bh = blockIdx.y;
    const int tid = threadIdx.x, lane = tid & 31, w = tid >> 5;
    const int q0 = qt * 64;
    const uint32_t sb = smem_u32(fsm);

    {
        const size_t qo = ((size_t)bh * SEQ + q0) * HDIM;
#pragma unroll
        for (int i = 0; i < 8; i++) {
            int c = tid + i * 128;
            int r = c >> 4, sg = c & 15;
            *(uint4*)(fsm + r * FL_STRIDE_B + sg * 16) =
                *(const uint4*)(Qp + qo + r * HDIM + sg * 8);
        }
    }

    float m0v = -1e30f, m1v = -1e30f, l0v = 0.0f, l1v = 0.0f;
    float o[16][4];
#pragma unroll
    for (int nt = 0; nt < 16; nt++)
#pragma unroll
        for (int r = 0; r < 4; r++) o[nt][r] = 0.0f;

    const uint32_t a_row  = (uint32_t)(w * 16 + (lane & 15));
    const uint32_t a_koff = (uint32_t)((lane >> 4) * 8);
    const uint32_t b_row  = (uint32_t)((lane & 7) + ((lane >> 4) << 3));
    const uint32_t b_koff = (uint32_t)(((lane >> 3) & 1) * 8);
    const uint32_t v_row  = (uint32_t)(lane & 15);
    const uint32_t v_coff = (uint32_t)((lane >> 4) * 8);

    for (int kt = 0; kt <= qt; kt++) {
        __syncthreads();

        const size_t ko = ((size_t)bh * SEQ + kt * 64) * HDIM;
#pragma unroll
        for (int i = 0; i < 8; i++) {
            int c = tid + i * 128;
            int r = c >> 4, sg = c & 15;
            uint32_t dof = (uint32_t)(r * FL_STRIDE_B + sg * 16);
            size_t so = ko + r * HDIM + sg * 8;
            CP16(sb + 1 * FL_TILE + dof, (const char*)(Kh + so));
            CP16(sb + 2 * FL_TILE + dof, (const char*)(Kl + so));
        }
        CPCOMMIT();
#pragma unroll
        for (int i = 0; i < 8; i++) {
            int c = tid + i * 128;
            int r = c >> 4, sg = c & 15;
            uint32_t dof = (uint32_t)(r * FL_STRIDE_B + sg * 16);
            size_t so = ko + r * HDIM + sg * 8;
            CP16(sb + 3 * FL_TILE + dof, (const char*)(Vh + so));
            CP16(sb + 4 * FL_TILE + dof, (const char*)(Vl + so));
        }
        CPCOMMIT();

        CPWAIT1();
        __syncthreads();

        float s[8][4];
#pragma unroll
        for (int nt = 0; nt < 8; nt++)
#pragma unroll
            for (int r = 0; r < 4; r++) s[nt][r] = 0.0f;

#pragma unroll
        for (int ks = 0; ks < 8; ks++) {
            uint32_t q[4];
            uint32_t qadr = sb + a_row * FL_STRIDE_B + (ks * 16 + a_koff) * 2;
            LDMX4(q[0], q[1], q[2], q[3], qadr);
            uint32_t khf[4][4], klf[4][4];
#pragma unroll
            for (int np = 0; np < 4; np++) {
                uint32_t kadr = sb + 1 * FL_TILE
                              + (np * 16 + b_row) * FL_STRIDE_B
                              + (ks * 16 + b_koff) * 2;
                LDMX4(khf[np][0], khf[np][1], khf[np][2], khf[np][3], kadr);
                LDMX4(klf[np][0], klf[np][1], klf[np][2], klf[np][3], kadr + FL_TILE);
            }
#pragma unroll
            for (int np = 0; np < 4; np++) {
                MMA16816(s[2*np],   q, khf[np][0], khf[np][1]);
                MMA16816(s[2*np+1], q, khf[np][2], khf[np][3]);
            }
#pragma unroll
            for (int np = 0; np < 4; np++) {
                MMA16816(s[2*np],   q, klf[np][0], klf[np][1]);
                MMA16816(s[2*np+1], q, klf[np][2], klf[np][3]);
            }
        }

        if (kt == qt) {
            const int r0 = w * 16 + (lane >> 2);
            const int r1 = r0 + 8;
#pragma unroll
            for (int nt = 0; nt < 8; nt++) {
                const int cb = nt * 8 + (lane & 3) * 2;
                if (cb     > r0) s[nt][0] = -1e30f;
                if (cb + 1 > r0) s[nt][1] = -1e30f;
                if (cb     > r1) s[nt][2] = -1e30f;
                if (cb + 1 > r1) s[nt][3] = -1e30f;
            }
        }

        float mx0 = -1e30f, mx1 = -1e30f;
#pragma unroll
        for (int nt = 0; nt < 8; nt++) {
            mx0 = fmaxf(mx0, fmaxf(s[nt][0], s[nt][1]));
            mx1 = fmaxf(mx1, fmaxf(s[nt][2], s[nt][3]));
        }
        mx0 = fmaxf(mx0, __shfl_xor_sync(0xffffffffu, mx0, 1));
        mx0 = fmaxf(mx0, __shfl_xor_sync(0xffffffffu, mx0, 2));
        mx1 = fmaxf(mx1, __shfl_xor_sync(0xffffffffu, mx1, 1));
        mx1 = fmaxf(mx1, __shfl_xor_sync(0xffffffffu, mx1, 2));

        float mn0 = fmaxf(m0v, mx0), mn1 = fmaxf(m1v, mx1);
        float sf0 = __expf(m0v - mn0), sf1 = __expf(m1v - mn1);
        m0v = mn0; m1v = mn1;

        float ls0 = 0.0f, ls1 = 0.0f;
#pragma unroll
        for (int nt = 0; nt < 8; nt++) {
            s[nt][0] = __expf(s[nt][0] - mn0); ls0 += s[nt][0];
            s[nt][1] = __expf(s[nt][1] - mn0); ls0 += s[nt][1];
            s[nt][2] = __expf(s[nt][2] - mn1); ls1 += s[nt][2];
            s[nt][3] = __expf(s[nt][3] - mn1); ls1 += s[nt][3];
        }
        ls0 += __shfl_xor_sync(0xffffffffu, ls0, 1);
        ls0 += __shfl_xor_sync(0xffffffffu, ls0, 2);
        ls1 += __shfl_xor_sync(0xffffffffu, ls1, 1);
        ls1 += __shfl_xor_sync(0xffffffffu, ls1, 2);
        l0v = l0v * sf0 + ls0;
        l1v = l1v * sf1 + ls1;
#pragma unroll
        for (int nt = 0; nt < 16; nt++) {
            o[nt][0] *= sf0; o[nt][1] *= sf0;
            o[nt][2] *= sf1; o[nt][3] *= sf1;
        }

        // P fragments (plain fp16)
        uint32_t ph[4][4];
#pragma unroll
        for (int k2 = 0; k2 < 4; k2++) {
            ph[k2][0] = cvt_plain_h(s[2*k2][0],   s[2*k2][1]);
            ph[k2][1] = cvt_plain_h(s[2*k2][2],   s[2*k2][3]);
            ph[k2][2] = cvt_plain_h(s[2*k2+1][0], s[2*k2+1][1]);
            ph[k2][3] = cvt_plain_h(s[2*k2+1][2], s[2*k2+1][3]);
        }

        CPWAIT0();
        __syncthreads();

        // O += P (Vh + Vl)
#pragma unroll
        for (int k2 = 0; k2 < 4; k2++) {
#pragma unroll
            for (int npp = 0; npp < 4; npp++) {
                const int np0 = 2 * npp, np1 = 2 * npp + 1;
                uint32_t vh0[4], vl0[4], vh1[4], vl1[4];
                uint32_t va0 = sb + 3 * FL_TILE
                             + (k2 * 16 + v_row) * FL_STRIDE_B
                             + (np0 * 16 + v_coff) * 2;
                uint32_t va1 = va0 + 32;
                LDMT4(vh0[0], vh0[1], vh0[2], vh0[3], va0);
                LDMT4(vl0[0], vl0[1], vl0[2], vl0[3], va0 + FL_TILE);
                LDMT4(vh1[0], vh1[1], vh1[2], vh1[3], va1);
                LDMT4(vl1[0], vl1[1], vl1[2], vl1[3], va1 + FL_TILE);
                MMA16816(o[2*np0],   ph[k2], vh0[0], vh0[1]);
                MMA16816(o[2*np0+1], ph[k2], vh0[2], vh0[3]);
                MMA16816(o[2*np1],   ph[k2], vh1[0], vh1[1]);
                MMA16816(o[2*np1+1], ph[k2], vh1[2], vh1[3]);
                MMA16816(o[2*np0],   ph[k2], vl0[0], vl0[1]);
                MMA16816(o[2*np0+1], ph[k2], vl0[2], vl0[3]);
                MMA16816(o[2*np1],   ph[k2], vl1[0], vl1[1]);
                MMA16816(o[2*np1+1], ph[k2], vl1[2], vl1[3]);
            }
        }
    }

    // epilogue: ctx = O / l -> plain fp16
    const float inv0 = 1.0f / l0v, inv1 = 1.0f / l1v;
    const int b = bh >> 4, h = bh & 15;
    const int gr0 = q0 + w * 16 + (lane >> 2);
    const size_t ro0 = (size_t)(b * SEQ + gr0) * EMB + h * HDIM;
    const size_t ro1 = (size_t)(b * SEQ + gr0 + 8) * EMB + h * HDIM;
#pragma unroll
    for (int nt = 0; nt < 16; nt++) {
        const int col = nt * 8 + (lane & 3) * 2;
        *(uint32_t*)(ctx + ro0 + col) = cvt_plain_h(o[nt][0] * inv0, o[nt][1] * inv0);
        *(uint32_t*)(ctx + ro1 + col) = cvt_plain_h(o[nt][2] * inv1, o[nt][3] * inv1);
    }
}

// ---------------------------------------------------------------------------
extern "C" void kernel_launch(void* const* d_in, const int* in_sizes, int n_in,
                              void* d_out, int out_size)
{
    const float* x      = (const float*)d_in[0];
    const float* wqkv_w = (const float*)d_in[1];
    const float* wqkv_b = (const float*)d_in[2];
    const float* out_w  = (const float*)d_in[3];
    const float* out_b  = (const float*)d_in[4];
    float* out = (float*)d_out;

    float* qkv;
    __half *x16, *w16, *o16w;
    __half *qp, *kh, *kl, *vh, *vl, *c16;
    cudaGetSymbolAddress((void**)&qkv, g_qkv);
    cudaGetSymbolAddress((void**)&x16, g_x16);
    cudaGetSymbolAddress((void**)&w16, g_w16);
    cudaGetSymbolAddress((void**)&o16w, g_o16w);
    cudaGetSymbolAddress((void**)&qp, g_qp);
    cudaGetSymbolAddress((void**)&kh, g_khh); cudaGetSymbolAddress((void**)&kl, g_kll);
    cudaGetSymbolAddress((void**)&vh, g_vhh); cudaGetSymbolAddress((void**)&vl, g_vll);
    cudaGetSymbolAddress((void**)&c16, g_c16);

    cudaFuncSetAttribute(gemm_fp16, cudaFuncAttributeMaxDynamicSharedMemorySize, GEMM_SMEM);
    cudaFuncSetAttribute(flash_mma, cudaFuncAttributeMaxDynamicSharedMemorySize, FLASH_SMEM);

    int n4;
    n4 = MROWS * EMB / 4;
    cvt_f32_h<<<(n4 + 255) / 256, 256>>>((const float4*)x, (uint2*)x16, n4);
    n4 = THREE_E * EMB / 4;
    cvt_f32_h<<<(n4 + 255) / 256, 256>>>((const float4*)wqkv_w, (uint2*)w16, n4);
    n4 = EMB * EMB / 4;
    cvt_f32_h<<<(n4 + 255) / 256, 256>>>((const float4*)out_w, (uint2*)o16w, n4);

    dim3 g1(THREE_E / 128, MROWS / 128);
    gemm_fp16<<<g1, 256, GEMM_SMEM>>>(x16, w16, wqkv_b, qkv, THREE_E, EMB);

    int nr = NBH * SEQ * 64;
    rope_split<<<(nr + 255) / 256, 256>>>(qkv, qp, kh, kl, vh, vl);

    dim3 g2(SEQ / 64, NBH);
    flash_mma<<<g2, 128, FLASH_SMEM>>>(qp, kh, kl, vh, vl, c16);

    dim3 g3(EMB / 128, MROWS / 128);
    gemm_fp16<<<g3, 256, GEMM_SMEM>>>(c16, o16w, out_b, out, EMB, EMB);
}

// round 11
// speedup vs baseline: 8.0946x; 1.1322x over previous
#include <cuda_runtime.h>
#include <cuda_fp16.h>
#include <math.h>
#include <stdint.h>

#define BATCH 2
#define SEQ   2048
#define EMB   2048
#define HEADS 16
#define HDIM  128
#define THREE_E 6144
#define MROWS (BATCH*SEQ)     // 4096
#define NBH   (BATCH*HEADS)   // 32

// ---------------- scratch (__device__ globals; no cudaMalloc) ----------------
__device__ float g_qkv[(size_t)MROWS * THREE_E];                 // fp32 QKV
__device__ __half g_x16[(size_t)MROWS * EMB];                    // x plain fp16
__device__ __half g_w16[(size_t)THREE_E * EMB];                  // wqkv plain fp16
__device__ __half g_o16w[(size_t)EMB * EMB];                     // out_w plain fp16
__device__ __half g_qp[(size_t)NBH*SEQ*HDIM];                    // Q plain fp16
__device__ __half g_khh[(size_t)NBH*SEQ*HDIM], g_kll[(size_t)NBH*SEQ*HDIM];
__device__ __half g_vp[(size_t)NBH*SEQ*HDIM];                    // V plain fp16
__device__ __half g_c16[(size_t)MROWS * EMB];                    // ctx plain fp16

// ---------------- PTX helpers ----------------
__device__ __forceinline__ uint32_t smem_u32(const void* p) {
    uint32_t a;
    asm("{ .reg .u64 t; cvta.to.shared.u64 t, %1; cvt.u32.u64 %0, t; }"
        : "=r"(a) : "l"(p));
    return a;
}
__device__ __forceinline__ uint32_t cvt_plain_h(float f0, float f1) {
    uint32_t h;
    asm("cvt.rn.f16x2.f32 %0, %1, %2;" : "=r"(h) : "f"(f1), "f"(f0));
    return h;
}
#define LDMX4(r0, r1, r2, r3, addr) \
    asm volatile("ldmatrix.sync.aligned.m8n8.x4.shared.b16 {%0,%1,%2,%3}, [%4];" \
        : "=r"(r0), "=r"(r1), "=r"(r2), "=r"(r3) : "r"(addr))
#define LDMT4(r0, r1, r2, r3, addr) \
    asm volatile("ldmatrix.sync.aligned.m8n8.x4.trans.shared.b16 {%0,%1,%2,%3}, [%4];" \
        : "=r"(r0), "=r"(r1), "=r"(r2), "=r"(r3) : "r"(addr))
#define MMA16816(d, a, b0, b1) \
    asm volatile("mma.sync.aligned.m16n8k16.row.col.f32.f16.f16.f32 " \
        "{%0,%1,%2,%3}, {%4,%5,%6,%7}, {%8,%9}, {%0,%1,%2,%3};" \
        : "+f"((d)[0]), "+f"((d)[1]), "+f"((d)[2]), "+f"((d)[3]) \
        : "r"((a)[0]), "r"((a)[1]), "r"((a)[2]), "r"((a)[3]), "r"(b0), "r"(b1))
#define CP16(dst, src) \
    asm volatile("cp.async.cg.shared.global [%0], [%1], 16;" :: "r"(dst), "l"(src))
#define CPCOMMIT() asm volatile("cp.async.commit_group;" ::: "memory")
#define CPWAIT0()  asm volatile("cp.async.wait_group 0;" ::: "memory")
#define CPWAIT1()  asm volatile("cp.async.wait_group 1;" ::: "memory")

// ---------------------------------------------------------------------------
// Prep kernels
// ---------------------------------------------------------------------------
__global__ void cvt_f32_h(const float4* __restrict__ in,
                          uint2* __restrict__ o16, int n4)
{
    int i = blockIdx.x * blockDim.x + threadIdx.x;
    if (i >= n4) return;
    float4 v = in[i];
    o16[i] = make_uint2(cvt_plain_h(v.x, v.y), cvt_plain_h(v.z, v.w));
}

// ---------------------------------------------------------------------------
// fp16 single-product tensor GEMM: C[M,N] = A[M,K] @ B[N,K]^T + bias
// BM=BN=128, BK=64 (halved barrier count), 256 threads = 8 warps (2m x 4n).
// 3-stage cp.async pipeline; 2 CTAs per SM.
// ---------------------------------------------------------------------------
#define LDS 72                       // 64 fp16 data + 8 pad per row (144 B)
#define A_SB (128 * LDS * 2)         // 18432 B
#define STAGE_SB (2 * A_SB)          // 36864 B (A + B)
#define GEMM_SMEM (3 * STAGE_SB)     // 110592 B  -> 2 CTAs/SM

__device__ __forceinline__ void gemm_issue(
    const __half* A, const __half* B,
    uint32_t sbase, int m0, int n0, int K, int cc, int tid)
{
    const uint32_t stg = sbase + (uint32_t)(cc % 3) * STAGE_SB;
    const int k0 = cc * 64;
#pragma unroll
    for (int i = 0; i < 4; i++) {
        int c = tid + i * 256;       // 0..1023
        int r = c >> 3, sg = c & 7;  // 128 rows x 8 segs of 16B
        uint32_t dof = (uint32_t)(r * 144 + sg * 16);
        size_t ao = (size_t)(m0 + r) * K + k0 + sg * 8;
        size_t bo = (size_t)(n0 + r) * K + k0 + sg * 8;
        CP16(stg + dof, (const char*)(A + ao));
        CP16(stg + A_SB + dof, (const char*)(B + bo));
    }
    CPCOMMIT();
}

__global__ __launch_bounds__(256, 2) void gemm_fp16(
    const __half* __restrict__ A, const __half* __restrict__ B,
    const float* __restrict__ bias, float* __restrict__ C, int N, int K)
{
    extern __shared__ char dsm[];
    __shared__ float sBias[128];

    const int tid  = threadIdx.x;
    const int lane = tid & 31;
    const int wid  = tid >> 5;
    const int wm   = wid >> 2;        // 0..1
    const int wn   = wid & 3;         // 0..3
    const int m0 = blockIdx.y * 128, n0 = blockIdx.x * 128;
    const uint32_t sbase = smem_u32(dsm);

    if (tid < 128) sBias[tid] = bias[n0 + tid];

    const int NCH = K >> 6;           // 64-wide chunks
    gemm_issue(A, B, sbase, m0, n0, K, 0, tid);
    gemm_issue(A, B, sbase, m0, n0, K, 1, tid);

    float acc[4][4][4];
#pragma unroll
    for (int mt = 0; mt < 4; mt++)
#pragma unroll
        for (int nt = 0; nt < 4; nt++)
#pragma unroll
            for (int r = 0; r < 4; r++) acc[mt][nt][r] = 0.0f;

    const uint32_t a_row  = (uint32_t)(wm * 64 + (lane & 15));
    const uint32_t a_koff = (uint32_t)((lane >> 4) * 8);
    const uint32_t b_row  = (uint32_t)(wn * 32 + (lane & 7) + ((lane >> 4) << 3));
    const uint32_t b_koff = (uint32_t)(((lane >> 3) & 1) * 8);

    for (int c = 0; c < NCH; c++) {
        CPWAIT1();
        __syncthreads();
        if (c + 2 < NCH) gemm_issue(A, B, sbase, m0, n0, K, c + 2, tid);
        else CPCOMMIT();

        const uint32_t stg = sbase + (uint32_t)(c % 3) * STAGE_SB;
#pragma unroll
        for (int ks = 0; ks < 4; ks++) {
            const uint32_t kofs = (uint32_t)(ks * 16);
            uint32_t a[4][4];
#pragma unroll
            for (int mt = 0; mt < 4; mt++) {
                uint32_t adr = stg + ((a_row + mt * 16) * LDS + kofs + a_koff) * 2;
                LDMX4(a[mt][0], a[mt][1], a[mt][2], a[mt][3], adr);
            }
            uint32_t b[2][4];
#pragma unroll
            for (int p = 0; p < 2; p++) {
                uint32_t adr = stg + A_SB
                             + ((b_row + p * 16) * LDS + kofs + b_koff) * 2;
                LDMX4(b[p][0], b[p][1], b[p][2], b[p][3], adr);
            }
#pragma unroll
            for (int mt = 0; mt < 4; mt++)
#pragma unroll
                for (int nt = 0; nt < 4; nt++) {
                    const int p = nt >> 1, hh = (nt & 1) * 2;
                    MMA16816(acc[mt][nt], a[mt], b[p][hh], b[p][hh + 1]);
                }
        }
    }

    const int erow = wm * 64 + (lane >> 2);
    const int ecol = wn * 32 + (lane & 3) * 2;
#pragma unroll
    for (int mt = 0; mt < 4; mt++) {
#pragma unroll
        for (int nt = 0; nt < 4; nt++) {
            const int cc = ecol + nt * 8;
            const float b0 = sBias[cc], b1 = sBias[cc + 1];
            float* p0 = C + (size_t)(m0 + erow + mt * 16) * N + n0 + cc;
            float* p1 = C + (size_t)(m0 + erow + mt * 16 + 8) * N + n0 + cc;
            float2 v0 = {acc[mt][nt][0] + b0, acc[mt][nt][1] + b1};
            float2 v1 = {acc[mt][nt][2] + b0, acc[mt][nt][3] + b1};
            *(float2*)p0 = v0;
            *(float2*)p1 = v1;
        }
    }
}

// ---------------------------------------------------------------------------
// RoPE + layout: Q plain fp16 (scaled), K hi/lo, V plain
// ---------------------------------------------------------------------------
__device__ __forceinline__ void split1h(float x, __half* ph, __half* pl) {
    __half h = __float2half_rn(x);
    *ph = h;
    *pl = __float2half_rn(x - __half2float(h));
}

__global__ __launch_bounds__(256) void rope_split(
    const float* __restrict__ qkv,
    __half* __restrict__ Qp,
    __half* __restrict__ Kh, __half* __restrict__ Kl,
    __half* __restrict__ Vp)
{
    int idx = blockIdx.x * blockDim.x + threadIdx.x;   // NBH*SEQ*64
    if (idx >= NBH * SEQ * 64) return;
    int j  = idx & 63;
    int s  = (idx >> 6) & (SEQ - 1);
    int bh = idx >> 17;
    int b = bh >> 4, h = bh & 15;

    size_t base = ((size_t)(b * SEQ + s) * 3) * EMB + h * HDIM;
    size_t dst  = ((size_t)bh * SEQ + s) * HDIM + j;
    const float scale = 0.08838834764831845f;

    float inv = powf(10000.0f, -(float)j / 64.0f);
    float ang = (float)s * inv;
    float sn, cs;
    sincosf(ang, &sn, &cs);

    float q1 = qkv[base + j], q2 = qkv[base + 64 + j];
    Qp[dst]      = __float2half_rn((q1 * cs - q2 * sn) * scale);
    Qp[dst + 64] = __float2half_rn((q1 * sn + q2 * cs) * scale);
    float k1 = qkv[base + EMB + j], k2 = qkv[base + EMB + 64 + j];
    split1h(k1 * cs - k2 * sn, Kh + dst, Kl + dst);
    split1h(k1 * sn + k2 * cs, Kh + dst + 64, Kl + dst + 64);
    Vp[dst]      = __float2half_rn(qkv[base + 2 * EMB + j]);
    Vp[dst + 64] = __float2half_rn(qkv[base + 2 * EMB + 64 + j]);
}

// ---------------------------------------------------------------------------
// Flash attention: Q plain, K hi/lo (2-product scores), V plain, causal.
// 128 threads (4 warps x 16 q-rows), 64x64 KV tiles, D=128, 2 CTAs/SM.
// smem tiles: Q, Kh, Kl, V
// ---------------------------------------------------------------------------
#define FL_STRIDE_B 272                  // 136 fp16 per smem row
#define FL_TILE (64 * FL_STRIDE_B)       // 17408 B
#define FLASH_SMEM (4 * FL_TILE)         // 69632 B

__global__ __launch_bounds__(128, 2) void flash_mma(
    const __half* __restrict__ Qp,
    const __half* __restrict__ Kh, const __half* __restrict__ Kl,
    const __half* __restrict__ Vp,
    __half* __restrict__ ctx)
{
    extern __shared__ char fsm[];
    const int qt = gridDim.x - 1 - blockIdx.x;   // heavy tiles first
    const int bh = blockIdx.y;
    const int tid = threadIdx.x, lane = tid & 31, w = tid >> 5;
    const int q0 = qt * 64;
    const uint32_t sb = smem_u32(fsm);

    {
        const size_t qo = ((size_t)bh * SEQ + q0) * HDIM;
#pragma unroll
        for (int i = 0; i < 8; i++) {
            int c = tid + i * 128;
            int r = c >> 4, sg = c & 15;
            *(uint4*)(fsm + r * FL_STRIDE_B + sg * 16) =
                *(const uint4*)(Qp + qo + r * HDIM + sg * 8);
        }
    }

    float m0v = -1e30f, m1v = -1e30f, l0v = 0.0f, l1v = 0.0f;
    float o[16][4];
#pragma unroll
    for (int nt = 0; nt < 16; nt++)
#pragma unroll
        for (int r = 0; r < 4; r++) o[nt][r] = 0.0f;

    const uint32_t a_row  = (uint32_t)(w * 16 + (lane & 15));
    const uint32_t a_koff = (uint32_t)((lane >> 4) * 8);
    const uint32_t b_row  = (uint32_t)((lane & 7) + ((lane >> 4) << 3));
    const uint32_t b_koff = (uint32_t)(((lane >> 3) & 1) * 8);
    const uint32_t v_row  = (uint32_t)(lane & 15);
    const uint32_t v_coff = (uint32_t)((lane >> 4) * 8);

    for (int kt = 0; kt <= qt; kt++) {
        __syncthreads();

        const size_t ko = ((size_t)bh * SEQ + kt * 64) * HDIM;
#pragma unroll
        for (int i = 0; i < 8; i++) {
            int c = tid + i * 128;
            int r = c >> 4, sg = c & 15;
            uint32_t dof = (uint32_t)(r * FL_STRIDE_B + sg * 16);
            size_t so = ko + r * HDIM + sg * 8;
            CP16(sb + 1 * FL_TILE + dof, (const char*)(Kh + so));
            CP16(sb + 2 * FL_TILE + dof, (const char*)(Kl + so));
        }
        CPCOMMIT();
#pragma unroll
        for (int i = 0; i < 8; i++) {
            int c = tid + i * 128;
            int r = c >> 4, sg = c & 15;
            uint32_t dof = (uint32_t)(r * FL_STRIDE_B + sg * 16);
            size_t so = ko + r * HDIM + sg * 8;
            CP16(sb + 3 * FL_TILE + dof, (const char*)(Vp + so));
        }
        CPCOMMIT();

        CPWAIT1();
        __syncthreads();

        float s[8][4];
#pragma unroll
        for (int nt = 0; nt < 8; nt++)
#pragma unroll
            for (int r = 0; r < 4; r++) s[nt][r] = 0.0f;

#pragma unroll
        for (int ks = 0; ks < 8; ks++) {
            uint32_t q[4];
            uint32_t qadr = sb + a_row * FL_STRIDE_B + (ks * 16 + a_koff) * 2;
            LDMX4(q[0], q[1], q[2], q[3], qadr);
            uint32_t khf[4][4], klf[4][4];
#pragma unroll
            for (int np = 0; np < 4; np++) {
                uint32_t kadr = sb + 1 * FL_TILE
                              + (np * 16 + b_row) * FL_STRIDE_B
                              + (ks * 16 + b_koff) * 2;
                LDMX4(khf[np][0], khf[np][1], khf[np][2], khf[np][3], kadr);
                LDMX4(klf[np][0], klf[np][1], klf[np][2], klf[np][3], kadr + FL_TILE);
            }
#pragma unroll
            for (int np = 0; np < 4; np++) {
                MMA16816(s[2*np],   q, khf[np][0], khf[np][1]);
                MMA16816(s[2*np+1], q, khf[np][2], khf[np][3]);
            }
#pragma unroll
            for (int np = 0; np < 4; np++) {
                MMA16816(s[2*np],   q, klf[np][0], klf[np][1]);
                MMA16816(s[2*np+1], q, klf[np][2], klf[np][3]);
            }
        }

        if (kt == qt) {
            const int r0 = w * 16 + (lane >> 2);
            const int r1 = r0 + 8;
#pragma unroll
            for (int nt = 0; nt < 8; nt++) {
                const int cb = nt * 8 + (lane & 3) * 2;
                if (cb     > r0) s[nt][0] = -1e30f;
                if (cb + 1 > r0) s[nt][1] = -1e30f;
                if (cb     > r1) s[nt][2] = -1e30f;
                if (cb + 1 > r1) s[nt][3] = -1e30f;
            }
        }

        float mx0 = -1e30f, mx1 = -1e30f;
#pragma unroll
        for (int nt = 0; nt < 8; nt++) {
            mx0 = fmaxf(mx0, fmaxf(s[nt][0], s[nt][1]));
            mx1 = fmaxf(mx1, fmaxf(s[nt][2], s[nt][3]));
        }
        mx0 = fmaxf(mx0, __shfl_xor_sync(0xffffffffu, mx0, 1));
        mx0 = fmaxf(mx0, __shfl_xor_sync(0xffffffffu, mx0, 2));
        mx1 = fmaxf(mx1, __shfl_xor_sync(0xffffffffu, mx1, 1));
        mx1 = fmaxf(mx1, __shfl_xor_sync(0xffffffffu, mx1, 2));

        float mn0 = fmaxf(m0v, mx0), mn1 = fmaxf(m1v, mx1);
        float sf0 = __expf(m0v - mn0), sf1 = __expf(m1v - mn1);
        m0v = mn0; m1v = mn1;

        float ls0 = 0.0f, ls1 = 0.0f;
#pragma unroll
        for (int nt = 0; nt < 8; nt++) {
            s[nt][0] = __expf(s[nt][0] - mn0); ls0 += s[nt][0];
            s[nt][1] = __expf(s[nt][1] - mn0); ls0 += s[nt][1];
            s[nt][2] = __expf(s[nt][2] - mn1); ls1 += s[nt][2];
            s[nt][3] = __expf(s[nt][3] - mn1); ls1 += s[nt][3];
        }
        ls0 += __shfl_xor_sync(0xffffffffu, ls0, 1);
        ls0 += __shfl_xor_sync(0xffffffffu, ls0, 2);
        ls1 += __shfl_xor_sync(0xffffffffu, ls1, 1);
        ls1 += __shfl_xor_sync(0xffffffffu, ls1, 2);
        l0v = l0v * sf0 + ls0;
        l1v = l1v * sf1 + ls1;
#pragma unroll
        for (int nt = 0; nt < 16; nt++) {
            o[nt][0] *= sf0; o[nt][1] *= sf0;
            o[nt][2] *= sf1; o[nt][3] *= sf1;
        }

        // P fragments (plain fp16)
        uint32_t ph[4][4];
#pragma unroll
        for (int k2 = 0; k2 < 4; k2++) {
            ph[k2][0] = cvt_plain_h(s[2*k2][0],   s[2*k2][1]);
            ph[k2][1] = cvt_plain_h(s[2*k2][2],   s[2*k2][3]);
            ph[k2][2] = cvt_plain_h(s[2*k2+1][0], s[2*k2+1][1]);
            ph[k2][3] = cvt_plain_h(s[2*k2+1][2], s[2*k2+1][3]);
        }

        CPWAIT0();
        __syncthreads();

        // O += P V (single product)
#pragma unroll
        for (int k2 = 0; k2 < 4; k2++) {
#pragma unroll
            for (int npp = 0; npp < 4; npp++) {
                const int np0 = 2 * npp, np1 = 2 * npp + 1;
                uint32_t vh0[4], vh1[4];
                uint32_t va0 = sb + 3 * FL_TILE
                             + (k2 * 16 + v_row) * FL_STRIDE_B
                             + (np0 * 16 + v_coff) * 2;
                uint32_t va1 = va0 + 32;
                LDMT4(vh0[0], vh0[1], vh0[2], vh0[3], va0);
                LDMT4(vh1[0], vh1[1], vh1[2], vh1[3], va1);
                MMA16816(o[2*np0],   ph[k2], vh0[0], vh0[1]);
                MMA16816(o[2*np0+1], ph[k2], vh0[2], vh0[3]);
                MMA16816(o[2*np1],   ph[k2], vh1[0], vh1[1]);
                MMA16816(o[2*np1+1], ph[k2], vh1[2], vh1[3]);
            }
        }
    }

    // epilogue: ctx = O / l -> plain fp16
    const float inv0 = 1.0f / l0v, inv1 = 1.0f / l1v;
    const int b = bh >> 4, h = bh & 15;
    const int gr0 = q0 + w * 16 + (lane >> 2);
    const size_t ro0 = (size_t)(b * SEQ + gr0) * EMB + h * HDIM;
    const size_t ro1 = (size_t)(b * SEQ + gr0 + 8) * EMB + h * HDIM;
#pragma unroll
    for (int nt = 0; nt < 16; nt++) {
        const int col = nt * 8 + (lane & 3) * 2;
        *(uint32_t*)(ctx + ro0 + col) = cvt_plain_h(o[nt][0] * inv0, o[nt][1] * inv0);
        *(uint32_t*)(ctx + ro1 + col) = cvt_plain_h(o[nt][2] * inv1, o[nt][3] * inv1);
    }
}

// ---------------------------------------------------------------------------
extern "C" void kernel_launch(void* const* d_in, const int* in_sizes, int n_in,
                              void* d_out, int out_size)
{
    const float* x      = (const float*)d_in[0];
    const float* wqkv_w = (const float*)d_in[1];
    const float* wqkv_b = (const float*)d_in[2];
    const float* out_w  = (const float*)d_in[3];
    const float* out_b  = (const float*)d_in[4];
    float* out = (float*)d_out;

    float* qkv;
    __half *x16, *w16, *o16w;
    __half *qp, *kh, *kl, *vp, *c16;
    cudaGetSymbolAddress((void**)&qkv, g_qkv);
    cudaGetSymbolAddress((void**)&x16, g_x16);
    cudaGetSymbolAddress((void**)&w16, g_w16);
    cudaGetSymbolAddress((void**)&o16w, g_o16w);
    cudaGetSymbolAddress((void**)&qp, g_qp);
    cudaGetSymbolAddress((void**)&kh, g_khh); cudaGetSymbolAddress((void**)&kl, g_kll);
    cudaGetSymbolAddress((void**)&vp, g_vp);
    cudaGetSymbolAddress((void**)&c16, g_c16);

    cudaFuncSetAttribute(gemm_fp16, cudaFuncAttributeMaxDynamicSharedMemorySize, GEMM_SMEM);
    cudaFuncSetAttribute(flash_mma, cudaFuncAttributeMaxDynamicSharedMemorySize, FLASH_SMEM);

    int n4;
    n4 = MROWS * EMB / 4;
    cvt_f32_h<<<(n4 + 255) / 256, 256>>>((const float4*)x, (uint2*)x16, n4);
    n4 = THREE_E * EMB / 4;
    cvt_f32_h<<<(n4 + 255) / 256, 256>>>((const float4*)wqkv_w, (uint2*)w16, n4);
    n4 = EMB * EMB / 4;
    cvt_f32_h<<<(n4 + 255) / 256, 256>>>((const float4*)out_w, (uint2*)o16w, n4);

    dim3 g1(THREE_E / 128, MROWS / 128);
    gemm_fp16<<<g1, 256, GEMM_SMEM>>>(x16, w16, wqkv_b, qkv, THREE_E, EMB);

    int nr = NBH * SEQ * 64;
    rope_split<<<(nr + 255) / 256, 256>>>(qkv, qp, kh, kl, vp);

    dim3 g2(SEQ / 64, NBH);
    flash_mma<<<g2, 128, FLASH_SMEM>>>(qp, kh, kl, vp, c16);

    dim3 g3(EMB / 128, MROWS / 128);
    gemm_fp16<<<g3, 256, GEMM_SMEM>>>(c16, o16w, out_b, out, EMB, EMB);
}